// round 8
// baseline (speedup 1.0000x reference)
#include <cuda_runtime.h>
#include <math.h>
#include <stdint.h>

#define Bn 8
#define Ln 2048
#define Dn 1024
#define M_ALL (Bn * Ln)   // 16384

// ---------------------------------------------------------------------------
// Device scratch (allocation-free rule -> __device__ globals)
// ---------------------------------------------------------------------------
__device__ float g_ctx_scratch[(size_t)M_ALL * Dn];
__device__ float g_attn_scratch[(size_t)Bn * Ln * Ln];
__device__ float g_vmean[(size_t)Bn * Dn];
__device__ float g_xmean[(size_t)Bn * Dn];
__device__ int   g_lens[Bn];

// fp32 intermediates
__device__ float g_XTf[(size_t)Bn * Dn * Ln];
__device__ float g_WqTf[(size_t)Dn * Dn];
__device__ float g_WkTf[(size_t)Dn * Dn];
__device__ float g_GTf[(size_t)Dn * Dn];
__device__ float g_QGf[(size_t)M_ALL * Dn];
__device__ float g_PXf[(size_t)M_ALL * Dn];

// int8 two-plane quantized operands + per-row scales
#define QDECL(name, rows, k) \
    __device__ __align__(128) int8_t g_##name##1[(size_t)(rows) * (k)]; \
    __device__ __align__(128) int8_t g_##name##2[(size_t)(rows) * (k)]; \
    __device__ float g_s##name[(rows)];

QDECL(X,   M_ALL, Dn)        // input_seq rows (key tokens)
QDECL(O,   M_ALL, Dn)        // output_seq rows (query tokens)
QDECL(XT,  Bn * Dn, Ln)      // X transposed per batch
QDECL(Wv,  Dn, Dn)
QDECL(WqT, Dn, Dn)
QDECL(WkT, Dn, Dn)
QDECL(GT,  Dn, Dn)
QDECL(QG,  M_ALL, Dn)
QDECL(P,   M_ALL, Ln)
QDECL(PX,  M_ALL, Dn)

// ---------------------------------------------------------------------------
// lens dtype sniffing (int64 vs int32)
// ---------------------------------------------------------------------------
__global__ void prep_lens_kernel(const void* lensraw) {
    if (threadIdx.x == 0 && blockIdx.x == 0) {
        const int* a32 = (const int*)lensraw;
        bool is64 = true;
        #pragma unroll
        for (int i = 0; i < 4; i++) {
            int lo = a32[2 * i], hi = a32[2 * i + 1];
            if (hi != 0 || lo < 1 || lo > Ln) { is64 = false; break; }
        }
        if (is64) {
            const long long* a64 = (const long long*)lensraw;
            for (int i = 0; i < Bn; i++) g_lens[i] = (int)a64[i];
        } else {
            for (int i = 0; i < Bn; i++) g_lens[i] = a32[i];
        }
    }
}

// ---------------------------------------------------------------------------
// fp32 transpose [R,C] -> [C,R], batched via blockIdx.z
// ---------------------------------------------------------------------------
__global__ __launch_bounds__(256)
void transf_kernel(const float* __restrict__ src, float* __restrict__ dst,
                   int R, int C) {
    __shared__ float tile[32][33];
    size_t bo = (size_t)blockIdx.z * R * C;
    src += bo; dst += bo;
    int c0 = blockIdx.x * 32;
    int r0 = blockIdx.y * 32;
    int tx = threadIdx.x & 31;
    int ty = threadIdx.x >> 5;

    #pragma unroll
    for (int j = 0; j < 4; j++)
        tile[ty + j * 8][tx] = src[(size_t)(r0 + ty + j * 8) * C + c0 + tx];
    __syncthreads();

    #pragma unroll
    for (int j = 0; j < 4; j++)
        dst[(size_t)(c0 + ty + j * 8) * R + r0 + tx] = tile[tx][ty + j * 8];
}

// ---------------------------------------------------------------------------
// Row quantization: fp32 row -> two int8 planes + scale.
// x ~= s * (a1 + a2/128), s = rowmax/127.
// maskChk: skip rows with (row & 2047) >= lens[row >> 11]
// ---------------------------------------------------------------------------
__global__ __launch_bounds__(256)
void rowquant_kernel(const float* __restrict__ src, int8_t* __restrict__ p1,
                     int8_t* __restrict__ p2, float* __restrict__ sArr,
                     int K, int maskChk) {
    const int row = blockIdx.x;
    if (maskChk && ((row & (Ln - 1)) >= g_lens[row >> 11])) return;
    const float* p = src + (size_t)row * K;
    const int t = threadIdx.x;
    const int nj = K >> 10;   // 1 (K=1024) or 2 (K=2048)

    float4 v[2];
    float m = 0.0f;
    for (int j = 0; j < nj; j++) {
        v[j] = ((const float4*)p)[t + j * 256];
        m = fmaxf(m, fmaxf(fmaxf(fabsf(v[j].x), fabsf(v[j].y)),
                           fmaxf(fabsf(v[j].z), fabsf(v[j].w))));
    }
    __shared__ float red[256];
    red[t] = m;
    __syncthreads();
    #pragma unroll
    for (int s = 128; s > 0; s >>= 1) {
        if (t < s) red[t] = fmaxf(red[t], red[t + s]);
        __syncthreads();
    }
    const float mx = red[0];
    const float inv = mx > 0.0f ? 127.0f / mx : 0.0f;
    if (t == 0) sArr[row] = mx > 0.0f ? mx / 127.0f : 1.0f;

    for (int j = 0; j < nj; j++) {
        float q[4] = {v[j].x * inv, v[j].y * inv, v[j].z * inv, v[j].w * inv};
        char c1[4], c2[4];
        #pragma unroll
        for (int i = 0; i < 4; i++) {
            int a1 = __float2int_rn(q[i]);
            a1 = max(-127, min(127, a1));
            int a2 = __float2int_rn((q[i] - (float)a1) * 128.0f);
            a2 = max(-127, min(127, a2));
            c1[i] = (char)a1;
            c2[i] = (char)a2;
        }
        size_t off = (size_t)row * K + (size_t)(t + j * 256) * 4;
        *(char4*)(p1 + off) = make_char4(c1[0], c1[1], c1[2], c1[3]);
        *(char4*)(p2 + off) = make_char4(c2[0], c2[1], c2[2], c2[3]);
    }
}

// ---------------------------------------------------------------------------
// xmean / vmean (exact fp32 path for masked ctx rows)
// ---------------------------------------------------------------------------
__global__ __launch_bounds__(256)
void xmean_kernel(const float* __restrict__ xf, float* __restrict__ xm) {
    int b = blockIdx.y;
    int d = blockIdx.x * 256 + threadIdx.x;
    const float* p = xf + (size_t)b * Ln * Dn + d;
    float s0 = 0.f, s1 = 0.f, s2 = 0.f, s3 = 0.f;
    for (int t = 0; t < Ln; t += 4) {
        s0 += p[(size_t)(t + 0) * Dn];
        s1 += p[(size_t)(t + 1) * Dn];
        s2 += p[(size_t)(t + 2) * Dn];
        s3 += p[(size_t)(t + 3) * Dn];
    }
    xm[b * Dn + d] = (s0 + s1 + s2 + s3) * (1.0f / 2048.0f);
}

__global__ __launch_bounds__(256)
void vmeanw_kernel(const float* __restrict__ xm, const float* __restrict__ Wv,
                   float* __restrict__ vm) {
    int b = blockIdx.y;
    int e = blockIdx.x * 8 + (threadIdx.x >> 5);
    int lane = threadIdx.x & 31;
    const float* xr = xm + b * Dn;
    const float* wr = Wv + (size_t)e * Dn;
    float s = 0.f;
    for (int d = lane; d < Dn; d += 32) s += xr[d] * wr[d];
    #pragma unroll
    for (int o = 16; o > 0; o >>= 1) s += __shfl_down_sync(0xffffffffu, s, o);
    if (lane == 0) vm[b * Dn + e] = s;
}

__global__ __launch_bounds__(256)
void fill_masked_kernel(const float* __restrict__ vm, float* __restrict__ ctx) {
    int b = blockIdx.z;
    int q = blockIdx.y;
    if (q < g_lens[b]) return;
    int d = blockIdx.x * 256 + threadIdx.x;
    ctx[((size_t)b * Ln + q) * Dn + d] = vm[b * Dn + d];
}

// ---------------------------------------------------------------------------
// IMMA GEMM core (mma.sync m16n8k32 s8, s32 accum), NT.
// CTA 128x128, BK=128 int8 bytes (SW128 rows), 3-stage cp.async,
// 8 warps 2x4 (warp tile 64x32).
// PASS 0: C = sA*sB*scale * (A1.B1)         (store)
// PASS 1: C += sA*sB*scale/128 * (A1.B2 + A2.B1)
// MODE 0: plain fp32 C. MODE 1: query-row mask (-1e9) epilogue.
// ---------------------------------------------------------------------------
__device__ __forceinline__ uint32_t sw128(uint32_t x) { return x ^ ((x >> 3) & 0x70); }

#define A_BYTES 16384
#define STAGE_B 32768
#define NSTAGE  3
#define SMEM_REQ (1024 + NSTAGE * STAGE_B)

__device__ __forceinline__ void cp16(uint32_t saddr, const void* gaddr) {
    asm volatile("cp.async.cg.shared.global [%0], [%1], 16;" :: "r"(saddr), "l"(gaddr));
}
__device__ __forceinline__ void cp_commit() {
    asm volatile("cp.async.commit_group;" ::: "memory");
}
template <int N> __device__ __forceinline__ void cp_wait() {
    asm volatile("cp.async.wait_group %0;" :: "n"(N) : "memory");
}
__device__ __forceinline__ void ldm4(uint32_t addr, uint32_t& r0, uint32_t& r1,
                                     uint32_t& r2, uint32_t& r3) {
    asm volatile("ldmatrix.sync.aligned.m8n8.x4.shared.b16 {%0,%1,%2,%3}, [%4];"
                 : "=r"(r0), "=r"(r1), "=r"(r2), "=r"(r3) : "r"(addr));
}
__device__ __forceinline__ void imma16832(int* c, uint32_t a0, uint32_t a1,
                                          uint32_t a2, uint32_t a3,
                                          uint32_t b0, uint32_t b1) {
    asm volatile(
        "mma.sync.aligned.m16n8k32.row.col.s32.s8.s8.s32 "
        "{%0,%1,%2,%3},{%4,%5,%6,%7},{%8,%9},{%0,%1,%2,%3};"
        : "+r"(c[0]), "+r"(c[1]), "+r"(c[2]), "+r"(c[3])
        : "r"(a0), "r"(a1), "r"(a2), "r"(a3), "r"(b0), "r"(b1));
}

template <int MODE, int PASS>
__global__ __launch_bounds__(256, 2)
void imma_gemm(const int8_t* __restrict__ A1, const int8_t* __restrict__ A2,
               const int8_t* __restrict__ B1, const int8_t* __restrict__ B2,
               const float* __restrict__ sA, const float* __restrict__ sB,
               float* __restrict__ C, int K, int ldc,
               long long strA, long long strB, long long strC,
               long long strSA, long long strSB, float scale, int skipMode) {
    const int z    = blockIdx.z;
    const int row0 = blockIdx.y * 128;
    const int n0   = blockIdx.x * 128;

    if (skipMode == 1) {
        if (row0 >= g_lens[z]) return;
    } else if (skipMode == 2) {
        if ((row0 & (Ln - 1)) >= g_lens[row0 >> 11]) return;
    }

    extern __shared__ char dsm[];
    uint32_t sraw = (uint32_t)__cvta_generic_to_shared(dsm);
    uint32_t sb   = (sraw + 1023) & ~1023u;

    const int tid  = threadIdx.x;
    const int lane = tid & 31;
    const int wid  = tid >> 5;
    const int wr   = wid >> 2;     // 0..1 : 64-row M half
    const int wc   = wid & 3;      // 0..3 : 32-col N quarter

    // loader: thread -> (row r, 64B half h); 4 x 16B per operand per chunk
    const int r = tid >> 1;
    const int h = (tid & 1) * 64;

    const char* aR1 = (const char*)(A1 + (size_t)z * strA + (size_t)(row0 + r) * K) + h;
    const char* aR2 = (const char*)(A2 + (size_t)z * strA + (size_t)(row0 + r) * K) + h;
    const char* bR1 = (const char*)(B1 + (size_t)z * strB + (size_t)(n0 + r) * K) + h;
    const char* bR2 = (const char*)(B2 + (size_t)z * strB + (size_t)(n0 + r) * K) + h;

    uint32_t swo[4];
    #pragma unroll
    for (int i = 0; i < 4; i++) swo[i] = sw128((uint32_t)r * 128u + h + i * 16);

    int acc[4][4][4];
    #pragma unroll
    for (int a = 0; a < 4; a++)
        #pragma unroll
        for (int b = 0; b < 4; b++)
            #pragma unroll
            for (int cc = 0; cc < 4; cc++) acc[a][b][cc] = 0;

    const int nch = K / 128;
    const int T   = PASS ? 2 * nch : nch;

    const char* aPtr = aR1;
    const char* bPtr = PASS ? bR2 : bR1;   // PASS1 seg0 = (A1,B2)
    int cIss = 0, bufIss = 0;

    auto issue_one = [&]() {
        uint32_t sa = sb + bufIss * STAGE_B;
        #pragma unroll
        for (int i = 0; i < 4; i++) cp16(sa + swo[i], aPtr + i * 16);
        uint32_t sbB = sa + A_BYTES;
        #pragma unroll
        for (int i = 0; i < 4; i++) cp16(sbB + swo[i], bPtr + i * 16);
        cp_commit();
        aPtr += 128; bPtr += 128;
        bufIss = (bufIss == NSTAGE - 1) ? 0 : bufIss + 1;
        if (++cIss == nch && PASS) {       // switch to seg1 = (A2,B1)
            aPtr = aR2; bPtr = bR1;
        }
    };

    issue_one();
    issue_one();

    int bufC = 0;
    for (int t = 0; t < T; t++) {
        if (t + 2 < T)      { issue_one(); cp_wait<2>(); }
        else if (t + 1 < T) { cp_wait<1>(); }
        else                { cp_wait<0>(); }
        __syncthreads();

        const uint32_t aBase = sb + bufC * STAGE_B;
        const uint32_t bBase = aBase + A_BYTES;

        const uint32_t asub = lane >> 3;          // 0..3
        const uint32_t arow8 = (asub & 1) * 8 + (lane & 7);
        const uint32_t acol16 = (asub >> 1) * 16;

        #pragma unroll
        for (int kk = 0; kk < 4; kk++) {
            uint32_t af[4][4];
            #pragma unroll
            for (int mi = 0; mi < 4; mi++) {
                uint32_t row  = wr * 64 + mi * 16 + arow8;
                uint32_t colb = kk * 32 + acol16;
                ldm4(aBase + sw128(row * 128u + colb),
                     af[mi][0], af[mi][1], af[mi][2], af[mi][3]);
            }
            uint32_t bfr[4][2];
            #pragma unroll
            for (int p = 0; p < 2; p++) {
                uint32_t nip  = 2 * p + (asub >> 1);
                uint32_t row  = wc * 32 + nip * 8 + (lane & 7);
                uint32_t colb = kk * 32 + (asub & 1) * 16;
                uint32_t r0, r1, r2, r3;
                ldm4(bBase + sw128(row * 128u + colb), r0, r1, r2, r3);
                bfr[2 * p][0] = r0;     bfr[2 * p][1] = r1;
                bfr[2 * p + 1][0] = r2; bfr[2 * p + 1][1] = r3;
            }
            #pragma unroll
            for (int mi = 0; mi < 4; mi++)
                #pragma unroll
                for (int n8 = 0; n8 < 4; n8++)
                    imma16832(acc[mi][n8], af[mi][0], af[mi][1], af[mi][2], af[mi][3],
                              bfr[n8][0], bfr[n8][1]);
        }
        __syncthreads();
        bufC = (bufC == NSTAGE - 1) ? 0 : bufC + 1;
    }

    // ---- epilogue
    const int g  = lane >> 2;
    const int tg = lane & 3;
    const int len = (MODE == 1) ? g_lens[z] : 0;
    const float w = scale * (PASS ? (1.0f / 128.0f) : 1.0f);
    const float* sAz = sA + (size_t)z * strSA;
    const float* sBz = sB + (size_t)z * strSB;
    float* Cz = C + (size_t)z * strC;

    #pragma unroll
    for (int mi = 0; mi < 4; mi++) {
        const int rA = row0 + wr * 64 + mi * 16 + g;
        const int rB = rA + 8;
        const float saA = sAz[rA] * w;
        const float saB = sAz[rB] * w;
        #pragma unroll
        for (int n8 = 0; n8 < 4; n8++) {
            const int col = n0 + wc * 32 + n8 * 8 + tg * 2;
            const float sb0 = sBz[col], sb1 = sBz[col + 1];
            float v0 = (float)acc[mi][n8][0] * saA * sb0;
            float v1 = (float)acc[mi][n8][1] * saA * sb1;
            float v2 = (float)acc[mi][n8][2] * saB * sb0;
            float v3 = (float)acc[mi][n8][3] * saB * sb1;
            float2* pA = (float2*)(Cz + (size_t)rA * ldc + col);
            float2* pB = (float2*)(Cz + (size_t)rB * ldc + col);
            if (MODE == 0) {
                if (PASS == 0) {
                    *pA = make_float2(v0, v1);
                    *pB = make_float2(v2, v3);
                } else {
                    float2 oA = *pA, oB = *pB;
                    *pA = make_float2(oA.x + v0, oA.y + v1);
                    *pB = make_float2(oB.x + v2, oB.y + v3);
                }
            } else {
                bool okA = rA < len, okB = rB < len;
                if (PASS == 0) {
                    *pA = okA ? make_float2(v0, v1) : make_float2(-1e9f, -1e9f);
                    *pB = okB ? make_float2(v2, v3) : make_float2(-1e9f, -1e9f);
                } else {
                    if (okA) { float2 o = *pA; *pA = make_float2(o.x + v0, o.y + v1); }
                    else     { *pA = make_float2(-1e9f, -1e9f); }
                    if (okB) { float2 o = *pB; *pB = make_float2(o.x + v2, o.y + v3); }
                    else     { *pB = make_float2(-1e9f, -1e9f); }
                }
            }
        }
    }
}

// ---------------------------------------------------------------------------
// Row softmax over Ln=2048, in place + two-plane int8 P output.
// P row max = 1/sum exactly -> scale = (1/sum)/127; q_i = 127*exp(v_i - m).
// Masked rows: exact uniform 1/2048 (a1=127, a2=0, s=(1/2048)/127).
// ---------------------------------------------------------------------------
__global__ __launch_bounds__(256)
void softmax_kernel(float* __restrict__ attn, int8_t* __restrict__ P1,
                    int8_t* __restrict__ P2, float* __restrict__ sP) {
    const size_t row = blockIdx.x;
    const int b  = (int)(row >> 11);
    const int ql = (int)(row & (Ln - 1));
    float* p = attn + row * Ln;
    const int t = threadIdx.x;

    if (ql >= g_lens[b]) {
        const float u = 1.0f / 2048.0f;
        float4 uv = make_float4(u, u, u, u);
        ((float4*)p)[t * 2]     = uv;
        ((float4*)p)[t * 2 + 1] = uv;
        char4 us = make_char4(127, 127, 127, 127);
        char4 zs = make_char4(0, 0, 0, 0);
        size_t off = row * Ln + (size_t)t * 8;
        *(char4*)(P1 + off)     = us;
        *(char4*)(P1 + off + 4) = us;
        *(char4*)(P2 + off)     = zs;
        *(char4*)(P2 + off + 4) = zs;
        if (t == 0) sP[row] = u / 127.0f;
        return;
    }

    float4 va = ((const float4*)p)[t * 2];
    float4 vb = ((const float4*)p)[t * 2 + 1];
    float v[8] = {va.x, va.y, va.z, va.w, vb.x, vb.y, vb.z, vb.w};

    float m = v[0];
    #pragma unroll
    for (int i = 1; i < 8; i++) m = fmaxf(m, v[i]);

    __shared__ float red[256];
    red[t] = m;
    __syncthreads();
    #pragma unroll
    for (int s = 128; s > 0; s >>= 1) {
        if (t < s) red[t] = fmaxf(red[t], red[t + s]);
        __syncthreads();
    }
    m = red[0];
    __syncthreads();

    float sum = 0.0f;
    #pragma unroll
    for (int i = 0; i < 8; i++) {
        v[i] = expf(v[i] - m);
        sum += v[i];
    }
    red[t] = sum;
    __syncthreads();
    #pragma unroll
    for (int s = 128; s > 0; s >>= 1) {
        if (t < s) red[t] += red[t + s];
        __syncthreads();
    }
    const float inv = 1.0f / red[0];
    if (t == 0) sP[row] = inv / 127.0f;

    char c1[8], c2[8];
    #pragma unroll
    for (int i = 0; i < 8; i++) {
        float q = 127.0f * v[i];         // in [0, 127]
        int a1 = __float2int_rn(q);
        a1 = max(0, min(127, a1));
        int a2 = __float2int_rn((q - (float)a1) * 128.0f);
        a2 = max(-127, min(127, a2));
        c1[i] = (char)a1;
        c2[i] = (char)a2;
        v[i] *= inv;
    }
    ((float4*)p)[t * 2]     = make_float4(v[0], v[1], v[2], v[3]);
    ((float4*)p)[t * 2 + 1] = make_float4(v[4], v[5], v[6], v[7]);
    size_t off = row * Ln + (size_t)t * 8;
    *(char4*)(P1 + off)     = make_char4(c1[0], c1[1], c1[2], c1[3]);
    *(char4*)(P1 + off + 4) = make_char4(c1[4], c1[5], c1[6], c1[7]);
    *(char4*)(P2 + off)     = make_char4(c2[0], c2[1], c2[2], c2[3]);
    *(char4*)(P2 + off + 4) = make_char4(c2[4], c2[5], c2[6], c2[7]);
}

// ---------------------------------------------------------------------------
// kernel_launch
// ---------------------------------------------------------------------------
#define GETSYM(var, sym) cudaGetSymbolAddress((void**)&var, sym)

extern "C" void kernel_launch(void* const* d_in, const int* in_sizes, int n_in,
                              void* d_out, int out_size) {
    const float* X  = (const float*)d_in[0];
    const void*  lens_raw = d_in[1];
    const float* O  = (const float*)d_in[2];
    const float* Wk = (const float*)d_in[3];
    const float* Wv = (const float*)d_in[4];
    const float* Wq = (const float*)d_in[5];

    const long long CTX = (long long)Bn * Ln * Dn;
    const long long ATT = (long long)Bn * Ln * Ln;

    float *ctx_s, *attn_s, *vm, *xm, *XTf, *WqTf, *WkTf, *GTf, *QGf, *PXf;
    GETSYM(ctx_s, g_ctx_scratch);  GETSYM(attn_s, g_attn_scratch);
    GETSYM(vm, g_vmean);           GETSYM(xm, g_xmean);
    GETSYM(XTf, g_XTf);            GETSYM(WqTf, g_WqTf);
    GETSYM(WkTf, g_WkTf);          GETSYM(GTf, g_GTf);
    GETSYM(QGf, g_QGf);            GETSYM(PXf, g_PXf);

    int8_t *Xq1, *Xq2, *Oq1, *Oq2, *XTq1, *XTq2, *Wvq1, *Wvq2;
    int8_t *WqTq1, *WqTq2, *WkTq1, *WkTq2, *GTq1, *GTq2;
    int8_t *QGq1, *QGq2, *Pq1, *Pq2, *PXq1, *PXq2;
    float *sX, *sO, *sXT, *sWv, *sWqT, *sWkT, *sGT, *sQG, *sP, *sPX;
    GETSYM(Xq1, g_X1);   GETSYM(Xq2, g_X2);   GETSYM(sX, g_sX);
    GETSYM(Oq1, g_O1);   GETSYM(Oq2, g_O2);   GETSYM(sO, g_sO);
    GETSYM(XTq1, g_XT1); GETSYM(XTq2, g_XT2); GETSYM(sXT, g_sXT);
    GETSYM(Wvq1, g_Wv1); GETSYM(Wvq2, g_Wv2); GETSYM(sWv, g_sWv);
    GETSYM(WqTq1, g_WqT1); GETSYM(WqTq2, g_WqT2); GETSYM(sWqT, g_sWqT);
    GETSYM(WkTq1, g_WkT1); GETSYM(WkTq2, g_WkT2); GETSYM(sWkT, g_sWkT);
    GETSYM(GTq1, g_GT1); GETSYM(GTq2, g_GT2); GETSYM(sGT, g_sGT);
    GETSYM(QGq1, g_QG1); GETSYM(QGq2, g_QG2); GETSYM(sQG, g_sQG);
    GETSYM(Pq1, g_P1);   GETSYM(Pq2, g_P2);   GETSYM(sP, g_sP);
    GETSYM(PXq1, g_PX1); GETSYM(PXq2, g_PX2); GETSYM(sPX, g_sPX);

    float* ctx;
    float* attn;
    if ((long long)out_size >= CTX + ATT) {
        ctx  = (float*)d_out;
        attn = (float*)d_out + CTX;
    } else if ((long long)out_size == ATT) {
        attn = (float*)d_out;
        ctx  = ctx_s;
    } else {
        ctx  = (float*)d_out;
        attn = attn_s;
    }

    cudaFuncSetAttribute(imma_gemm<0,0>, cudaFuncAttributeMaxDynamicSharedMemorySize, SMEM_REQ);
    cudaFuncSetAttribute(imma_gemm<0,1>, cudaFuncAttributeMaxDynamicSharedMemorySize, SMEM_REQ);
    cudaFuncSetAttribute(imma_gemm<1,0>, cudaFuncAttributeMaxDynamicSharedMemorySize, SMEM_REQ);
    cudaFuncSetAttribute(imma_gemm<1,1>, cudaFuncAttributeMaxDynamicSharedMemorySize, SMEM_REQ);

    prep_lens_kernel<<<1, 32>>>(lens_raw);

    // Transposes (fp32)
    transf_kernel<<<dim3(Dn / 32, Dn / 32, 1), 256>>>(Wq, WqTf, Dn, Dn);
    transf_kernel<<<dim3(Dn / 32, Dn / 32, 1), 256>>>(Wk, WkTf, Dn, Dn);
    transf_kernel<<<dim3(Dn / 32, Ln / 32, Bn), 256>>>(X, XTf, Ln, Dn);

    // Quantize raw operands
    rowquant_kernel<<<M_ALL, 256>>>(X, Xq1, Xq2, sX, Dn, 0);
    rowquant_kernel<<<M_ALL, 256>>>(O, Oq1, Oq2, sO, Dn, 1);
    rowquant_kernel<<<Bn * Dn, 256>>>(XTf, XTq1, XTq2, sXT, Ln, 0);
    rowquant_kernel<<<Dn, 256>>>(Wv, Wvq1, Wvq2, sWv, Dn, 0);
    rowquant_kernel<<<Dn, 256>>>(WqTf, WqTq1, WqTq2, sWqT, Dn, 0);
    rowquant_kernel<<<Dn, 256>>>(WkTf, WkTq1, WkTq2, sWkT, Dn, 0);

    // vmean (exact fp32 path for masked ctx rows)
    xmean_kernel<<<dim3(Dn / 256, Bn), 256>>>(X, xm);
    vmeanw_kernel<<<dim3(Dn / 8, Bn), 256>>>(xm, Wv, vm);

    // GT = Wk^T @ Wq  -> GTf -> quantize
    {
        dim3 grid(Dn / 128, Dn / 128, 1);
        imma_gemm<0,0><<<grid, 256, SMEM_REQ>>>(WkTq1, WkTq2, WqTq1, WqTq2, sWkT, sWqT,
                                                GTf, Dn, Dn, 0, 0, 0, 0, 0, 1.0f, 0);
        imma_gemm<0,1><<<grid, 256, SMEM_REQ>>>(WkTq1, WkTq2, WqTq1, WqTq2, sWkT, sWqT,
                                                GTf, Dn, Dn, 0, 0, 0, 0, 0, 1.0f, 0);
    }
    rowquant_kernel<<<Dn, 256>>>(GTf, GTq1, GTq2, sGT, Dn, 0);

    // QG = O @ G -> QGf -> quantize (masked row tiles skipped)
    {
        dim3 grid(Dn / 128, M_ALL / 128, 1);
        imma_gemm<0,0><<<grid, 256, SMEM_REQ>>>(Oq1, Oq2, GTq1, GTq2, sO, sGT,
                                                QGf, Dn, Dn, 0, 0, 0, 0, 0, 1.0f, 2);
        imma_gemm<0,1><<<grid, 256, SMEM_REQ>>>(Oq1, Oq2, GTq1, GTq2, sO, sGT,
                                                QGf, Dn, Dn, 0, 0, 0, 0, 0, 1.0f, 2);
    }
    rowquant_kernel<<<M_ALL, 256>>>(QGf, QGq1, QGq2, sQG, Dn, 1);

    // scores = QG @ X^T / 32 per batch, mask epilogue, masked tiles skipped
    {
        dim3 grid(Ln / 128, Ln / 128, Bn);
        imma_gemm<1,0><<<grid, 256, SMEM_REQ>>>(QGq1, QGq2, Xq1, Xq2, sQG, sX,
                                                attn, Dn, Ln,
                                                (long long)Ln * Dn, (long long)Ln * Dn,
                                                (long long)Ln * Ln, Ln, Ln, 0.03125f, 1);
        imma_gemm<1,1><<<grid, 256, SMEM_REQ>>>(QGq1, QGq2, Xq1, Xq2, sQG, sX,
                                                attn, Dn, Ln,
                                                (long long)Ln * Dn, (long long)Ln * Dn,
                                                (long long)Ln * Ln, Ln, Ln, 0.03125f, 1);
    }

    // Softmax in place + quantized P
    softmax_kernel<<<Bn * Ln, 256>>>(attn, Pq1, Pq2, sP);

    // PX = P @ X^T per batch -> PXf -> quantize (masked tiles skipped)
    {
        dim3 grid(Dn / 128, Ln / 128, Bn);
        imma_gemm<0,0><<<grid, 256, SMEM_REQ>>>(Pq1, Pq2, XTq1, XTq2, sP, sXT,
                                                PXf, Ln, Dn,
                                                (long long)Ln * Ln, (long long)Dn * Ln,
                                                (long long)Ln * Dn, Ln, Dn, 1.0f, 1);
        imma_gemm<0,1><<<grid, 256, SMEM_REQ>>>(Pq1, Pq2, XTq1, XTq2, sP, sXT,
                                                PXf, Ln, Dn,
                                                (long long)Ln * Ln, (long long)Dn * Ln,
                                                (long long)Ln * Dn, Ln, Dn, 1.0f, 1);
    }
    rowquant_kernel<<<M_ALL, 256>>>(PXf, PXq1, PXq2, sPX, Dn, 1);

    // ctx = PX @ Wv^T (masked tiles skipped; masked rows filled after)
    {
        dim3 grid(Dn / 128, M_ALL / 128, 1);
        imma_gemm<0,0><<<grid, 256, SMEM_REQ>>>(PXq1, PXq2, Wvq1, Wvq2, sPX, sWv,
                                                ctx, Dn, Dn, 0, 0, 0, 0, 0, 1.0f, 2);
        imma_gemm<0,1><<<grid, 256, SMEM_REQ>>>(PXq1, PXq2, Wvq1, Wvq2, sPX, sWv,
                                                ctx, Dn, Dn, 0, 0, 0, 0, 0, 1.0f, 2);
    }

    // Masked ctx rows = per-batch V mean
    fill_masked_kernel<<<dim3(Dn / 256, Ln, Bn), 256>>>(vm, ctx);
}

// round 9
// speedup vs baseline: 2.4051x; 2.4051x over previous
#include <cuda_runtime.h>
#include <cuda_fp16.h>
#include <math.h>
#include <stdint.h>

#define Bn 8
#define Ln 2048
#define Dn 1024
#define M_ALL (Bn * Ln)   // 16384

// ---------------------------------------------------------------------------
// Device scratch (allocation-free rule -> __device__ globals)
// ---------------------------------------------------------------------------
__device__ float g_ctx_scratch[(size_t)M_ALL * Dn];
__device__ float g_attn_scratch[(size_t)Bn * Ln * Ln];
__device__ float g_vmean[(size_t)Bn * Dn];
__device__ float g_xmean[(size_t)Bn * Dn];
__device__ int   g_lens[Bn];

// fp16 hi/lo planes
__device__ __half g_Xh[(size_t)M_ALL * Dn];
__device__ __half g_Xl[(size_t)M_ALL * Dn];
__device__ __half g_Oh[(size_t)M_ALL * Dn];
__device__ __half g_Ol[(size_t)M_ALL * Dn];
__device__ __half g_Wvh[(size_t)Dn * Dn];
__device__ __half g_Wvl[(size_t)Dn * Dn];
__device__ __half g_WqTh[(size_t)Dn * Dn];
__device__ __half g_WqTl[(size_t)Dn * Dn];
__device__ __half g_WkTh[(size_t)Dn * Dn];
__device__ __half g_WkTl[(size_t)Dn * Dn];
__device__ __half g_GTh[(size_t)Dn * Dn];
__device__ __half g_GTl[(size_t)Dn * Dn];
__device__ __half g_QGh[(size_t)M_ALL * Dn];
__device__ __half g_QGl[(size_t)M_ALL * Dn];
__device__ __half g_XTh[(size_t)Bn * Dn * Ln];
__device__ __half g_XTl[(size_t)Bn * Dn * Ln];
__device__ __half g_Ph[(size_t)M_ALL * Ln];
__device__ __half g_Pl[(size_t)M_ALL * Ln];
__device__ __half g_PXh[(size_t)M_ALL * Dn];
__device__ __half g_PXl[(size_t)M_ALL * Dn];

// ---------------------------------------------------------------------------
// lens dtype sniffing (int64 vs int32)
// ---------------------------------------------------------------------------
__global__ void prep_lens_kernel(const void* lensraw) {
    if (threadIdx.x == 0 && blockIdx.x == 0) {
        const int* a32 = (const int*)lensraw;
        bool is64 = true;
        #pragma unroll
        for (int i = 0; i < 4; i++) {
            int lo = a32[2 * i], hi = a32[2 * i + 1];
            if (hi != 0 || lo < 1 || lo > Ln) { is64 = false; break; }
        }
        if (is64) {
            const long long* a64 = (const long long*)lensraw;
            for (int i = 0; i < Bn; i++) g_lens[i] = (int)a64[i];
        } else {
            for (int i = 0; i < Bn; i++) g_lens[i] = a32[i];
        }
    }
}

// ---------------------------------------------------------------------------
// fp32 -> (hi, lo) fp16 planes, flat
// ---------------------------------------------------------------------------
__global__ __launch_bounds__(256)
void expand2_kernel(const float* __restrict__ src, __half* __restrict__ dh,
                    __half* __restrict__ dl, long long total4) {
    long long i = (long long)blockIdx.x * blockDim.x + threadIdx.x;
    if (i >= total4) return;
    float4 v = *(const float4*)(src + i * 4);
    float vv[4] = {v.x, v.y, v.z, v.w};
    unsigned short hb[4], lb[4];
    #pragma unroll
    for (int j = 0; j < 4; j++) {
        __half hbf = __float2half_rn(vv[j]);
        float hf = __half2float(hbf);
        __half lbf = __float2half_rn(vv[j] - hf);
        hb[j] = __half_as_ushort(hbf);
        lb[j] = __half_as_ushort(lbf);
    }
    *(ushort4*)(dh + i * 4) = make_ushort4(hb[0], hb[1], hb[2], hb[3]);
    *(ushort4*)(dl + i * 4) = make_ushort4(lb[0], lb[1], lb[2], lb[3]);
}

// ---------------------------------------------------------------------------
// Transpose fp32 [R,C] -> fp16 hi/lo planes [C,R]; batched via blockIdx.z.
// ---------------------------------------------------------------------------
__global__ __launch_bounds__(256)
void trans_kernel(const float* __restrict__ src, __half* __restrict__ oh,
                  __half* __restrict__ ol, int R, int C) {
    __shared__ float tile[32][33];
    size_t bo = (size_t)blockIdx.z * R * C;
    src += bo; oh += bo; ol += bo;
    int c0 = blockIdx.x * 32;
    int r0 = blockIdx.y * 32;
    int tx = threadIdx.x & 31;
    int ty = threadIdx.x >> 5;

    #pragma unroll
    for (int j = 0; j < 4; j++)
        tile[ty + j * 8][tx] = src[(size_t)(r0 + ty + j * 8) * C + c0 + tx];
    __syncthreads();

    #pragma unroll
    for (int j = 0; j < 4; j++) {
        float v = tile[tx][ty + j * 8];
        __half h = __float2half_rn(v);
        __half l = __float2half_rn(v - __half2float(h));
        size_t o = (size_t)(c0 + ty + j * 8) * R + r0 + tx;
        oh[o] = h;
        ol[o] = l;
    }
}

// ---------------------------------------------------------------------------
// xmean[b][d] = (1/2048) * sum_t X[b*Ln+t][d]
// ---------------------------------------------------------------------------
__global__ __launch_bounds__(256)
void xmean_kernel(const float* __restrict__ xf, float* __restrict__ xm) {
    int b = blockIdx.y;
    int d = blockIdx.x * 256 + threadIdx.x;
    const float* p = xf + (size_t)b * Ln * Dn + d;
    float s0 = 0.f, s1 = 0.f, s2 = 0.f, s3 = 0.f;
    for (int t = 0; t < Ln; t += 4) {
        s0 += p[(size_t)(t + 0) * Dn];
        s1 += p[(size_t)(t + 1) * Dn];
        s2 += p[(size_t)(t + 2) * Dn];
        s3 += p[(size_t)(t + 3) * Dn];
    }
    xm[b * Dn + d] = (s0 + s1 + s2 + s3) * (1.0f / 2048.0f);
}

// ---------------------------------------------------------------------------
// vmean[b][e] = sum_d xmean[b][d] * Wv[e][d]
// ---------------------------------------------------------------------------
__global__ __launch_bounds__(256)
void vmeanw_kernel(const float* __restrict__ xm, const float* __restrict__ Wv,
                   float* __restrict__ vm) {
    int b = blockIdx.y;
    int e = blockIdx.x * 8 + (threadIdx.x >> 5);
    int lane = threadIdx.x & 31;
    const float* xr = xm + b * Dn;
    const float* wr = Wv + (size_t)e * Dn;
    float s = 0.f;
    for (int d = lane; d < Dn; d += 32) s += xr[d] * wr[d];
    #pragma unroll
    for (int o = 16; o > 0; o >>= 1) s += __shfl_down_sync(0xffffffffu, s, o);
    if (lane == 0) vm[b * Dn + e] = s;
}

// ---------------------------------------------------------------------------
// Fill masked ctx rows with vmean
// ---------------------------------------------------------------------------
__global__ __launch_bounds__(256)
void fill_masked_kernel(const float* __restrict__ vm, float* __restrict__ ctx) {
    int b = blockIdx.z;
    int q = blockIdx.y;
    if (q < g_lens[b]) return;
    int d = blockIdx.x * 256 + threadIdx.x;
    ctx[((size_t)b * Ln + q) * Dn + d] = vm[b * Dn + d];
}

// ---------------------------------------------------------------------------
// HMMA GEMM core (mma.sync m16n8k16 fp16, fp32 accum), NT.
// nseg=3: (Ah,Bh), (Ah,Bl), (Al,Bh).   nseg=2: (Ah,Bh), (Al,Bh).
// BM=BN=128, BK=64, 3-stage cp.async, 8 warps 2x4, warp tile 64x32.
// MODE 0: fp32 C. MODE 1: scale+mask fp32 C. MODE 2: write hi/lo fp16 planes.
// skipMode 1: skip tile if local row0 >= lens[z]
// skipMode 2: skip tile if (row0 & 2047) >= lens[row0 >> 11]
// ---------------------------------------------------------------------------
__device__ __forceinline__ uint32_t sw128(uint32_t x) { return x ^ ((x >> 3) & 0x70); }

#define STAGE_B 32768
#define NSTAGE  3
#define SMEM_REQ (1024 + NSTAGE * STAGE_B)

__device__ __forceinline__ void cp16(uint32_t saddr, const void* gaddr) {
    asm volatile("cp.async.cg.shared.global [%0], [%1], 16;" :: "r"(saddr), "l"(gaddr));
}
__device__ __forceinline__ void cp_commit() {
    asm volatile("cp.async.commit_group;" ::: "memory");
}
template <int N> __device__ __forceinline__ void cp_wait() {
    asm volatile("cp.async.wait_group %0;" :: "n"(N) : "memory");
}
__device__ __forceinline__ void ldm4(uint32_t addr, uint32_t& r0, uint32_t& r1,
                                     uint32_t& r2, uint32_t& r3) {
    asm volatile("ldmatrix.sync.aligned.m8n8.x4.shared.b16 {%0,%1,%2,%3}, [%4];"
                 : "=r"(r0), "=r"(r1), "=r"(r2), "=r"(r3) : "r"(addr));
}
__device__ __forceinline__ void mma16816(float* c, uint32_t a0, uint32_t a1,
                                         uint32_t a2, uint32_t a3,
                                         uint32_t b0, uint32_t b1) {
    asm volatile(
        "mma.sync.aligned.m16n8k16.row.col.f32.f16.f16.f32 "
        "{%0,%1,%2,%3},{%4,%5,%6,%7},{%8,%9},{%0,%1,%2,%3};"
        : "+f"(c[0]), "+f"(c[1]), "+f"(c[2]), "+f"(c[3])
        : "r"(a0), "r"(a1), "r"(a2), "r"(a3), "r"(b0), "r"(b1));
}
__device__ __forceinline__ uint32_t pack_h2(__half a, __half b) {
    return (uint32_t)__half_as_ushort(a) | ((uint32_t)__half_as_ushort(b) << 16);
}

template <int MODE>
__global__ __launch_bounds__(256, 2)
void hmma_gemm(const __half* __restrict__ Ah, const __half* __restrict__ Al,
               const __half* __restrict__ Bh, const __half* __restrict__ Bl,
               float* __restrict__ C,
               __half* __restrict__ Poh, __half* __restrict__ Pol,
               int K, int ldc,
               long long sA, long long sB, long long sC, float scale,
               int skipMode, int nseg) {
    const int z    = blockIdx.z;
    const int row0 = blockIdx.y * 128;
    const int n0   = blockIdx.x * 128;

    if (skipMode == 1) {
        if (row0 >= g_lens[z]) return;
    } else if (skipMode == 2) {
        if ((row0 & (Ln - 1)) >= g_lens[row0 >> 11]) return;
    }

    extern __shared__ char dsm[];
    uint32_t sraw = (uint32_t)__cvta_generic_to_shared(dsm);
    uint32_t sb   = (sraw + 1023) & ~1023u;

    const int tid  = threadIdx.x;
    const int lane = tid & 31;
    const int wid  = tid >> 5;
    const int wr   = wid >> 2;
    const int wc   = wid & 3;

    const int r = tid >> 1;
    const int h = (tid & 1) * 64;

    const char* aRowH = (const char*)(Ah + (size_t)z * sA + (size_t)(row0 + r) * K) + h;
    const char* aRowL = (const char*)(Al + (size_t)z * sA + (size_t)(row0 + r) * K) + h;
    const char* bRowH = (const char*)(Bh + (size_t)z * sB + (size_t)(n0 + r) * K) + h;
    const char* bRowL = (const char*)(Bl + (size_t)z * sB + (size_t)(n0 + r) * K) + h;

    uint32_t swo[4];
    #pragma unroll
    for (int i = 0; i < 4; i++) swo[i] = sw128((uint32_t)r * 128u + h + i * 16);

    float acc[4][4][4];
    #pragma unroll
    for (int a = 0; a < 4; a++)
        #pragma unroll
        for (int b = 0; b < 4; b++)
            #pragma unroll
            for (int cc = 0; cc < 4; cc++) acc[a][b][cc] = 0.0f;

    const int nch = K / 64;
    const int T   = nseg * nch;

    const char* aPtr = aRowH;
    const char* bPtr = bRowH;
    int cIss = 0, segIss = 0, bufIss = 0;

    auto issue_one = [&]() {
        uint32_t sa = sb + bufIss * STAGE_B;
        #pragma unroll
        for (int i = 0; i < 4; i++) {
            cp16(sa + swo[i], aPtr + i * 16);
            cp16(sa + 16384 + swo[i], bPtr + i * 16);
        }
        cp_commit();
        aPtr += 128; bPtr += 128;
        bufIss = (bufIss == NSTAGE - 1) ? 0 : bufIss + 1;
        if (++cIss == nch) {
            cIss = 0; segIss++;
            if (segIss == 1) {
                if (nseg == 2) { aPtr = aRowL; bPtr = bRowH; }
                else           { aPtr = aRowH; bPtr = bRowL; }
            } else if (segIss == 2) {
                aPtr = aRowL; bPtr = bRowH;
            }
        }
    };

    issue_one();
    issue_one();

    int bufC = 0;
    for (int t = 0; t < T; t++) {
        if (t + 2 < T)      { issue_one(); cp_wait<2>(); }
        else if (t + 1 < T) { cp_wait<1>(); }
        else                { cp_wait<0>(); }
        __syncthreads();

        const uint32_t aBase = sb + bufC * STAGE_B;
        const uint32_t bBase = aBase + 16384;

        #pragma unroll
        for (int kk = 0; kk < 4; kk++) {
            uint32_t af[4][4];
            #pragma unroll
            for (int mi = 0; mi < 4; mi++) {
                uint32_t row  = wr * 64 + mi * 16 + (lane & 15);
                uint32_t colb = kk * 32 + ((lane >> 4) << 4);
                ldm4(aBase + sw128(row * 128u + colb), af[mi][0], af[mi][1], af[mi][2], af[mi][3]);
            }
            uint32_t bf[2][4];
            #pragma unroll
            for (int ni = 0; ni < 2; ni++) {
                uint32_t q    = lane >> 3;
                uint32_t row  = wc * 32 + ni * 16 + ((q >> 1) << 3) + (lane & 7);
                uint32_t colb = kk * 32 + ((q & 1) << 4);
                ldm4(bBase + sw128(row * 128u + colb), bf[ni][0], bf[ni][1], bf[ni][2], bf[ni][3]);
            }
            #pragma unroll
            for (int mi = 0; mi < 4; mi++)
                #pragma unroll
                for (int n8 = 0; n8 < 4; n8++) {
                    uint32_t b0 = bf[n8 >> 1][(n8 & 1) * 2 + 0];
                    uint32_t b1 = bf[n8 >> 1][(n8 & 1) * 2 + 1];
                    mma16816(acc[mi][n8], af[mi][0], af[mi][1], af[mi][2], af[mi][3], b0, b1);
                }
        }
        __syncthreads();
        bufC = (bufC == NSTAGE - 1) ? 0 : bufC + 1;
    }

    // ---- epilogue
    const int g  = lane >> 2;
    const int tg = lane & 3;
    const int len = (MODE == 1) ? g_lens[z] : 0;

    #pragma unroll
    for (int mi = 0; mi < 4; mi++) {
        const int rA = row0 + wr * 64 + mi * 16 + g;
        const int rB = rA + 8;
        #pragma unroll
        for (int n8 = 0; n8 < 4; n8++) {
            const int col = n0 + wc * 32 + n8 * 8 + tg * 2;
            float v0 = acc[mi][n8][0], v1 = acc[mi][n8][1];
            float v2 = acc[mi][n8][2], v3 = acc[mi][n8][3];
            if (MODE == 0) {
                float* Cz = C + (size_t)z * sC;
                *(float2*)(Cz + (size_t)rA * ldc + col) = make_float2(v0, v1);
                *(float2*)(Cz + (size_t)rB * ldc + col) = make_float2(v2, v3);
            } else if (MODE == 1) {
                float* Cz = C + (size_t)z * sC;
                bool okA = rA < len, okB = rB < len;
                *(float2*)(Cz + (size_t)rA * ldc + col) =
                    make_float2(okA ? v0 * scale : -1e9f, okA ? v1 * scale : -1e9f);
                *(float2*)(Cz + (size_t)rB * ldc + col) =
                    make_float2(okB ? v2 * scale : -1e9f, okB ? v3 * scale : -1e9f);
            } else {
                __half* PohZ = Poh + (size_t)z * sC;
                __half* PolZ = Pol + (size_t)z * sC;
                __half h0 = __float2half_rn(v0), h1 = __float2half_rn(v1);
                __half h2 = __float2half_rn(v2), h3 = __float2half_rn(v3);
                __half l0 = __float2half_rn(v0 - __half2float(h0));
                __half l1 = __float2half_rn(v1 - __half2float(h1));
                __half l2 = __float2half_rn(v2 - __half2float(h2));
                __half l3 = __float2half_rn(v3 - __half2float(h3));
                *(uint32_t*)(PohZ + (size_t)rA * ldc + col) = pack_h2(h0, h1);
                *(uint32_t*)(PohZ + (size_t)rB * ldc + col) = pack_h2(h2, h3);
                *(uint32_t*)(PolZ + (size_t)rA * ldc + col) = pack_h2(l0, l1);
                *(uint32_t*)(PolZ + (size_t)rB * ldc + col) = pack_h2(l2, l3);
            }
        }
    }
}

// ---------------------------------------------------------------------------
// Row softmax over Ln=2048, in place + hi/lo fp16 plane outputs.
// Masked rows (q >= len): exact uniform 1/2048, no reads.
// ---------------------------------------------------------------------------
__global__ __launch_bounds__(256)
void softmax_kernel(float* __restrict__ attn, __half* __restrict__ Ph,
                    __half* __restrict__ Pl) {
    const size_t row = blockIdx.x;
    const int b  = (int)(row >> 11);
    const int ql = (int)(row & (Ln - 1));
    float* p = attn + row * Ln;
    const int t = threadIdx.x;

    if (ql >= g_lens[b]) {
        const float u = 1.0f / 2048.0f;
        const unsigned short uh = __half_as_ushort(__float2half_rn(u));
        float4 uv = make_float4(u, u, u, u);
        ((float4*)p)[t * 2]     = uv;
        ((float4*)p)[t * 2 + 1] = uv;
        ushort4 us = make_ushort4(uh, uh, uh, uh);
        ushort4 zs = make_ushort4(0, 0, 0, 0);
        __half* ph = Ph + row * Ln + t * 8;
        __half* pl = Pl + row * Ln + t * 8;
        *(ushort4*)(ph) = us; *(ushort4*)(ph + 4) = us;
        *(ushort4*)(pl) = zs; *(ushort4*)(pl + 4) = zs;
        return;
    }

    float4 va = ((const float4*)p)[t * 2];
    float4 vb = ((const float4*)p)[t * 2 + 1];
    float v[8] = {va.x, va.y, va.z, va.w, vb.x, vb.y, vb.z, vb.w};

    float m = v[0];
    #pragma unroll
    for (int i = 1; i < 8; i++) m = fmaxf(m, v[i]);

    __shared__ float red[256];
    red[t] = m;
    __syncthreads();
    #pragma unroll
    for (int s = 128; s > 0; s >>= 1) {
        if (t < s) red[t] = fmaxf(red[t], red[t + s]);
        __syncthreads();
    }
    m = red[0];
    __syncthreads();

    float sum = 0.0f;
    #pragma unroll
    for (int i = 0; i < 8; i++) {
        v[i] = expf(v[i] - m);
        sum += v[i];
    }
    red[t] = sum;
    __syncthreads();
    #pragma unroll
    for (int s = 128; s > 0; s >>= 1) {
        if (t < s) red[t] += red[t + s];
        __syncthreads();
    }
    const float inv = 1.0f / red[0];

    unsigned short hb[8], lb[8];
    #pragma unroll
    for (int i = 0; i < 8; i++) {
        v[i] *= inv;
        __half hbf = __float2half_rn(v[i]);
        float hf = __half2float(hbf);
        __half lbf = __float2half_rn(v[i] - hf);
        hb[i] = __half_as_ushort(hbf);
        lb[i] = __half_as_ushort(lbf);
    }
    ((float4*)p)[t * 2]     = make_float4(v[0], v[1], v[2], v[3]);
    ((float4*)p)[t * 2 + 1] = make_float4(v[4], v[5], v[6], v[7]);
    __half* ph = Ph + row * Ln + t * 8;
    __half* pl = Pl + row * Ln + t * 8;
    *(ushort4*)(ph)     = make_ushort4(hb[0], hb[1], hb[2], hb[3]);
    *(ushort4*)(ph + 4) = make_ushort4(hb[4], hb[5], hb[6], hb[7]);
    *(ushort4*)(pl)     = make_ushort4(lb[0], lb[1], lb[2], lb[3]);
    *(ushort4*)(pl + 4) = make_ushort4(lb[4], lb[5], lb[6], lb[7]);
}

// ---------------------------------------------------------------------------
// kernel_launch
// ---------------------------------------------------------------------------
extern "C" void kernel_launch(void* const* d_in, const int* in_sizes, int n_in,
                              void* d_out, int out_size) {
    const float* X  = (const float*)d_in[0];
    const void*  lens_raw = d_in[1];
    const float* O  = (const float*)d_in[2];
    const float* Wk = (const float*)d_in[3];
    const float* Wv = (const float*)d_in[4];
    const float* Wq = (const float*)d_in[5];

    const long long CTX = (long long)Bn * Ln * Dn;
    const long long ATT = (long long)Bn * Ln * Ln;

    float *ctx_s, *attn_s, *vm, *xm;
    __half *Xh, *Xl, *Oh, *Ol, *Wvh, *Wvl, *WqTh, *WqTl, *WkTh, *WkTl;
    __half *GTh, *GTl, *QGh, *QGl, *XTh, *XTl, *Ph, *Pl, *PXh, *PXl;
    cudaGetSymbolAddress((void**)&ctx_s, g_ctx_scratch);
    cudaGetSymbolAddress((void**)&attn_s, g_attn_scratch);
    cudaGetSymbolAddress((void**)&vm, g_vmean);
    cudaGetSymbolAddress((void**)&xm, g_xmean);
    cudaGetSymbolAddress((void**)&Xh, g_Xh);   cudaGetSymbolAddress((void**)&Xl, g_Xl);
    cudaGetSymbolAddress((void**)&Oh, g_Oh);   cudaGetSymbolAddress((void**)&Ol, g_Ol);
    cudaGetSymbolAddress((void**)&Wvh, g_Wvh); cudaGetSymbolAddress((void**)&Wvl, g_Wvl);
    cudaGetSymbolAddress((void**)&WqTh, g_WqTh); cudaGetSymbolAddress((void**)&WqTl, g_WqTl);
    cudaGetSymbolAddress((void**)&WkTh, g_WkTh); cudaGetSymbolAddress((void**)&WkTl, g_WkTl);
    cudaGetSymbolAddress((void**)&GTh, g_GTh); cudaGetSymbolAddress((void**)&GTl, g_GTl);
    cudaGetSymbolAddress((void**)&QGh, g_QGh); cudaGetSymbolAddress((void**)&QGl, g_QGl);
    cudaGetSymbolAddress((void**)&XTh, g_XTh); cudaGetSymbolAddress((void**)&XTl, g_XTl);
    cudaGetSymbolAddress((void**)&Ph, g_Ph);   cudaGetSymbolAddress((void**)&Pl, g_Pl);
    cudaGetSymbolAddress((void**)&PXh, g_PXh); cudaGetSymbolAddress((void**)&PXl, g_PXl);

    float* ctx;
    float* attn;
    if ((long long)out_size >= CTX + ATT) {
        ctx  = (float*)d_out;
        attn = (float*)d_out + CTX;
    } else if ((long long)out_size == ATT) {
        attn = (float*)d_out;
        ctx  = ctx_s;
    } else {
        ctx  = (float*)d_out;
        attn = attn_s;
    }

    cudaFuncSetAttribute(hmma_gemm<0>, cudaFuncAttributeMaxDynamicSharedMemorySize, SMEM_REQ);
    cudaFuncSetAttribute(hmma_gemm<1>, cudaFuncAttributeMaxDynamicSharedMemorySize, SMEM_REQ);
    cudaFuncSetAttribute(hmma_gemm<2>, cudaFuncAttributeMaxDynamicSharedMemorySize, SMEM_REQ);

    prep_lens_kernel<<<1, 32>>>(lens_raw);

    // Expansions + transposes of raw inputs
    {
        long long t4 = (long long)M_ALL * Dn / 4;
        int blocks = (int)((t4 + 255) / 256);
        expand2_kernel<<<blocks, 256>>>(X, Xh, Xl, t4);
        expand2_kernel<<<blocks, 256>>>(O, Oh, Ol, t4);
        long long w4 = (long long)Dn * Dn / 4;
        int wb = (int)((w4 + 255) / 256);
        expand2_kernel<<<wb, 256>>>(Wv, Wvh, Wvl, w4);
        trans_kernel<<<dim3(Dn / 32, Dn / 32, 1), 256>>>(Wq, WqTh, WqTl, Dn, Dn);
        trans_kernel<<<dim3(Dn / 32, Dn / 32, 1), 256>>>(Wk, WkTh, WkTl, Dn, Dn);
        trans_kernel<<<dim3(Dn / 32, Ln / 32, Bn), 256>>>(X, XTh, XTl, Ln, Dn);
    }

    // vmean = (mean_t X) @ Wv^T  (exact fp32 path for masked ctx rows)
    xmean_kernel<<<dim3(Dn / 256, Bn), 256>>>(X, xm);
    vmeanw_kernel<<<dim3(Dn / 8, Bn), 256>>>(xm, Wv, vm);

    // GT = Wk^T @ Wq   (3 segments — feeds everything downstream)
    hmma_gemm<2><<<dim3(Dn / 128, Dn / 128, 1), 256, SMEM_REQ>>>(
        WkTh, WkTl, WqTh, WqTl, nullptr, GTh, GTl, Dn, Dn, 0, 0, 0, 1.0f, 0, 3);

    // QG = O @ G; masked row tiles skipped (3 segments)
    hmma_gemm<2><<<dim3(Dn / 128, M_ALL / 128, 1), 256, SMEM_REQ>>>(
        Oh, Ol, GTh, GTl, nullptr, QGh, QGl, Dn, Dn, 0, 0, 0, 1.0f, 2, 3);

    // scores = QG @ X^T / 32 per batch, mask epilogue, masked tiles skipped
    // (2 segments: drop Ah*Bl cross term, ~2^-12 relative)
    hmma_gemm<1><<<dim3(Ln / 128, Ln / 128, Bn), 256, SMEM_REQ>>>(
        QGh, QGl, Xh, Xl, attn, nullptr, nullptr, Dn, Ln,
        (long long)Ln * Dn, (long long)Ln * Dn, (long long)Ln * Ln, 0.03125f, 1, 2);

    // Softmax in place + P hi/lo planes (uniform fill for masked rows)
    softmax_kernel<<<Bn * Ln, 256>>>(attn, Ph, Pl);

    // PX = P @ X per batch; masked tiles skipped (2 segments)
    hmma_gemm<2><<<dim3(Dn / 128, Ln / 128, Bn), 256, SMEM_REQ>>>(
        Ph, Pl, XTh, XTl, nullptr, PXh, PXl, Ln, Dn,
        (long long)Ln * Ln, (long long)Dn * Ln, (long long)Ln * Dn, 1.0f, 1, 2);

    // ctx = PX @ Wv^T; masked tiles skipped (3 segments)
    hmma_gemm<0><<<dim3(Dn / 128, M_ALL / 128, 1), 256, SMEM_REQ>>>(
        PXh, PXl, Wvh, Wvl, ctx, nullptr, nullptr, Dn, Dn, 0, 0, 0, 1.0f, 2, 3);

    // Masked ctx rows = per-batch V mean
    fill_masked_kernel<<<dim3(Dn / 256, Ln, Bn), 256>>>(vm, ctx);
}

// round 10
// speedup vs baseline: 2.6817x; 1.1150x over previous
#include <cuda_runtime.h>
#include <cuda_fp16.h>
#include <math.h>
#include <stdint.h>

#define Bn 8
#define Ln 2048
#define Dn 1024
#define M_ALL (Bn * Ln)   // 16384

// ---------------------------------------------------------------------------
// Device scratch (allocation-free rule -> __device__ globals)
// ---------------------------------------------------------------------------
__device__ float g_ctx_scratch[(size_t)M_ALL * Dn];
__device__ float g_attn_scratch[(size_t)Bn * Ln * Ln];
__device__ float g_vmean[(size_t)Bn * Dn];
__device__ float g_xmean[(size_t)Bn * Dn];
__device__ int   g_lens[Bn];

// fp16 hi/lo planes
__device__ __half g_Xh[(size_t)M_ALL * Dn];
__device__ __half g_Xl[(size_t)M_ALL * Dn];
__device__ __half g_Oh[(size_t)M_ALL * Dn];
__device__ __half g_Ol[(size_t)M_ALL * Dn];
__device__ __half g_Wvh[(size_t)Dn * Dn];
__device__ __half g_Wvl[(size_t)Dn * Dn];
__device__ __half g_WqTh[(size_t)Dn * Dn];
__device__ __half g_WqTl[(size_t)Dn * Dn];
__device__ __half g_WkTh[(size_t)Dn * Dn];
__device__ __half g_WkTl[(size_t)Dn * Dn];
__device__ __half g_GTh[(size_t)Dn * Dn];
__device__ __half g_GTl[(size_t)Dn * Dn];
__device__ __half g_QGh[(size_t)M_ALL * Dn];
__device__ __half g_QGl[(size_t)M_ALL * Dn];
__device__ __half g_XTh[(size_t)Bn * Dn * Ln];
__device__ __half g_XTl[(size_t)Bn * Dn * Ln];
__device__ __half g_Ph[(size_t)M_ALL * Ln];
__device__ __half g_Pl[(size_t)M_ALL * Ln];
__device__ __half g_PXh[(size_t)M_ALL * Dn];
__device__ __half g_PXl[(size_t)M_ALL * Dn];

// ---------------------------------------------------------------------------
// lens dtype sniffing (int64 vs int32)
// ---------------------------------------------------------------------------
__global__ void prep_lens_kernel(const void* lensraw) {
    if (threadIdx.x == 0 && blockIdx.x == 0) {
        const int* a32 = (const int*)lensraw;
        bool is64 = true;
        #pragma unroll
        for (int i = 0; i < 4; i++) {
            int lo = a32[2 * i], hi = a32[2 * i + 1];
            if (hi != 0 || lo < 1 || lo > Ln) { is64 = false; break; }
        }
        if (is64) {
            const long long* a64 = (const long long*)lensraw;
            for (int i = 0; i < Bn; i++) g_lens[i] = (int)a64[i];
        } else {
            for (int i = 0; i < Bn; i++) g_lens[i] = a32[i];
        }
    }
}

// ---------------------------------------------------------------------------
// fp32 -> (hi, lo) fp16 planes, flat
// ---------------------------------------------------------------------------
__global__ __launch_bounds__(256)
void expand2_kernel(const float* __restrict__ src, __half* __restrict__ dh,
                    __half* __restrict__ dl, long long total4) {
    long long i = (long long)blockIdx.x * blockDim.x + threadIdx.x;
    if (i >= total4) return;
    float4 v = *(const float4*)(src + i * 4);
    float vv[4] = {v.x, v.y, v.z, v.w};
    unsigned short hb[4], lb[4];
    #pragma unroll
    for (int j = 0; j < 4; j++) {
        __half hbf = __float2half_rn(vv[j]);
        float hf = __half2float(hbf);
        __half lbf = __float2half_rn(vv[j] - hf);
        hb[j] = __half_as_ushort(hbf);
        lb[j] = __half_as_ushort(lbf);
    }
    *(ushort4*)(dh + i * 4) = make_ushort4(hb[0], hb[1], hb[2], hb[3]);
    *(ushort4*)(dl + i * 4) = make_ushort4(lb[0], lb[1], lb[2], lb[3]);
}

// ---------------------------------------------------------------------------
// Transpose fp32 [R,C] -> fp16 hi/lo planes [C,R]; batched via blockIdx.z.
// ---------------------------------------------------------------------------
__global__ __launch_bounds__(256)
void trans_kernel(const float* __restrict__ src, __half* __restrict__ oh,
                  __half* __restrict__ ol, int R, int C) {
    __shared__ float tile[32][33];
    size_t bo = (size_t)blockIdx.z * R * C;
    src += bo; oh += bo; ol += bo;
    int c0 = blockIdx.x * 32;
    int r0 = blockIdx.y * 32;
    int tx = threadIdx.x & 31;
    int ty = threadIdx.x >> 5;

    #pragma unroll
    for (int j = 0; j < 4; j++)
        tile[ty + j * 8][tx] = src[(size_t)(r0 + ty + j * 8) * C + c0 + tx];
    __syncthreads();

    #pragma unroll
    for (int j = 0; j < 4; j++) {
        float v = tile[tx][ty + j * 8];
        __half h = __float2half_rn(v);
        __half l = __float2half_rn(v - __half2float(h));
        size_t o = (size_t)(c0 + ty + j * 8) * R + r0 + tx;
        oh[o] = h;
        ol[o] = l;
    }
}

// ---------------------------------------------------------------------------
// xmean[b][d] = (1/2048) * sum_t X[b*Ln+t][d]
// ---------------------------------------------------------------------------
__global__ __launch_bounds__(256)
void xmean_kernel(const float* __restrict__ xf, float* __restrict__ xm) {
    int b = blockIdx.y;
    int d = blockIdx.x * 256 + threadIdx.x;
    const float* p = xf + (size_t)b * Ln * Dn + d;
    float s0 = 0.f, s1 = 0.f, s2 = 0.f, s3 = 0.f;
    for (int t = 0; t < Ln; t += 4) {
        s0 += p[(size_t)(t + 0) * Dn];
        s1 += p[(size_t)(t + 1) * Dn];
        s2 += p[(size_t)(t + 2) * Dn];
        s3 += p[(size_t)(t + 3) * Dn];
    }
    xm[b * Dn + d] = (s0 + s1 + s2 + s3) * (1.0f / 2048.0f);
}

// ---------------------------------------------------------------------------
// vmean[b][e] = sum_d xmean[b][d] * Wv[e][d]
// ---------------------------------------------------------------------------
__global__ __launch_bounds__(256)
void vmeanw_kernel(const float* __restrict__ xm, const float* __restrict__ Wv,
                   float* __restrict__ vm) {
    int b = blockIdx.y;
    int e = blockIdx.x * 8 + (threadIdx.x >> 5);
    int lane = threadIdx.x & 31;
    const float* xr = xm + b * Dn;
    const float* wr = Wv + (size_t)e * Dn;
    float s = 0.f;
    for (int d = lane; d < Dn; d += 32) s += xr[d] * wr[d];
    #pragma unroll
    for (int o = 16; o > 0; o >>= 1) s += __shfl_down_sync(0xffffffffu, s, o);
    if (lane == 0) vm[b * Dn + e] = s;
}

// ---------------------------------------------------------------------------
// Fill masked ctx rows with vmean
// ---------------------------------------------------------------------------
__global__ __launch_bounds__(256)
void fill_masked_kernel(const float* __restrict__ vm, float* __restrict__ ctx) {
    int b = blockIdx.z;
    int q = blockIdx.y;
    if (q < g_lens[b]) return;
    int d = blockIdx.x * 256 + threadIdx.x;
    ctx[((size_t)b * Ln + q) * Dn + d] = vm[b * Dn + d];
}

// ---------------------------------------------------------------------------
// HMMA GEMM core (mma.sync m16n8k16 fp16, fp32 accum), NT.
// nseg=3: (Ah,Bh), (Ah,Bl), (Al,Bh).   nseg=2: (Ah,Bh), (Al,Bh).
// BM=BN=128, BK=64, 3-stage cp.async, 8 warps 2x4, warp tile 64x32.
// MODE 0: fp32 C. MODE 1: scale+mask fp32 C. MODE 2: write hi/lo fp16 planes.
// skipMode 1: skip tile if local row0 >= lens[z]
// skipMode 2: skip tile if (row0 & 2047) >= lens[row0 >> 11]
// ---------------------------------------------------------------------------
__device__ __forceinline__ uint32_t sw128(uint32_t x) { return x ^ ((x >> 3) & 0x70); }

#define STAGE_B 32768
#define NSTAGE  3
#define SMEM_REQ (1024 + NSTAGE * STAGE_B)

__device__ __forceinline__ void cp16(uint32_t saddr, const void* gaddr) {
    asm volatile("cp.async.cg.shared.global [%0], [%1], 16;" :: "r"(saddr), "l"(gaddr));
}
__device__ __forceinline__ void cp_commit() {
    asm volatile("cp.async.commit_group;" ::: "memory");
}
template <int N> __device__ __forceinline__ void cp_wait() {
    asm volatile("cp.async.wait_group %0;" :: "n"(N) : "memory");
}
__device__ __forceinline__ void ldm4(uint32_t addr, uint32_t& r0, uint32_t& r1,
                                     uint32_t& r2, uint32_t& r3) {
    asm volatile("ldmatrix.sync.aligned.m8n8.x4.shared.b16 {%0,%1,%2,%3}, [%4];"
                 : "=r"(r0), "=r"(r1), "=r"(r2), "=r"(r3) : "r"(addr));
}
__device__ __forceinline__ void mma16816(float* c, uint32_t a0, uint32_t a1,
                                         uint32_t a2, uint32_t a3,
                                         uint32_t b0, uint32_t b1) {
    asm volatile(
        "mma.sync.aligned.m16n8k16.row.col.f32.f16.f16.f32 "
        "{%0,%1,%2,%3},{%4,%5,%6,%7},{%8,%9},{%0,%1,%2,%3};"
        : "+f"(c[0]), "+f"(c[1]), "+f"(c[2]), "+f"(c[3])
        : "r"(a0), "r"(a1), "r"(a2), "r"(a3), "r"(b0), "r"(b1));
}
__device__ __forceinline__ uint32_t pack_h2(__half a, __half b) {
    return (uint32_t)__half_as_ushort(a) | ((uint32_t)__half_as_ushort(b) << 16);
}

template <int MODE>
__global__ __launch_bounds__(256, 2)
void hmma_gemm(const __half* __restrict__ Ah, const __half* __restrict__ Al,
               const __half* __restrict__ Bh, const __half* __restrict__ Bl,
               float* __restrict__ C,
               __half* __restrict__ Poh, __half* __restrict__ Pol,
               int K, int ldc,
               long long sA, long long sB, long long sC, float scale,
               int skipMode, int nseg) {
    const int z    = blockIdx.z;
    const int row0 = blockIdx.y * 128;
    const int n0   = blockIdx.x * 128;

    if (skipMode == 1) {
        if (row0 >= g_lens[z]) return;
    } else if (skipMode == 2) {
        if ((row0 & (Ln - 1)) >= g_lens[row0 >> 11]) return;
    }

    extern __shared__ char dsm[];
    uint32_t sraw = (uint32_t)__cvta_generic_to_shared(dsm);
    uint32_t sb   = (sraw + 1023) & ~1023u;

    const int tid  = threadIdx.x;
    const int lane = tid & 31;
    const int wid  = tid >> 5;
    const int wr   = wid >> 2;
    const int wc   = wid & 3;

    const int r = tid >> 1;
    const int h = (tid & 1) * 64;

    const char* aRowH = (const char*)(Ah + (size_t)z * sA + (size_t)(row0 + r) * K) + h;
    const char* aRowL = (const char*)(Al + (size_t)z * sA + (size_t)(row0 + r) * K) + h;
    const char* bRowH = (const char*)(Bh + (size_t)z * sB + (size_t)(n0 + r) * K) + h;
    const char* bRowL = (const char*)(Bl + (size_t)z * sB + (size_t)(n0 + r) * K) + h;

    uint32_t swo[4];
    #pragma unroll
    for (int i = 0; i < 4; i++) swo[i] = sw128((uint32_t)r * 128u + h + i * 16);

    float acc[4][4][4];
    #pragma unroll
    for (int a = 0; a < 4; a++)
        #pragma unroll
        for (int b = 0; b < 4; b++)
            #pragma unroll
            for (int cc = 0; cc < 4; cc++) acc[a][b][cc] = 0.0f;

    const int nch = K / 64;
    const int T   = nseg * nch;

    const char* aPtr = aRowH;
    const char* bPtr = bRowH;
    int cIss = 0, segIss = 0, bufIss = 0;

    auto issue_one = [&]() {
        uint32_t sa = sb + bufIss * STAGE_B;
        #pragma unroll
        for (int i = 0; i < 4; i++) {
            cp16(sa + swo[i], aPtr + i * 16);
            cp16(sa + 16384 + swo[i], bPtr + i * 16);
        }
        cp_commit();
        aPtr += 128; bPtr += 128;
        bufIss = (bufIss == NSTAGE - 1) ? 0 : bufIss + 1;
        if (++cIss == nch) {
            cIss = 0; segIss++;
            if (segIss == 1) {
                if (nseg == 2) { aPtr = aRowL; bPtr = bRowH; }
                else           { aPtr = aRowH; bPtr = bRowL; }
            } else if (segIss == 2) {
                aPtr = aRowL; bPtr = bRowH;
            }
        }
    };

    issue_one();
    issue_one();

    int bufC = 0;
    for (int t = 0; t < T; t++) {
        if (t + 2 < T)      { issue_one(); cp_wait<2>(); }
        else if (t + 1 < T) { cp_wait<1>(); }
        else                { cp_wait<0>(); }
        __syncthreads();

        const uint32_t aBase = sb + bufC * STAGE_B;
        const uint32_t bBase = aBase + 16384;

        #pragma unroll
        for (int kk = 0; kk < 4; kk++) {
            uint32_t af[4][4];
            #pragma unroll
            for (int mi = 0; mi < 4; mi++) {
                uint32_t row  = wr * 64 + mi * 16 + (lane & 15);
                uint32_t colb = kk * 32 + ((lane >> 4) << 4);
                ldm4(aBase + sw128(row * 128u + colb), af[mi][0], af[mi][1], af[mi][2], af[mi][3]);
            }
            uint32_t bf[2][4];
            #pragma unroll
            for (int ni = 0; ni < 2; ni++) {
                uint32_t q    = lane >> 3;
                uint32_t row  = wc * 32 + ni * 16 + ((q >> 1) << 3) + (lane & 7);
                uint32_t colb = kk * 32 + ((q & 1) << 4);
                ldm4(bBase + sw128(row * 128u + colb), bf[ni][0], bf[ni][1], bf[ni][2], bf[ni][3]);
            }
            #pragma unroll
            for (int mi = 0; mi < 4; mi++)
                #pragma unroll
                for (int n8 = 0; n8 < 4; n8++) {
                    uint32_t b0 = bf[n8 >> 1][(n8 & 1) * 2 + 0];
                    uint32_t b1 = bf[n8 >> 1][(n8 & 1) * 2 + 1];
                    mma16816(acc[mi][n8], af[mi][0], af[mi][1], af[mi][2], af[mi][3], b0, b1);
                }
        }
        __syncthreads();
        bufC = (bufC == NSTAGE - 1) ? 0 : bufC + 1;
    }

    // ---- epilogue
    const int g  = lane >> 2;
    const int tg = lane & 3;
    const int len = (MODE == 1) ? g_lens[z] : 0;

    #pragma unroll
    for (int mi = 0; mi < 4; mi++) {
        const int rA = row0 + wr * 64 + mi * 16 + g;
        const int rB = rA + 8;
        #pragma unroll
        for (int n8 = 0; n8 < 4; n8++) {
            const int col = n0 + wc * 32 + n8 * 8 + tg * 2;
            float v0 = acc[mi][n8][0], v1 = acc[mi][n8][1];
            float v2 = acc[mi][n8][2], v3 = acc[mi][n8][3];
            if (MODE == 0) {
                float* Cz = C + (size_t)z * sC;
                *(float2*)(Cz + (size_t)rA * ldc + col) = make_float2(v0, v1);
                *(float2*)(Cz + (size_t)rB * ldc + col) = make_float2(v2, v3);
            } else if (MODE == 1) {
                float* Cz = C + (size_t)z * sC;
                bool okA = rA < len, okB = rB < len;
                *(float2*)(Cz + (size_t)rA * ldc + col) =
                    make_float2(okA ? v0 * scale : -1e9f, okA ? v1 * scale : -1e9f);
                *(float2*)(Cz + (size_t)rB * ldc + col) =
                    make_float2(okB ? v2 * scale : -1e9f, okB ? v3 * scale : -1e9f);
            } else {
                __half* PohZ = Poh + (size_t)z * sC;
                __half* PolZ = Pol + (size_t)z * sC;
                __half h0 = __float2half_rn(v0), h1 = __float2half_rn(v1);
                __half h2 = __float2half_rn(v2), h3 = __float2half_rn(v3);
                __half l0 = __float2half_rn(v0 - __half2float(h0));
                __half l1 = __float2half_rn(v1 - __half2float(h1));
                __half l2 = __float2half_rn(v2 - __half2float(h2));
                __half l3 = __float2half_rn(v3 - __half2float(h3));
                *(uint32_t*)(PohZ + (size_t)rA * ldc + col) = pack_h2(h0, h1);
                *(uint32_t*)(PohZ + (size_t)rB * ldc + col) = pack_h2(h2, h3);
                *(uint32_t*)(PolZ + (size_t)rA * ldc + col) = pack_h2(l0, l1);
                *(uint32_t*)(PolZ + (size_t)rB * ldc + col) = pack_h2(l2, l3);
            }
        }
    }
}

// ---------------------------------------------------------------------------
// Row softmax over Ln=2048, in place + hi/lo fp16 plane outputs.
// Masked rows (q >= len): exact uniform 1/2048, no reads.
// ---------------------------------------------------------------------------
__global__ __launch_bounds__(256)
void softmax_kernel(float* __restrict__ attn, __half* __restrict__ Ph,
                    __half* __restrict__ Pl) {
    const size_t row = blockIdx.x;
    const int b  = (int)(row >> 11);
    const int ql = (int)(row & (Ln - 1));
    float* p = attn + row * Ln;
    const int t = threadIdx.x;

    if (ql >= g_lens[b]) {
        const float u = 1.0f / 2048.0f;
        const unsigned short uh = __half_as_ushort(__float2half_rn(u));
        float4 uv = make_float4(u, u, u, u);
        ((float4*)p)[t * 2]     = uv;
        ((float4*)p)[t * 2 + 1] = uv;
        ushort4 us = make_ushort4(uh, uh, uh, uh);
        ushort4 zs = make_ushort4(0, 0, 0, 0);
        __half* ph = Ph + row * Ln + t * 8;
        __half* pl = Pl + row * Ln + t * 8;
        *(ushort4*)(ph) = us; *(ushort4*)(ph + 4) = us;
        *(ushort4*)(pl) = zs; *(ushort4*)(pl + 4) = zs;
        return;
    }

    float4 va = ((const float4*)p)[t * 2];
    float4 vb = ((const float4*)p)[t * 2 + 1];
    float v[8] = {va.x, va.y, va.z, va.w, vb.x, vb.y, vb.z, vb.w};

    float m = v[0];
    #pragma unroll
    for (int i = 1; i < 8; i++) m = fmaxf(m, v[i]);

    __shared__ float red[256];
    red[t] = m;
    __syncthreads();
    #pragma unroll
    for (int s = 128; s > 0; s >>= 1) {
        if (t < s) red[t] = fmaxf(red[t], red[t + s]);
        __syncthreads();
    }
    m = red[0];
    __syncthreads();

    float sum = 0.0f;
    #pragma unroll
    for (int i = 0; i < 8; i++) {
        v[i] = expf(v[i] - m);
        sum += v[i];
    }
    red[t] = sum;
    __syncthreads();
    #pragma unroll
    for (int s = 128; s > 0; s >>= 1) {
        if (t < s) red[t] += red[t + s];
        __syncthreads();
    }
    const float inv = 1.0f / red[0];

    unsigned short hb[8], lb[8];
    #pragma unroll
    for (int i = 0; i < 8; i++) {
        v[i] *= inv;
        __half hbf = __float2half_rn(v[i]);
        float hf = __half2float(hbf);
        __half lbf = __float2half_rn(v[i] - hf);
        hb[i] = __half_as_ushort(hbf);
        lb[i] = __half_as_ushort(lbf);
    }
    ((float4*)p)[t * 2]     = make_float4(v[0], v[1], v[2], v[3]);
    ((float4*)p)[t * 2 + 1] = make_float4(v[4], v[5], v[6], v[7]);
    __half* ph = Ph + row * Ln + t * 8;
    __half* pl = Pl + row * Ln + t * 8;
    *(ushort4*)(ph)     = make_ushort4(hb[0], hb[1], hb[2], hb[3]);
    *(ushort4*)(ph + 4) = make_ushort4(hb[4], hb[5], hb[6], hb[7]);
    *(ushort4*)(pl)     = make_ushort4(lb[0], lb[1], lb[2], lb[3]);
    *(ushort4*)(pl + 4) = make_ushort4(lb[4], lb[5], lb[6], lb[7]);
}

// ---------------------------------------------------------------------------
// kernel_launch
// ---------------------------------------------------------------------------
extern "C" void kernel_launch(void* const* d_in, const int* in_sizes, int n_in,
                              void* d_out, int out_size) {
    const float* X  = (const float*)d_in[0];
    const void*  lens_raw = d_in[1];
    const float* O  = (const float*)d_in[2];
    const float* Wk = (const float*)d_in[3];
    const float* Wv = (const float*)d_in[4];
    const float* Wq = (const float*)d_in[5];

    const long long CTX = (long long)Bn * Ln * Dn;
    const long long ATT = (long long)Bn * Ln * Ln;

    float *ctx_s, *attn_s, *vm, *xm;
    __half *Xh, *Xl, *Oh, *Ol, *Wvh, *Wvl, *WqTh, *WqTl, *WkTh, *WkTl;
    __half *GTh, *GTl, *QGh, *QGl, *XTh, *XTl, *Ph, *Pl, *PXh, *PXl;
    cudaGetSymbolAddress((void**)&ctx_s, g_ctx_scratch);
    cudaGetSymbolAddress((void**)&attn_s, g_attn_scratch);
    cudaGetSymbolAddress((void**)&vm, g_vmean);
    cudaGetSymbolAddress((void**)&xm, g_xmean);
    cudaGetSymbolAddress((void**)&Xh, g_Xh);   cudaGetSymbolAddress((void**)&Xl, g_Xl);
    cudaGetSymbolAddress((void**)&Oh, g_Oh);   cudaGetSymbolAddress((void**)&Ol, g_Ol);
    cudaGetSymbolAddress((void**)&Wvh, g_Wvh); cudaGetSymbolAddress((void**)&Wvl, g_Wvl);
    cudaGetSymbolAddress((void**)&WqTh, g_WqTh); cudaGetSymbolAddress((void**)&WqTl, g_WqTl);
    cudaGetSymbolAddress((void**)&WkTh, g_WkTh); cudaGetSymbolAddress((void**)&WkTl, g_WkTl);
    cudaGetSymbolAddress((void**)&GTh, g_GTh); cudaGetSymbolAddress((void**)&GTl, g_GTl);
    cudaGetSymbolAddress((void**)&QGh, g_QGh); cudaGetSymbolAddress((void**)&QGl, g_QGl);
    cudaGetSymbolAddress((void**)&XTh, g_XTh); cudaGetSymbolAddress((void**)&XTl, g_XTl);
    cudaGetSymbolAddress((void**)&Ph, g_Ph);   cudaGetSymbolAddress((void**)&Pl, g_Pl);
    cudaGetSymbolAddress((void**)&PXh, g_PXh); cudaGetSymbolAddress((void**)&PXl, g_PXl);

    float* ctx;
    float* attn;
    if ((long long)out_size >= CTX + ATT) {
        ctx  = (float*)d_out;
        attn = (float*)d_out + CTX;
    } else if ((long long)out_size == ATT) {
        attn = (float*)d_out;
        ctx  = ctx_s;
    } else {
        ctx  = (float*)d_out;
        attn = attn_s;
    }

    cudaFuncSetAttribute(hmma_gemm<0>, cudaFuncAttributeMaxDynamicSharedMemorySize, SMEM_REQ);
    cudaFuncSetAttribute(hmma_gemm<1>, cudaFuncAttributeMaxDynamicSharedMemorySize, SMEM_REQ);
    cudaFuncSetAttribute(hmma_gemm<2>, cudaFuncAttributeMaxDynamicSharedMemorySize, SMEM_REQ);

    prep_lens_kernel<<<1, 32>>>(lens_raw);

    // Expansions + transposes of raw inputs
    {
        long long t4 = (long long)M_ALL * Dn / 4;
        int blocks = (int)((t4 + 255) / 256);
        expand2_kernel<<<blocks, 256>>>(X, Xh, Xl, t4);
        expand2_kernel<<<blocks, 256>>>(O, Oh, Ol, t4);
        long long w4 = (long long)Dn * Dn / 4;
        int wb = (int)((w4 + 255) / 256);
        expand2_kernel<<<wb, 256>>>(Wv, Wvh, Wvl, w4);
        trans_kernel<<<dim3(Dn / 32, Dn / 32, 1), 256>>>(Wq, WqTh, WqTl, Dn, Dn);
        trans_kernel<<<dim3(Dn / 32, Dn / 32, 1), 256>>>(Wk, WkTh, WkTl, Dn, Dn);
        trans_kernel<<<dim3(Dn / 32, Ln / 32, Bn), 256>>>(X, XTh, XTl, Ln, Dn);
    }

    // vmean = (mean_t X) @ Wv^T  (exact fp32 path for masked ctx rows)
    xmean_kernel<<<dim3(Dn / 256, Bn), 256>>>(X, xm);
    vmeanw_kernel<<<dim3(Dn / 8, Bn), 256>>>(xm, Wv, vm);

    // GT = Wk^T @ Wq   (3 segments — feeds everything downstream)
    hmma_gemm<2><<<dim3(Dn / 128, Dn / 128, 1), 256, SMEM_REQ>>>(
        WkTh, WkTl, WqTh, WqTl, nullptr, GTh, GTl, Dn, Dn, 0, 0, 0, 1.0f, 0, 3);

    // QG = O @ G; masked row tiles skipped (2 segments: drop Oh*GTl)
    hmma_gemm<2><<<dim3(Dn / 128, M_ALL / 128, 1), 256, SMEM_REQ>>>(
        Oh, Ol, GTh, GTl, nullptr, QGh, QGl, Dn, Dn, 0, 0, 0, 1.0f, 2, 2);

    // scores = QG @ X^T / 32 per batch, mask epilogue, masked tiles skipped
    // (2 segments: drop QGh*Xl)
    hmma_gemm<1><<<dim3(Ln / 128, Ln / 128, Bn), 256, SMEM_REQ>>>(
        QGh, QGl, Xh, Xl, attn, nullptr, nullptr, Dn, Ln,
        (long long)Ln * Dn, (long long)Ln * Dn, (long long)Ln * Ln, 0.03125f, 1, 2);

    // Softmax in place + P hi/lo planes (uniform fill for masked rows)
    softmax_kernel<<<Bn * Ln, 256>>>(attn, Ph, Pl);

    // PX = P @ X per batch; masked tiles skipped (2 segments: drop Ph*XTl)
    hmma_gemm<2><<<dim3(Dn / 128, Ln / 128, Bn), 256, SMEM_REQ>>>(
        Ph, Pl, XTh, XTl, nullptr, PXh, PXl, Ln, Dn,
        (long long)Ln * Ln, (long long)Dn * Ln, (long long)Ln * Dn, 1.0f, 1, 2);

    // ctx = PX @ Wv^T; masked tiles skipped (2 segments: drop PXh*Wvl)
    hmma_gemm<0><<<dim3(Dn / 128, M_ALL / 128, 1), 256, SMEM_REQ>>>(
        PXh, PXl, Wvh, Wvl, ctx, nullptr, nullptr, Dn, Dn, 0, 0, 0, 1.0f, 2, 2);

    // Masked ctx rows = per-batch V mean
    fill_masked_kernel<<<dim3(Dn / 256, Ln, Bn), 256>>>(vm, ctx);
}

// round 11
// speedup vs baseline: 3.5184x; 1.3120x over previous
#include <cuda_runtime.h>
#include <cuda_fp16.h>
#include <math.h>
#include <stdint.h>

#define Bn 8
#define Ln 2048
#define Dn 1024
#define M_ALL (Bn * Ln)   // 16384

// ---------------------------------------------------------------------------
// Device scratch (allocation-free rule -> __device__ globals)
// ---------------------------------------------------------------------------
__device__ float g_ctx_scratch[(size_t)M_ALL * Dn];
__device__ float g_attn_scratch[(size_t)Bn * Ln * Ln];
__device__ float g_vmean[(size_t)Bn * Dn];
__device__ float g_xmean[(size_t)Bn * Dn];
__device__ int   g_lens[Bn];

// fp16 planes (lo planes only where actually consumed)
__device__ __half g_Xh[(size_t)M_ALL * Dn];
__device__ __half g_Oh[(size_t)M_ALL * Dn];
__device__ __half g_Ol[(size_t)M_ALL * Dn];
__device__ __half g_Wvh[(size_t)Dn * Dn];
__device__ __half g_WqTh[(size_t)Dn * Dn];
__device__ __half g_WqTl[(size_t)Dn * Dn];
__device__ __half g_WkTh[(size_t)Dn * Dn];
__device__ __half g_WkTl[(size_t)Dn * Dn];
__device__ __half g_GTh[(size_t)Dn * Dn];
__device__ __half g_QGh[(size_t)M_ALL * Dn];
__device__ __half g_XTh[(size_t)Bn * Dn * Ln];
__device__ __half g_Ph[(size_t)M_ALL * Ln];
__device__ __half g_PXh[(size_t)M_ALL * Dn];
__device__ __half g_PXl[(size_t)M_ALL * Dn];

// ---------------------------------------------------------------------------
// lens dtype sniffing (int64 vs int32)
// ---------------------------------------------------------------------------
__global__ void prep_lens_kernel(const void* lensraw) {
    if (threadIdx.x == 0 && blockIdx.x == 0) {
        const int* a32 = (const int*)lensraw;
        bool is64 = true;
        #pragma unroll
        for (int i = 0; i < 4; i++) {
            int lo = a32[2 * i], hi = a32[2 * i + 1];
            if (hi != 0 || lo < 1 || lo > Ln) { is64 = false; break; }
        }
        if (is64) {
            const long long* a64 = (const long long*)lensraw;
            for (int i = 0; i < Bn; i++) g_lens[i] = (int)a64[i];
        } else {
            for (int i = 0; i < Bn; i++) g_lens[i] = a32[i];
        }
    }
}

// ---------------------------------------------------------------------------
// fp32 -> (hi, lo) fp16 planes, flat
// ---------------------------------------------------------------------------
__global__ __launch_bounds__(256)
void expand2_kernel(const float* __restrict__ src, __half* __restrict__ dh,
                    __half* __restrict__ dl, long long total4) {
    long long i = (long long)blockIdx.x * blockDim.x + threadIdx.x;
    if (i >= total4) return;
    float4 v = *(const float4*)(src + i * 4);
    float vv[4] = {v.x, v.y, v.z, v.w};
    unsigned short hb[4], lb[4];
    #pragma unroll
    for (int j = 0; j < 4; j++) {
        __half hbf = __float2half_rn(vv[j]);
        float hf = __half2float(hbf);
        __half lbf = __float2half_rn(vv[j] - hf);
        hb[j] = __half_as_ushort(hbf);
        lb[j] = __half_as_ushort(lbf);
    }
    *(ushort4*)(dh + i * 4) = make_ushort4(hb[0], hb[1], hb[2], hb[3]);
    *(ushort4*)(dl + i * 4) = make_ushort4(lb[0], lb[1], lb[2], lb[3]);
}

// fp32 -> hi fp16 plane only
__global__ __launch_bounds__(256)
void expand1_kernel(const float* __restrict__ src, __half* __restrict__ dh,
                    long long total4) {
    long long i = (long long)blockIdx.x * blockDim.x + threadIdx.x;
    if (i >= total4) return;
    float4 v = *(const float4*)(src + i * 4);
    ushort4 hu = make_ushort4(
        __half_as_ushort(__float2half_rn(v.x)),
        __half_as_ushort(__float2half_rn(v.y)),
        __half_as_ushort(__float2half_rn(v.z)),
        __half_as_ushort(__float2half_rn(v.w)));
    *(ushort4*)(dh + i * 4) = hu;
}

// ---------------------------------------------------------------------------
// Transpose fp32 [R,C] -> fp16 hi/lo planes [C,R]; batched via blockIdx.z.
// ---------------------------------------------------------------------------
__global__ __launch_bounds__(256)
void trans_kernel(const float* __restrict__ src, __half* __restrict__ oh,
                  __half* __restrict__ ol, int R, int C) {
    __shared__ float tile[32][33];
    size_t bo = (size_t)blockIdx.z * R * C;
    src += bo; oh += bo; ol += bo;
    int c0 = blockIdx.x * 32;
    int r0 = blockIdx.y * 32;
    int tx = threadIdx.x & 31;
    int ty = threadIdx.x >> 5;

    #pragma unroll
    for (int j = 0; j < 4; j++)
        tile[ty + j * 8][tx] = src[(size_t)(r0 + ty + j * 8) * C + c0 + tx];
    __syncthreads();

    #pragma unroll
    for (int j = 0; j < 4; j++) {
        float v = tile[tx][ty + j * 8];
        __half h = __float2half_rn(v);
        __half l = __float2half_rn(v - __half2float(h));
        size_t o = (size_t)(c0 + ty + j * 8) * R + r0 + tx;
        oh[o] = h;
        ol[o] = l;
    }
}

// Transpose fp32 [R,C] -> hi fp16 plane [C,R] only; batched via blockIdx.z.
__global__ __launch_bounds__(256)
void trans1_kernel(const float* __restrict__ src, __half* __restrict__ oh,
                   int R, int C) {
    __shared__ float tile[32][33];
    size_t bo = (size_t)blockIdx.z * R * C;
    src += bo; oh += bo;
    int c0 = blockIdx.x * 32;
    int r0 = blockIdx.y * 32;
    int tx = threadIdx.x & 31;
    int ty = threadIdx.x >> 5;

    #pragma unroll
    for (int j = 0; j < 4; j++)
        tile[ty + j * 8][tx] = src[(size_t)(r0 + ty + j * 8) * C + c0 + tx];
    __syncthreads();

    #pragma unroll
    for (int j = 0; j < 4; j++) {
        float v = tile[tx][ty + j * 8];
        oh[(size_t)(c0 + ty + j * 8) * R + r0 + tx] = __float2half_rn(v);
    }
}

// ---------------------------------------------------------------------------
// xmean[b][d] = (1/2048) * sum_t X[b*Ln+t][d]
// ---------------------------------------------------------------------------
__global__ __launch_bounds__(256)
void xmean_kernel(const float* __restrict__ xf, float* __restrict__ xm) {
    int b = blockIdx.y;
    int d = blockIdx.x * 256 + threadIdx.x;
    const float* p = xf + (size_t)b * Ln * Dn + d;
    float s0 = 0.f, s1 = 0.f, s2 = 0.f, s3 = 0.f;
    for (int t = 0; t < Ln; t += 4) {
        s0 += p[(size_t)(t + 0) * Dn];
        s1 += p[(size_t)(t + 1) * Dn];
        s2 += p[(size_t)(t + 2) * Dn];
        s3 += p[(size_t)(t + 3) * Dn];
    }
    xm[b * Dn + d] = (s0 + s1 + s2 + s3) * (1.0f / 2048.0f);
}

// ---------------------------------------------------------------------------
// vmean[b][e] = sum_d xmean[b][d] * Wv[e][d]
// ---------------------------------------------------------------------------
__global__ __launch_bounds__(256)
void vmeanw_kernel(const float* __restrict__ xm, const float* __restrict__ Wv,
                   float* __restrict__ vm) {
    int b = blockIdx.y;
    int e = blockIdx.x * 8 + (threadIdx.x >> 5);
    int lane = threadIdx.x & 31;
    const float* xr = xm + b * Dn;
    const float* wr = Wv + (size_t)e * Dn;
    float s = 0.f;
    for (int d = lane; d < Dn; d += 32) s += xr[d] * wr[d];
    #pragma unroll
    for (int o = 16; o > 0; o >>= 1) s += __shfl_down_sync(0xffffffffu, s, o);
    if (lane == 0) vm[b * Dn + e] = s;
}

// ---------------------------------------------------------------------------
// Fill masked ctx rows with vmean
// ---------------------------------------------------------------------------
__global__ __launch_bounds__(256)
void fill_masked_kernel(const float* __restrict__ vm, float* __restrict__ ctx) {
    int b = blockIdx.z;
    int q = blockIdx.y;
    if (q < g_lens[b]) return;
    int d = blockIdx.x * 256 + threadIdx.x;
    ctx[((size_t)b * Ln + q) * Dn + d] = vm[b * Dn + d];
}

// ---------------------------------------------------------------------------
// HMMA GEMM core (mma.sync m16n8k16 fp16, fp32 accum), NT.
// nseg=3: (Ah,Bh),(Ah,Bl),(Al,Bh).  nseg=2: (Ah,Bh),(Al,Bh).  nseg=1: (Ah,Bh).
// BM=BN=128, BK=64, 3-stage cp.async, 8 warps 2x4, warp tile 64x32.
// MODE 0: fp32 C. MODE 1: scale+mask fp32 C. MODE 2: hi/lo fp16 planes.
// MODE 3: hi fp16 plane only.
// skipMode 1: skip tile if local row0 >= lens[z]
// skipMode 2: skip tile if (row0 & 2047) >= lens[row0 >> 11]
// ---------------------------------------------------------------------------
__device__ __forceinline__ uint32_t sw128(uint32_t x) { return x ^ ((x >> 3) & 0x70); }

#define STAGE_B 32768
#define NSTAGE  3
#define SMEM_REQ (1024 + NSTAGE * STAGE_B)

__device__ __forceinline__ void cp16(uint32_t saddr, const void* gaddr) {
    asm volatile("cp.async.cg.shared.global [%0], [%1], 16;" :: "r"(saddr), "l"(gaddr));
}
__device__ __forceinline__ void cp_commit() {
    asm volatile("cp.async.commit_group;" ::: "memory");
}
template <int N> __device__ __forceinline__ void cp_wait() {
    asm volatile("cp.async.wait_group %0;" :: "n"(N) : "memory");
}
__device__ __forceinline__ void ldm4(uint32_t addr, uint32_t& r0, uint32_t& r1,
                                     uint32_t& r2, uint32_t& r3) {
    asm volatile("ldmatrix.sync.aligned.m8n8.x4.shared.b16 {%0,%1,%2,%3}, [%4];"
                 : "=r"(r0), "=r"(r1), "=r"(r2), "=r"(r3) : "r"(addr));
}
__device__ __forceinline__ void mma16816(float* c, uint32_t a0, uint32_t a1,
                                         uint32_t a2, uint32_t a3,
                                         uint32_t b0, uint32_t b1) {
    asm volatile(
        "mma.sync.aligned.m16n8k16.row.col.f32.f16.f16.f32 "
        "{%0,%1,%2,%3},{%4,%5,%6,%7},{%8,%9},{%0,%1,%2,%3};"
        : "+f"(c[0]), "+f"(c[1]), "+f"(c[2]), "+f"(c[3])
        : "r"(a0), "r"(a1), "r"(a2), "r"(a3), "r"(b0), "r"(b1));
}
__device__ __forceinline__ uint32_t pack_h2(__half a, __half b) {
    return (uint32_t)__half_as_ushort(a) | ((uint32_t)__half_as_ushort(b) << 16);
}

template <int MODE>
__global__ __launch_bounds__(256, 2)
void hmma_gemm(const __half* __restrict__ Ah, const __half* __restrict__ Al,
               const __half* __restrict__ Bh, const __half* __restrict__ Bl,
               float* __restrict__ C,
               __half* __restrict__ Poh, __half* __restrict__ Pol,
               int K, int ldc,
               long long sA, long long sB, long long sC, float scale,
               int skipMode, int nseg) {
    const int z    = blockIdx.z;
    const int row0 = blockIdx.y * 128;
    const int n0   = blockIdx.x * 128;

    if (skipMode == 1) {
        if (row0 >= g_lens[z]) return;
    } else if (skipMode == 2) {
        if ((row0 & (Ln - 1)) >= g_lens[row0 >> 11]) return;
    }

    extern __shared__ char dsm[];
    uint32_t sraw = (uint32_t)__cvta_generic_to_shared(dsm);
    uint32_t sb   = (sraw + 1023) & ~1023u;

    const int tid  = threadIdx.x;
    const int lane = tid & 31;
    const int wid  = tid >> 5;
    const int wr   = wid >> 2;
    const int wc   = wid & 3;

    const int r = tid >> 1;
    const int h = (tid & 1) * 64;

    const char* aRowH = (const char*)(Ah + (size_t)z * sA + (size_t)(row0 + r) * K) + h;
    const char* aRowL = (const char*)(Al + (size_t)z * sA + (size_t)(row0 + r) * K) + h;
    const char* bRowH = (const char*)(Bh + (size_t)z * sB + (size_t)(n0 + r) * K) + h;
    const char* bRowL = (const char*)(Bl + (size_t)z * sB + (size_t)(n0 + r) * K) + h;

    uint32_t swo[4];
    #pragma unroll
    for (int i = 0; i < 4; i++) swo[i] = sw128((uint32_t)r * 128u + h + i * 16);

    float acc[4][4][4];
    #pragma unroll
    for (int a = 0; a < 4; a++)
        #pragma unroll
        for (int b = 0; b < 4; b++)
            #pragma unroll
            for (int cc = 0; cc < 4; cc++) acc[a][b][cc] = 0.0f;

    const int nch = K / 64;
    const int T   = nseg * nch;

    const char* aPtr = aRowH;
    const char* bPtr = bRowH;
    int cIss = 0, segIss = 0, bufIss = 0;

    auto issue_one = [&]() {
        uint32_t sa = sb + bufIss * STAGE_B;
        #pragma unroll
        for (int i = 0; i < 4; i++) {
            cp16(sa + swo[i], aPtr + i * 16);
            cp16(sa + 16384 + swo[i], bPtr + i * 16);
        }
        cp_commit();
        aPtr += 128; bPtr += 128;
        bufIss = (bufIss == NSTAGE - 1) ? 0 : bufIss + 1;
        if (++cIss == nch) {
            cIss = 0; segIss++;
            if (segIss == 1) {
                if (nseg == 2) { aPtr = aRowL; bPtr = bRowH; }
                else           { aPtr = aRowH; bPtr = bRowL; }
            } else if (segIss == 2) {
                aPtr = aRowL; bPtr = bRowH;
            }
        }
    };

    issue_one();
    issue_one();

    int bufC = 0;
    for (int t = 0; t < T; t++) {
        if (t + 2 < T)      { issue_one(); cp_wait<2>(); }
        else if (t + 1 < T) { cp_wait<1>(); }
        else                { cp_wait<0>(); }
        __syncthreads();

        const uint32_t aBase = sb + bufC * STAGE_B;
        const uint32_t bBase = aBase + 16384;

        #pragma unroll
        for (int kk = 0; kk < 4; kk++) {
            uint32_t af[4][4];
            #pragma unroll
            for (int mi = 0; mi < 4; mi++) {
                uint32_t row  = wr * 64 + mi * 16 + (lane & 15);
                uint32_t colb = kk * 32 + ((lane >> 4) << 4);
                ldm4(aBase + sw128(row * 128u + colb), af[mi][0], af[mi][1], af[mi][2], af[mi][3]);
            }
            uint32_t bf[2][4];
            #pragma unroll
            for (int ni = 0; ni < 2; ni++) {
                uint32_t q    = lane >> 3;
                uint32_t row  = wc * 32 + ni * 16 + ((q >> 1) << 3) + (lane & 7);
                uint32_t colb = kk * 32 + ((q & 1) << 4);
                ldm4(bBase + sw128(row * 128u + colb), bf[ni][0], bf[ni][1], bf[ni][2], bf[ni][3]);
            }
            #pragma unroll
            for (int mi = 0; mi < 4; mi++)
                #pragma unroll
                for (int n8 = 0; n8 < 4; n8++) {
                    uint32_t b0 = bf[n8 >> 1][(n8 & 1) * 2 + 0];
                    uint32_t b1 = bf[n8 >> 1][(n8 & 1) * 2 + 1];
                    mma16816(acc[mi][n8], af[mi][0], af[mi][1], af[mi][2], af[mi][3], b0, b1);
                }
        }
        __syncthreads();
        bufC = (bufC == NSTAGE - 1) ? 0 : bufC + 1;
    }

    // ---- epilogue
    const int g  = lane >> 2;
    const int tg = lane & 3;
    const int len = (MODE == 1) ? g_lens[z] : 0;

    #pragma unroll
    for (int mi = 0; mi < 4; mi++) {
        const int rA = row0 + wr * 64 + mi * 16 + g;
        const int rB = rA + 8;
        #pragma unroll
        for (int n8 = 0; n8 < 4; n8++) {
            const int col = n0 + wc * 32 + n8 * 8 + tg * 2;
            float v0 = acc[mi][n8][0], v1 = acc[mi][n8][1];
            float v2 = acc[mi][n8][2], v3 = acc[mi][n8][3];
            if (MODE == 0) {
                float* Cz = C + (size_t)z * sC;
                *(float2*)(Cz + (size_t)rA * ldc + col) = make_float2(v0, v1);
                *(float2*)(Cz + (size_t)rB * ldc + col) = make_float2(v2, v3);
            } else if (MODE == 1) {
                float* Cz = C + (size_t)z * sC;
                bool okA = rA < len, okB = rB < len;
                *(float2*)(Cz + (size_t)rA * ldc + col) =
                    make_float2(okA ? v0 * scale : -1e9f, okA ? v1 * scale : -1e9f);
                *(float2*)(Cz + (size_t)rB * ldc + col) =
                    make_float2(okB ? v2 * scale : -1e9f, okB ? v3 * scale : -1e9f);
            } else if (MODE == 2) {
                __half* PohZ = Poh + (size_t)z * sC;
                __half* PolZ = Pol + (size_t)z * sC;
                __half h0 = __float2half_rn(v0), h1 = __float2half_rn(v1);
                __half h2 = __float2half_rn(v2), h3 = __float2half_rn(v3);
                __half l0 = __float2half_rn(v0 - __half2float(h0));
                __half l1 = __float2half_rn(v1 - __half2float(h1));
                __half l2 = __float2half_rn(v2 - __half2float(h2));
                __half l3 = __float2half_rn(v3 - __half2float(h3));
                *(uint32_t*)(PohZ + (size_t)rA * ldc + col) = pack_h2(h0, h1);
                *(uint32_t*)(PohZ + (size_t)rB * ldc + col) = pack_h2(h2, h3);
                *(uint32_t*)(PolZ + (size_t)rA * ldc + col) = pack_h2(l0, l1);
                *(uint32_t*)(PolZ + (size_t)rB * ldc + col) = pack_h2(l2, l3);
            } else {
                __half* PohZ = Poh + (size_t)z * sC;
                *(uint32_t*)(PohZ + (size_t)rA * ldc + col) =
                    pack_h2(__float2half_rn(v0), __float2half_rn(v1));
                *(uint32_t*)(PohZ + (size_t)rB * ldc + col) =
                    pack_h2(__float2half_rn(v2), __float2half_rn(v3));
            }
        }
    }
}

// ---------------------------------------------------------------------------
// Row softmax over Ln=2048, in place + hi fp16 plane output.
// Masked rows (q >= len): exact uniform 1/2048, no reads.
// ---------------------------------------------------------------------------
__global__ __launch_bounds__(256)
void softmax_kernel(float* __restrict__ attn, __half* __restrict__ Ph) {
    const size_t row = blockIdx.x;
    const int b  = (int)(row >> 11);
    const int ql = (int)(row & (Ln - 1));
    float* p = attn + row * Ln;
    const int t = threadIdx.x;

    if (ql >= g_lens[b]) {
        const float u = 1.0f / 2048.0f;
        const unsigned short uh = __half_as_ushort(__float2half_rn(u));
        float4 uv = make_float4(u, u, u, u);
        ((float4*)p)[t * 2]     = uv;
        ((float4*)p)[t * 2 + 1] = uv;
        ushort4 us = make_ushort4(uh, uh, uh, uh);
        __half* ph = Ph + row * Ln + t * 8;
        *(ushort4*)(ph) = us; *(ushort4*)(ph + 4) = us;
        return;
    }

    float4 va = ((const float4*)p)[t * 2];
    float4 vb = ((const float4*)p)[t * 2 + 1];
    float v[8] = {va.x, va.y, va.z, va.w, vb.x, vb.y, vb.z, vb.w};

    float m = v[0];
    #pragma unroll
    for (int i = 1; i < 8; i++) m = fmaxf(m, v[i]);

    __shared__ float red[256];
    red[t] = m;
    __syncthreads();
    #pragma unroll
    for (int s = 128; s > 0; s >>= 1) {
        if (t < s) red[t] = fmaxf(red[t], red[t + s]);
        __syncthreads();
    }
    m = red[0];
    __syncthreads();

    float sum = 0.0f;
    #pragma unroll
    for (int i = 0; i < 8; i++) {
        v[i] = expf(v[i] - m);
        sum += v[i];
    }
    red[t] = sum;
    __syncthreads();
    #pragma unroll
    for (int s = 128; s > 0; s >>= 1) {
        if (t < s) red[t] += red[t + s];
        __syncthreads();
    }
    const float inv = 1.0f / red[0];

    unsigned short hb[8];
    #pragma unroll
    for (int i = 0; i < 8; i++) {
        v[i] *= inv;
        hb[i] = __half_as_ushort(__float2half_rn(v[i]));
    }
    ((float4*)p)[t * 2]     = make_float4(v[0], v[1], v[2], v[3]);
    ((float4*)p)[t * 2 + 1] = make_float4(v[4], v[5], v[6], v[7]);
    __half* ph = Ph + row * Ln + t * 8;
    *(ushort4*)(ph)     = make_ushort4(hb[0], hb[1], hb[2], hb[3]);
    *(ushort4*)(ph + 4) = make_ushort4(hb[4], hb[5], hb[6], hb[7]);
}

// ---------------------------------------------------------------------------
// kernel_launch
// ---------------------------------------------------------------------------
extern "C" void kernel_launch(void* const* d_in, const int* in_sizes, int n_in,
                              void* d_out, int out_size) {
    const float* X  = (const float*)d_in[0];
    const void*  lens_raw = d_in[1];
    const float* O  = (const float*)d_in[2];
    const float* Wk = (const float*)d_in[3];
    const float* Wv = (const float*)d_in[4];
    const float* Wq = (const float*)d_in[5];

    const long long CTX = (long long)Bn * Ln * Dn;
    const long long ATT = (long long)Bn * Ln * Ln;

    float *ctx_s, *attn_s, *vm, *xm;
    __half *Xh, *Oh, *Ol, *Wvh, *WqTh, *WqTl, *WkTh, *WkTl;
    __half *GTh, *QGh, *XTh, *Ph, *PXh, *PXl;
    cudaGetSymbolAddress((void**)&ctx_s, g_ctx_scratch);
    cudaGetSymbolAddress((void**)&attn_s, g_attn_scratch);
    cudaGetSymbolAddress((void**)&vm, g_vmean);
    cudaGetSymbolAddress((void**)&xm, g_xmean);
    cudaGetSymbolAddress((void**)&Xh, g_Xh);
    cudaGetSymbolAddress((void**)&Oh, g_Oh);   cudaGetSymbolAddress((void**)&Ol, g_Ol);
    cudaGetSymbolAddress((void**)&Wvh, g_Wvh);
    cudaGetSymbolAddress((void**)&WqTh, g_WqTh); cudaGetSymbolAddress((void**)&WqTl, g_WqTl);
    cudaGetSymbolAddress((void**)&WkTh, g_WkTh); cudaGetSymbolAddress((void**)&WkTl, g_WkTl);
    cudaGetSymbolAddress((void**)&GTh, g_GTh);
    cudaGetSymbolAddress((void**)&QGh, g_QGh);
    cudaGetSymbolAddress((void**)&XTh, g_XTh);
    cudaGetSymbolAddress((void**)&Ph, g_Ph);
    cudaGetSymbolAddress((void**)&PXh, g_PXh); cudaGetSymbolAddress((void**)&PXl, g_PXl);

    float* ctx;
    float* attn;
    if ((long long)out_size >= CTX + ATT) {
        ctx  = (float*)d_out;
        attn = (float*)d_out + CTX;
    } else if ((long long)out_size == ATT) {
        attn = (float*)d_out;
        ctx  = ctx_s;
    } else {
        ctx  = (float*)d_out;
        attn = attn_s;
    }

    cudaFuncSetAttribute(hmma_gemm<0>, cudaFuncAttributeMaxDynamicSharedMemorySize, SMEM_REQ);
    cudaFuncSetAttribute(hmma_gemm<1>, cudaFuncAttributeMaxDynamicSharedMemorySize, SMEM_REQ);
    cudaFuncSetAttribute(hmma_gemm<2>, cudaFuncAttributeMaxDynamicSharedMemorySize, SMEM_REQ);
    cudaFuncSetAttribute(hmma_gemm<3>, cudaFuncAttributeMaxDynamicSharedMemorySize, SMEM_REQ);

    prep_lens_kernel<<<1, 32>>>(lens_raw);

    // Expansions + transposes of raw inputs (only consumed planes written)
    {
        long long t4 = (long long)M_ALL * Dn / 4;
        int blocks = (int)((t4 + 255) / 256);
        expand1_kernel<<<blocks, 256>>>(X, Xh, t4);           // Xl never read
        expand2_kernel<<<blocks, 256>>>(O, Oh, Ol, t4);
        long long w4 = (long long)Dn * Dn / 4;
        int wb = (int)((w4 + 255) / 256);
        expand1_kernel<<<wb, 256>>>(Wv, Wvh, w4);             // Wvl never read
        trans_kernel<<<dim3(Dn / 32, Dn / 32, 1), 256>>>(Wq, WqTh, WqTl, Dn, Dn);
        trans_kernel<<<dim3(Dn / 32, Dn / 32, 1), 256>>>(Wk, WkTh, WkTl, Dn, Dn);
        trans1_kernel<<<dim3(Dn / 32, Ln / 32, Bn), 256>>>(X, XTh, Ln, Dn);  // XTl never read
    }

    // vmean = (mean_t X) @ Wv^T  (exact fp32 path for masked ctx rows)
    xmean_kernel<<<dim3(Dn / 256, Bn), 256>>>(X, xm);
    vmeanw_kernel<<<dim3(Dn / 8, Bn), 256>>>(xm, Wv, vm);

    // GT = Wk^T @ Wq   (3 segments; hi plane out — GTl never read)
    hmma_gemm<3><<<dim3(Dn / 128, Dn / 128, 1), 256, SMEM_REQ>>>(
        WkTh, WkTl, WqTh, WqTl, nullptr, GTh, nullptr, Dn, Dn, 0, 0, 0, 1.0f, 0, 3);

    // QG = O @ G; masked row tiles skipped (2 segments; hi plane out)
    hmma_gemm<3><<<dim3(Dn / 128, M_ALL / 128, 1), 256, SMEM_REQ>>>(
        Oh, Ol, GTh, nullptr, nullptr, QGh, nullptr, Dn, Dn, 0, 0, 0, 1.0f, 2, 2);

    // scores = QGh @ Xh^T / 32 per batch (1 segment), mask epilogue, tiles skipped
    hmma_gemm<1><<<dim3(Ln / 128, Ln / 128, Bn), 256, SMEM_REQ>>>(
        QGh, nullptr, Xh, nullptr, attn, nullptr, nullptr, Dn, Ln,
        (long long)Ln * Dn, (long long)Ln * Dn, (long long)Ln * Ln, 0.03125f, 1, 1);

    // Softmax in place + P hi plane (uniform fill for masked rows)
    softmax_kernel<<<Bn * Ln, 256>>>(attn, Ph);

    // PX = Ph @ XTh per batch (1 segment); masked tiles skipped; hi/lo planes out
    hmma_gemm<2><<<dim3(Dn / 128, Ln / 128, Bn), 256, SMEM_REQ>>>(
        Ph, nullptr, XTh, nullptr, nullptr, PXh, PXl, Ln, Dn,
        (long long)Ln * Ln, (long long)Dn * Ln, (long long)Ln * Dn, 1.0f, 1, 1);

    // ctx = PX @ Wv^T; masked tiles skipped (2 segments)
    hmma_gemm<0><<<dim3(Dn / 128, M_ALL / 128, 1), 256, SMEM_REQ>>>(
        PXh, PXl, Wvh, nullptr, ctx, nullptr, nullptr, Dn, Dn, 0, 0, 0, 1.0f, 2, 2);

    // Masked ctx rows = per-batch V mean
    fill_masked_kernel<<<dim3(Dn / 256, Ln, Bn), 256>>>(vm, ctx);
}

// round 12
// speedup vs baseline: 4.1647x; 1.1837x over previous
#include <cuda_runtime.h>
#include <cuda_fp16.h>
#include <math.h>
#include <stdint.h>

#define Bn 8
#define Ln 2048
#define Dn 1024
#define M_ALL (Bn * Ln)   // 16384

// ---------------------------------------------------------------------------
// Device scratch (allocation-free rule -> __device__ globals)
// ---------------------------------------------------------------------------
__device__ float g_ctx_scratch[(size_t)M_ALL * Dn];
__device__ float g_attn_scratch[(size_t)Bn * Ln * Ln];
__device__ float g_vmean[(size_t)Bn * Dn];
__device__ float g_xmean[(size_t)Bn * Dn];
__device__ int   g_lens[Bn];

// fp16 planes (lo planes only where actually consumed: GT inputs)
__device__ __half g_Xh[(size_t)M_ALL * Dn];
__device__ __half g_Oh[(size_t)M_ALL * Dn];
__device__ __half g_Wvh[(size_t)Dn * Dn];
__device__ __half g_WqTh[(size_t)Dn * Dn];
__device__ __half g_WqTl[(size_t)Dn * Dn];
__device__ __half g_WkTh[(size_t)Dn * Dn];
__device__ __half g_WkTl[(size_t)Dn * Dn];
__device__ __half g_GTh[(size_t)Dn * Dn];
__device__ __half g_QGh[(size_t)M_ALL * Dn];
__device__ __half g_XTh[(size_t)Bn * Dn * Ln];
__device__ __half g_Ph[(size_t)M_ALL * Ln];
__device__ __half g_PXh[(size_t)M_ALL * Dn];

// ---------------------------------------------------------------------------
// lens dtype sniffing (int64 vs int32)
// ---------------------------------------------------------------------------
__global__ void prep_lens_kernel(const void* lensraw) {
    if (threadIdx.x == 0 && blockIdx.x == 0) {
        const int* a32 = (const int*)lensraw;
        bool is64 = true;
        #pragma unroll
        for (int i = 0; i < 4; i++) {
            int lo = a32[2 * i], hi = a32[2 * i + 1];
            if (hi != 0 || lo < 1 || lo > Ln) { is64 = false; break; }
        }
        if (is64) {
            const long long* a64 = (const long long*)lensraw;
            for (int i = 0; i < Bn; i++) g_lens[i] = (int)a64[i];
        } else {
            for (int i = 0; i < Bn; i++) g_lens[i] = a32[i];
        }
    }
}

// ---------------------------------------------------------------------------
// fp32 -> hi fp16 plane only
// ---------------------------------------------------------------------------
__global__ __launch_bounds__(256)
void expand1_kernel(const float* __restrict__ src, __half* __restrict__ dh,
                    long long total4) {
    long long i = (long long)blockIdx.x * blockDim.x + threadIdx.x;
    if (i >= total4) return;
    float4 v = *(const float4*)(src + i * 4);
    ushort4 hu = make_ushort4(
        __half_as_ushort(__float2half_rn(v.x)),
        __half_as_ushort(__float2half_rn(v.y)),
        __half_as_ushort(__float2half_rn(v.z)),
        __half_as_ushort(__float2half_rn(v.w)));
    *(ushort4*)(dh + i * 4) = hu;
}

// ---------------------------------------------------------------------------
// Transpose fp32 [R,C] -> fp16 hi/lo planes [C,R]; batched via blockIdx.z.
// ---------------------------------------------------------------------------
__global__ __launch_bounds__(256)
void trans_kernel(const float* __restrict__ src, __half* __restrict__ oh,
                  __half* __restrict__ ol, int R, int C) {
    __shared__ float tile[32][33];
    size_t bo = (size_t)blockIdx.z * R * C;
    src += bo; oh += bo; ol += bo;
    int c0 = blockIdx.x * 32;
    int r0 = blockIdx.y * 32;
    int tx = threadIdx.x & 31;
    int ty = threadIdx.x >> 5;

    #pragma unroll
    for (int j = 0; j < 4; j++)
        tile[ty + j * 8][tx] = src[(size_t)(r0 + ty + j * 8) * C + c0 + tx];
    __syncthreads();

    #pragma unroll
    for (int j = 0; j < 4; j++) {
        float v = tile[tx][ty + j * 8];
        __half h = __float2half_rn(v);
        __half l = __float2half_rn(v - __half2float(h));
        size_t o = (size_t)(c0 + ty + j * 8) * R + r0 + tx;
        oh[o] = h;
        ol[o] = l;
    }
}

// Transpose fp32 [R,C] -> hi fp16 plane [C,R] only; batched via blockIdx.z.
__global__ __launch_bounds__(256)
void trans1_kernel(const float* __restrict__ src, __half* __restrict__ oh,
                   int R, int C) {
    __shared__ float tile[32][33];
    size_t bo = (size_t)blockIdx.z * R * C;
    src += bo; oh += bo;
    int c0 = blockIdx.x * 32;
    int r0 = blockIdx.y * 32;
    int tx = threadIdx.x & 31;
    int ty = threadIdx.x >> 5;

    #pragma unroll
    for (int j = 0; j < 4; j++)
        tile[ty + j * 8][tx] = src[(size_t)(r0 + ty + j * 8) * C + c0 + tx];
    __syncthreads();

    #pragma unroll
    for (int j = 0; j < 4; j++) {
        float v = tile[tx][ty + j * 8];
        oh[(size_t)(c0 + ty + j * 8) * R + r0 + tx] = __float2half_rn(v);
    }
}

// ---------------------------------------------------------------------------
// xmean[b][d] = (1/2048) * sum_t X[b*Ln+t][d]
// ---------------------------------------------------------------------------
__global__ __launch_bounds__(256)
void xmean_kernel(const float* __restrict__ xf, float* __restrict__ xm) {
    int b = blockIdx.y;
    int d = blockIdx.x * 256 + threadIdx.x;
    const float* p = xf + (size_t)b * Ln * Dn + d;
    float s0 = 0.f, s1 = 0.f, s2 = 0.f, s3 = 0.f;
    for (int t = 0; t < Ln; t += 4) {
        s0 += p[(size_t)(t + 0) * Dn];
        s1 += p[(size_t)(t + 1) * Dn];
        s2 += p[(size_t)(t + 2) * Dn];
        s3 += p[(size_t)(t + 3) * Dn];
    }
    xm[b * Dn + d] = (s0 + s1 + s2 + s3) * (1.0f / 2048.0f);
}

// ---------------------------------------------------------------------------
// vmean[b][e] = sum_d xmean[b][d] * Wv[e][d]
// ---------------------------------------------------------------------------
__global__ __launch_bounds__(256)
void vmeanw_kernel(const float* __restrict__ xm, const float* __restrict__ Wv,
                   float* __restrict__ vm) {
    int b = blockIdx.y;
    int e = blockIdx.x * 8 + (threadIdx.x >> 5);
    int lane = threadIdx.x & 31;
    const float* xr = xm + b * Dn;
    const float* wr = Wv + (size_t)e * Dn;
    float s = 0.f;
    for (int d = lane; d < Dn; d += 32) s += xr[d] * wr[d];
    #pragma unroll
    for (int o = 16; o > 0; o >>= 1) s += __shfl_down_sync(0xffffffffu, s, o);
    if (lane == 0) vm[b * Dn + e] = s;
}

// ---------------------------------------------------------------------------
// Fill masked ctx rows with vmean
// ---------------------------------------------------------------------------
__global__ __launch_bounds__(256)
void fill_masked_kernel(const float* __restrict__ vm, float* __restrict__ ctx) {
    int b = blockIdx.z;
    int q = blockIdx.y;
    if (q < g_lens[b]) return;
    int d = blockIdx.x * 256 + threadIdx.x;
    ctx[((size_t)b * Ln + q) * Dn + d] = vm[b * Dn + d];
}

// ---------------------------------------------------------------------------
// HMMA GEMM core (mma.sync m16n8k16 fp16, fp32 accum), NT.
// nseg=3: (Ah,Bh),(Ah,Bl),(Al,Bh).  nseg=2: (Ah,Bh),(Al,Bh).  nseg=1: (Ah,Bh).
// BM=BN=128, BK=64, 3-stage cp.async, 8 warps 2x4, warp tile 64x32.
// MODE 0: fp32 C. MODE 1: scale+mask fp32 C. MODE 3: hi fp16 plane only.
// skipMode 1: skip tile if local row0 >= lens[z]
// skipMode 2: skip tile if (row0 & 2047) >= lens[row0 >> 11]
// ---------------------------------------------------------------------------
__device__ __forceinline__ uint32_t sw128(uint32_t x) { return x ^ ((x >> 3) & 0x70); }

#define STAGE_B 32768
#define NSTAGE  3
#define SMEM_REQ (1024 + NSTAGE * STAGE_B)

__device__ __forceinline__ void cp16(uint32_t saddr, const void* gaddr) {
    asm volatile("cp.async.cg.shared.global [%0], [%1], 16;" :: "r"(saddr), "l"(gaddr));
}
__device__ __forceinline__ void cp_commit() {
    asm volatile("cp.async.commit_group;" ::: "memory");
}
template <int N> __device__ __forceinline__ void cp_wait() {
    asm volatile("cp.async.wait_group %0;" :: "n"(N) : "memory");
}
__device__ __forceinline__ void ldm4(uint32_t addr, uint32_t& r0, uint32_t& r1,
                                     uint32_t& r2, uint32_t& r3) {
    asm volatile("ldmatrix.sync.aligned.m8n8.x4.shared.b16 {%0,%1,%2,%3}, [%4];"
                 : "=r"(r0), "=r"(r1), "=r"(r2), "=r"(r3) : "r"(addr));
}
__device__ __forceinline__ void mma16816(float* c, uint32_t a0, uint32_t a1,
                                         uint32_t a2, uint32_t a3,
                                         uint32_t b0, uint32_t b1) {
    asm volatile(
        "mma.sync.aligned.m16n8k16.row.col.f32.f16.f16.f32 "
        "{%0,%1,%2,%3},{%4,%5,%6,%7},{%8,%9},{%0,%1,%2,%3};"
        : "+f"(c[0]), "+f"(c[1]), "+f"(c[2]), "+f"(c[3])
        : "r"(a0), "r"(a1), "r"(a2), "r"(a3), "r"(b0), "r"(b1));
}
__device__ __forceinline__ uint32_t pack_h2(__half a, __half b) {
    return (uint32_t)__half_as_ushort(a) | ((uint32_t)__half_as_ushort(b) << 16);
}

template <int MODE>
__global__ __launch_bounds__(256, 2)
void hmma_gemm(const __half* __restrict__ Ah, const __half* __restrict__ Al,
               const __half* __restrict__ Bh, const __half* __restrict__ Bl,
               float* __restrict__ C,
               __half* __restrict__ Poh,
               int K, int ldc,
               long long sA, long long sB, long long sC, float scale,
               int skipMode, int nseg) {
    const int z    = blockIdx.z;
    const int row0 = blockIdx.y * 128;
    const int n0   = blockIdx.x * 128;

    if (skipMode == 1) {
        if (row0 >= g_lens[z]) return;
    } else if (skipMode == 2) {
        if ((row0 & (Ln - 1)) >= g_lens[row0 >> 11]) return;
    }

    extern __shared__ char dsm[];
    uint32_t sraw = (uint32_t)__cvta_generic_to_shared(dsm);
    uint32_t sb   = (sraw + 1023) & ~1023u;

    const int tid  = threadIdx.x;
    const int lane = tid & 31;
    const int wid  = tid >> 5;
    const int wr   = wid >> 2;
    const int wc   = wid & 3;

    const int r = tid >> 1;
    const int h = (tid & 1) * 64;

    const char* aRowH = (const char*)(Ah + (size_t)z * sA + (size_t)(row0 + r) * K) + h;
    const char* aRowL = (const char*)(Al + (size_t)z * sA + (size_t)(row0 + r) * K) + h;
    const char* bRowH = (const char*)(Bh + (size_t)z * sB + (size_t)(n0 + r) * K) + h;
    const char* bRowL = (const char*)(Bl + (size_t)z * sB + (size_t)(n0 + r) * K) + h;

    uint32_t swo[4];
    #pragma unroll
    for (int i = 0; i < 4; i++) swo[i] = sw128((uint32_t)r * 128u + h + i * 16);

    float acc[4][4][4];
    #pragma unroll
    for (int a = 0; a < 4; a++)
        #pragma unroll
        for (int b = 0; b < 4; b++)
            #pragma unroll
            for (int cc = 0; cc < 4; cc++) acc[a][b][cc] = 0.0f;

    const int nch = K / 64;
    const int T   = nseg * nch;

    const char* aPtr = aRowH;
    const char* bPtr = bRowH;
    int cIss = 0, segIss = 0, bufIss = 0;

    auto issue_one = [&]() {
        uint32_t sa = sb + bufIss * STAGE_B;
        #pragma unroll
        for (int i = 0; i < 4; i++) {
            cp16(sa + swo[i], aPtr + i * 16);
            cp16(sa + 16384 + swo[i], bPtr + i * 16);
        }
        cp_commit();
        aPtr += 128; bPtr += 128;
        bufIss = (bufIss == NSTAGE - 1) ? 0 : bufIss + 1;
        if (++cIss == nch) {
            cIss = 0; segIss++;
            if (segIss == 1) {
                if (nseg == 2) { aPtr = aRowL; bPtr = bRowH; }
                else           { aPtr = aRowH; bPtr = bRowL; }
            } else if (segIss == 2) {
                aPtr = aRowL; bPtr = bRowH;
            }
        }
    };

    issue_one();
    issue_one();

    int bufC = 0;
    for (int t = 0; t < T; t++) {
        if (t + 2 < T)      { issue_one(); cp_wait<2>(); }
        else if (t + 1 < T) { cp_wait<1>(); }
        else                { cp_wait<0>(); }
        __syncthreads();

        const uint32_t aBase = sb + bufC * STAGE_B;
        const uint32_t bBase = aBase + 16384;

        #pragma unroll
        for (int kk = 0; kk < 4; kk++) {
            uint32_t af[4][4];
            #pragma unroll
            for (int mi = 0; mi < 4; mi++) {
                uint32_t row  = wr * 64 + mi * 16 + (lane & 15);
                uint32_t colb = kk * 32 + ((lane >> 4) << 4);
                ldm4(aBase + sw128(row * 128u + colb), af[mi][0], af[mi][1], af[mi][2], af[mi][3]);
            }
            uint32_t bf[2][4];
            #pragma unroll
            for (int ni = 0; ni < 2; ni++) {
                uint32_t q    = lane >> 3;
                uint32_t row  = wc * 32 + ni * 16 + ((q >> 1) << 3) + (lane & 7);
                uint32_t colb = kk * 32 + ((q & 1) << 4);
                ldm4(bBase + sw128(row * 128u + colb), bf[ni][0], bf[ni][1], bf[ni][2], bf[ni][3]);
            }
            #pragma unroll
            for (int mi = 0; mi < 4; mi++)
                #pragma unroll
                for (int n8 = 0; n8 < 4; n8++) {
                    uint32_t b0 = bf[n8 >> 1][(n8 & 1) * 2 + 0];
                    uint32_t b1 = bf[n8 >> 1][(n8 & 1) * 2 + 1];
                    mma16816(acc[mi][n8], af[mi][0], af[mi][1], af[mi][2], af[mi][3], b0, b1);
                }
        }
        __syncthreads();
        bufC = (bufC == NSTAGE - 1) ? 0 : bufC + 1;
    }

    // ---- epilogue
    const int g  = lane >> 2;
    const int tg = lane & 3;
    const int len = (MODE == 1) ? g_lens[z] : 0;

    #pragma unroll
    for (int mi = 0; mi < 4; mi++) {
        const int rA = row0 + wr * 64 + mi * 16 + g;
        const int rB = rA + 8;
        #pragma unroll
        for (int n8 = 0; n8 < 4; n8++) {
            const int col = n0 + wc * 32 + n8 * 8 + tg * 2;
            float v0 = acc[mi][n8][0], v1 = acc[mi][n8][1];
            float v2 = acc[mi][n8][2], v3 = acc[mi][n8][3];
            if (MODE == 0) {
                float* Cz = C + (size_t)z * sC;
                *(float2*)(Cz + (size_t)rA * ldc + col) = make_float2(v0, v1);
                *(float2*)(Cz + (size_t)rB * ldc + col) = make_float2(v2, v3);
            } else if (MODE == 1) {
                float* Cz = C + (size_t)z * sC;
                bool okA = rA < len, okB = rB < len;
                *(float2*)(Cz + (size_t)rA * ldc + col) =
                    make_float2(okA ? v0 * scale : -1e9f, okA ? v1 * scale : -1e9f);
                *(float2*)(Cz + (size_t)rB * ldc + col) =
                    make_float2(okB ? v2 * scale : -1e9f, okB ? v3 * scale : -1e9f);
            } else {
                __half* PohZ = Poh + (size_t)z * sC;
                *(uint32_t*)(PohZ + (size_t)rA * ldc + col) =
                    pack_h2(__float2half_rn(v0), __float2half_rn(v1));
                *(uint32_t*)(PohZ + (size_t)rB * ldc + col) =
                    pack_h2(__float2half_rn(v2), __float2half_rn(v3));
            }
        }
    }
}

// ---------------------------------------------------------------------------
// Row softmax over Ln=2048, in place + hi fp16 plane output.
// Masked rows (q >= len): exact uniform 1/2048, no reads.
// ---------------------------------------------------------------------------
__global__ __launch_bounds__(256)
void softmax_kernel(float* __restrict__ attn, __half* __restrict__ Ph) {
    const size_t row = blockIdx.x;
    const int b  = (int)(row >> 11);
    const int ql = (int)(row & (Ln - 1));
    float* p = attn + row * Ln;
    const int t = threadIdx.x;

    if (ql >= g_lens[b]) {
        const float u = 1.0f / 2048.0f;
        const unsigned short uh = __half_as_ushort(__float2half_rn(u));
        float4 uv = make_float4(u, u, u, u);
        ((float4*)p)[t * 2]     = uv;
        ((float4*)p)[t * 2 + 1] = uv;
        ushort4 us = make_ushort4(uh, uh, uh, uh);
        __half* ph = Ph + row * Ln + t * 8;
        *(ushort4*)(ph) = us; *(ushort4*)(ph + 4) = us;
        return;
    }

    float4 va = ((const float4*)p)[t * 2];
    float4 vb = ((const float4*)p)[t * 2 + 1];
    float v[8] = {va.x, va.y, va.z, va.w, vb.x, vb.y, vb.z, vb.w};

    float m = v[0];
    #pragma unroll
    for (int i = 1; i < 8; i++) m = fmaxf(m, v[i]);

    __shared__ float red[256];
    red[t] = m;
    __syncthreads();
    #pragma unroll
    for (int s = 128; s > 0; s >>= 1) {
        if (t < s) red[t] = fmaxf(red[t], red[t + s]);
        __syncthreads();
    }
    m = red[0];
    __syncthreads();

    float sum = 0.0f;
    #pragma unroll
    for (int i = 0; i < 8; i++) {
        v[i] = expf(v[i] - m);
        sum += v[i];
    }
    red[t] = sum;
    __syncthreads();
    #pragma unroll
    for (int s = 128; s > 0; s >>= 1) {
        if (t < s) red[t] += red[t + s];
        __syncthreads();
    }
    const float inv = 1.0f / red[0];

    unsigned short hb[8];
    #pragma unroll
    for (int i = 0; i < 8; i++) {
        v[i] *= inv;
        hb[i] = __half_as_ushort(__float2half_rn(v[i]));
    }
    ((float4*)p)[t * 2]     = make_float4(v[0], v[1], v[2], v[3]);
    ((float4*)p)[t * 2 + 1] = make_float4(v[4], v[5], v[6], v[7]);
    __half* ph = Ph + row * Ln + t * 8;
    *(ushort4*)(ph)     = make_ushort4(hb[0], hb[1], hb[2], hb[3]);
    *(ushort4*)(ph + 4) = make_ushort4(hb[4], hb[5], hb[6], hb[7]);
}

// ---------------------------------------------------------------------------
// kernel_launch
// ---------------------------------------------------------------------------
extern "C" void kernel_launch(void* const* d_in, const int* in_sizes, int n_in,
                              void* d_out, int out_size) {
    const float* X  = (const float*)d_in[0];
    const void*  lens_raw = d_in[1];
    const float* O  = (const float*)d_in[2];
    const float* Wk = (const float*)d_in[3];
    const float* Wv = (const float*)d_in[4];
    const float* Wq = (const float*)d_in[5];

    const long long CTX = (long long)Bn * Ln * Dn;
    const long long ATT = (long long)Bn * Ln * Ln;

    float *ctx_s, *attn_s, *vm, *xm;
    __half *Xh, *Oh, *Wvh, *WqTh, *WqTl, *WkTh, *WkTl;
    __half *GTh, *QGh, *XTh, *Ph, *PXh;
    cudaGetSymbolAddress((void**)&ctx_s, g_ctx_scratch);
    cudaGetSymbolAddress((void**)&attn_s, g_attn_scratch);
    cudaGetSymbolAddress((void**)&vm, g_vmean);
    cudaGetSymbolAddress((void**)&xm, g_xmean);
    cudaGetSymbolAddress((void**)&Xh, g_Xh);
    cudaGetSymbolAddress((void**)&Oh, g_Oh);
    cudaGetSymbolAddress((void**)&Wvh, g_Wvh);
    cudaGetSymbolAddress((void**)&WqTh, g_WqTh); cudaGetSymbolAddress((void**)&WqTl, g_WqTl);
    cudaGetSymbolAddress((void**)&WkTh, g_WkTh); cudaGetSymbolAddress((void**)&WkTl, g_WkTl);
    cudaGetSymbolAddress((void**)&GTh, g_GTh);
    cudaGetSymbolAddress((void**)&QGh, g_QGh);
    cudaGetSymbolAddress((void**)&XTh, g_XTh);
    cudaGetSymbolAddress((void**)&Ph, g_Ph);
    cudaGetSymbolAddress((void**)&PXh, g_PXh);

    float* ctx;
    float* attn;
    if ((long long)out_size >= CTX + ATT) {
        ctx  = (float*)d_out;
        attn = (float*)d_out + CTX;
    } else if ((long long)out_size == ATT) {
        attn = (float*)d_out;
        ctx  = ctx_s;
    } else {
        ctx  = (float*)d_out;
        attn = attn_s;
    }

    cudaFuncSetAttribute(hmma_gemm<0>, cudaFuncAttributeMaxDynamicSharedMemorySize, SMEM_REQ);
    cudaFuncSetAttribute(hmma_gemm<1>, cudaFuncAttributeMaxDynamicSharedMemorySize, SMEM_REQ);
    cudaFuncSetAttribute(hmma_gemm<3>, cudaFuncAttributeMaxDynamicSharedMemorySize, SMEM_REQ);

    prep_lens_kernel<<<1, 32>>>(lens_raw);

    // Expansions + transposes of raw inputs (only consumed planes written)
    {
        long long t4 = (long long)M_ALL * Dn / 4;
        int blocks = (int)((t4 + 255) / 256);
        expand1_kernel<<<blocks, 256>>>(X, Xh, t4);
        expand1_kernel<<<blocks, 256>>>(O, Oh, t4);
        long long w4 = (long long)Dn * Dn / 4;
        int wb = (int)((w4 + 255) / 256);
        expand1_kernel<<<wb, 256>>>(Wv, Wvh, w4);
        trans_kernel<<<dim3(Dn / 32, Dn / 32, 1), 256>>>(Wq, WqTh, WqTl, Dn, Dn);
        trans_kernel<<<dim3(Dn / 32, Dn / 32, 1), 256>>>(Wk, WkTh, WkTl, Dn, Dn);
        trans1_kernel<<<dim3(Dn / 32, Ln / 32, Bn), 256>>>(X, XTh, Ln, Dn);
    }

    // vmean = (mean_t X) @ Wv^T  (exact fp32 path for masked ctx rows)
    xmean_kernel<<<dim3(Dn / 256, Bn), 256>>>(X, xm);
    vmeanw_kernel<<<dim3(Dn / 8, Bn), 256>>>(xm, Wv, vm);

    // GT = Wk^T @ Wq   (3 segments; hi plane out)
    hmma_gemm<3><<<dim3(Dn / 128, Dn / 128, 1), 256, SMEM_REQ>>>(
        WkTh, WkTl, WqTh, WqTl, nullptr, GTh, Dn, Dn, 0, 0, 0, 1.0f, 0, 3);

    // QG = Oh @ GTh (1 segment); masked row tiles skipped; hi plane out
    hmma_gemm<3><<<dim3(Dn / 128, M_ALL / 128, 1), 256, SMEM_REQ>>>(
        Oh, nullptr, GTh, nullptr, nullptr, QGh, Dn, Dn, 0, 0, 0, 1.0f, 2, 1);

    // scores = QGh @ Xh^T / 32 per batch (1 segment), mask epilogue, tiles skipped
    hmma_gemm<1><<<dim3(Ln / 128, Ln / 128, Bn), 256, SMEM_REQ>>>(
        QGh, nullptr, Xh, nullptr, attn, nullptr, Dn, Ln,
        (long long)Ln * Dn, (long long)Ln * Dn, (long long)Ln * Ln, 0.03125f, 1, 1);

    // Softmax in place + P hi plane (uniform fill for masked rows)
    softmax_kernel<<<Bn * Ln, 256>>>(attn, Ph);

    // PX = Ph @ XTh per batch (1 segment); masked tiles skipped; hi plane out
    hmma_gemm<3><<<dim3(Dn / 128, Ln / 128, Bn), 256, SMEM_REQ>>>(
        Ph, nullptr, XTh, nullptr, nullptr, PXh, Ln, Dn,
        (long long)Ln * Ln, (long long)Dn * Ln, (long long)Ln * Dn, 1.0f, 1, 1);

    // ctx = PXh @ Wvh^T (1 segment); masked tiles skipped
    hmma_gemm<0><<<dim3(Dn / 128, M_ALL / 128, 1), 256, SMEM_REQ>>>(
        PXh, nullptr, Wvh, nullptr, ctx, nullptr, Dn, Dn, 0, 0, 0, 1.0f, 2, 1);

    // Masked ctx rows = per-batch V mean
    fill_masked_kernel<<<dim3(Dn / 256, Ln, Bn), 256>>>(vm, ctx);
}

// round 13
// speedup vs baseline: 4.6405x; 1.1143x over previous
#include <cuda_runtime.h>
#include <cuda_fp16.h>
#include <math.h>
#include <stdint.h>

#define Bn 8
#define Ln 2048
#define Dn 1024
#define M_ALL (Bn * Ln)   // 16384

// ---------------------------------------------------------------------------
// Device scratch (allocation-free rule -> __device__ globals)
// ---------------------------------------------------------------------------
__device__ float g_ctx_scratch[(size_t)M_ALL * Dn];
__device__ float g_attn_scratch[(size_t)Bn * Ln * Ln];
__device__ float g_vmean[(size_t)Bn * Dn];
__device__ float g_xmean[(size_t)Bn * Dn];
__device__ int   g_lens[Bn];

// fp16 planes (lo planes only where actually consumed: GT inputs)
__device__ __half g_Xh[(size_t)M_ALL * Dn];
__device__ __half g_Oh[(size_t)M_ALL * Dn];
__device__ __half g_Wvh[(size_t)Dn * Dn];
__device__ __half g_WqTh[(size_t)Dn * Dn];
__device__ __half g_WqTl[(size_t)Dn * Dn];
__device__ __half g_WkTh[(size_t)Dn * Dn];
__device__ __half g_WkTl[(size_t)Dn * Dn];
__device__ __half g_GTh[(size_t)Dn * Dn];
__device__ __half g_QGh[(size_t)M_ALL * Dn];
__device__ __half g_XTh[(size_t)Bn * Dn * Ln];
__device__ __half g_Ph[(size_t)M_ALL * Ln];
__device__ __half g_PXh[(size_t)M_ALL * Dn];

// ---------------------------------------------------------------------------
// lens dtype sniffing (int64 vs int32)
// ---------------------------------------------------------------------------
__global__ void prep_lens_kernel(const void* lensraw) {
    if (threadIdx.x == 0 && blockIdx.x == 0) {
        const int* a32 = (const int*)lensraw;
        bool is64 = true;
        #pragma unroll
        for (int i = 0; i < 4; i++) {
            int lo = a32[2 * i], hi = a32[2 * i + 1];
            if (hi != 0 || lo < 1 || lo > Ln) { is64 = false; break; }
        }
        if (is64) {
            const long long* a64 = (const long long*)lensraw;
            for (int i = 0; i < Bn; i++) g_lens[i] = (int)a64[i];
        } else {
            for (int i = 0; i < Bn; i++) g_lens[i] = a32[i];
        }
    }
}

// ---------------------------------------------------------------------------
// Fused X prep: one pass over X produces
//   Xh  (fp16 cast, row-major)
//   XTh (fp16, transposed per batch [Dn, Ln])
//   xmean[b][d] = (1/2048) * sum_t X[b,t,d]     (deterministic, no atomics)
// Grid: (Dn/32, Bn); each block owns a 32-wide d stripe over all 2048 tokens.
// ---------------------------------------------------------------------------
__global__ __launch_bounds__(256)
void xprep_kernel(const float* __restrict__ X, __half* __restrict__ Xh,
                  __half* __restrict__ XTh, float* __restrict__ xm) {
    __shared__ float tile[32][33];
    __shared__ float red[8][33];
    const int b  = blockIdx.y;
    const int d0 = blockIdx.x * 32;
    const int tx = threadIdx.x & 31;
    const int ty = threadIdx.x >> 5;     // 0..7

    const float* Xb  = X   + (size_t)b * Ln * Dn;
    __half* Xhb      = Xh  + (size_t)b * Ln * Dn;
    __half* XThb     = XTh + (size_t)b * Dn * Ln;

    float csum = 0.0f;
    for (int t0 = 0; t0 < Ln; t0 += 32) {
        #pragma unroll
        for (int j = 0; j < 4; j++) {
            int row = t0 + ty + j * 8;
            float v = Xb[(size_t)row * Dn + d0 + tx];
            tile[ty + j * 8][tx] = v;
            csum += v;
            Xhb[(size_t)row * Dn + d0 + tx] = __float2half_rn(v);
        }
        __syncthreads();
        #pragma unroll
        for (int j = 0; j < 4; j++) {
            XThb[(size_t)(d0 + ty + j * 8) * Ln + t0 + tx] =
                __float2half_rn(tile[tx][ty + j * 8]);
        }
        __syncthreads();
    }

    red[ty][tx] = csum;
    __syncthreads();
    if (ty == 0) {
        float s = red[0][tx];
        #pragma unroll
        for (int j = 1; j < 8; j++) s += red[j][tx];
        xm[b * Dn + d0 + tx] = s * (1.0f / 2048.0f);
    }
}

// ---------------------------------------------------------------------------
// fp32 -> hi fp16 plane only
// ---------------------------------------------------------------------------
__global__ __launch_bounds__(256)
void expand1_kernel(const float* __restrict__ src, __half* __restrict__ dh,
                    long long total4) {
    long long i = (long long)blockIdx.x * blockDim.x + threadIdx.x;
    if (i >= total4) return;
    float4 v = *(const float4*)(src + i * 4);
    ushort4 hu = make_ushort4(
        __half_as_ushort(__float2half_rn(v.x)),
        __half_as_ushort(__float2half_rn(v.y)),
        __half_as_ushort(__float2half_rn(v.z)),
        __half_as_ushort(__float2half_rn(v.w)));
    *(ushort4*)(dh + i * 4) = hu;
}

// ---------------------------------------------------------------------------
// Transpose fp32 [R,C] -> fp16 hi/lo planes [C,R]
// ---------------------------------------------------------------------------
__global__ __launch_bounds__(256)
void trans_kernel(const float* __restrict__ src, __half* __restrict__ oh,
                  __half* __restrict__ ol, int R, int C) {
    __shared__ float tile[32][33];
    int c0 = blockIdx.x * 32;
    int r0 = blockIdx.y * 32;
    int tx = threadIdx.x & 31;
    int ty = threadIdx.x >> 5;

    #pragma unroll
    for (int j = 0; j < 4; j++)
        tile[ty + j * 8][tx] = src[(size_t)(r0 + ty + j * 8) * C + c0 + tx];
    __syncthreads();

    #pragma unroll
    for (int j = 0; j < 4; j++) {
        float v = tile[tx][ty + j * 8];
        __half h = __float2half_rn(v);
        __half l = __float2half_rn(v - __half2float(h));
        size_t o = (size_t)(c0 + ty + j * 8) * R + r0 + tx;
        oh[o] = h;
        ol[o] = l;
    }
}

// ---------------------------------------------------------------------------
// vmean[b][e] = sum_d xmean[b][d] * Wv[e][d]
// ---------------------------------------------------------------------------
__global__ __launch_bounds__(256)
void vmeanw_kernel(const float* __restrict__ xm, const float* __restrict__ Wv,
                   float* __restrict__ vm) {
    int b = blockIdx.y;
    int e = blockIdx.x * 8 + (threadIdx.x >> 5);
    int lane = threadIdx.x & 31;
    const float* xr = xm + b * Dn;
    const float* wr = Wv + (size_t)e * Dn;
    float s = 0.f;
    for (int d = lane; d < Dn; d += 32) s += xr[d] * wr[d];
    #pragma unroll
    for (int o = 16; o > 0; o >>= 1) s += __shfl_down_sync(0xffffffffu, s, o);
    if (lane == 0) vm[b * Dn + e] = s;
}

// ---------------------------------------------------------------------------
// Fill masked ctx rows with vmean
// ---------------------------------------------------------------------------
__global__ __launch_bounds__(256)
void fill_masked_kernel(const float* __restrict__ vm, float* __restrict__ ctx) {
    int b = blockIdx.z;
    int q = blockIdx.y;
    if (q < g_lens[b]) return;
    int d = blockIdx.x * 256 + threadIdx.x;
    ctx[((size_t)b * Ln + q) * Dn + d] = vm[b * Dn + d];
}

// ---------------------------------------------------------------------------
// HMMA GEMM core (mma.sync m16n8k16 fp16, fp32 accum), NT.
// nseg=3: (Ah,Bh),(Ah,Bl),(Al,Bh).  nseg=1: (Ah,Bh).
// BM=BN=128, BK=64, 3-stage cp.async, 8 warps 2x4, warp tile 64x32.
// MODE 0: fp32 C. MODE 1: scale+mask fp32 C. MODE 3: hi fp16 plane only.
// skipMode 1: skip tile if local row0 >= lens[z]
// skipMode 2: skip tile if (row0 & 2047) >= lens[row0 >> 11]
// ---------------------------------------------------------------------------
__device__ __forceinline__ uint32_t sw128(uint32_t x) { return x ^ ((x >> 3) & 0x70); }

#define STAGE_B 32768
#define NSTAGE  3
#define SMEM_REQ (1024 + NSTAGE * STAGE_B)

__device__ __forceinline__ void cp16(uint32_t saddr, const void* gaddr) {
    asm volatile("cp.async.cg.shared.global [%0], [%1], 16;" :: "r"(saddr), "l"(gaddr));
}
__device__ __forceinline__ void cp_commit() {
    asm volatile("cp.async.commit_group;" ::: "memory");
}
template <int N> __device__ __forceinline__ void cp_wait() {
    asm volatile("cp.async.wait_group %0;" :: "n"(N) : "memory");
}
__device__ __forceinline__ void ldm4(uint32_t addr, uint32_t& r0, uint32_t& r1,
                                     uint32_t& r2, uint32_t& r3) {
    asm volatile("ldmatrix.sync.aligned.m8n8.x4.shared.b16 {%0,%1,%2,%3}, [%4];"
                 : "=r"(r0), "=r"(r1), "=r"(r2), "=r"(r3) : "r"(addr));
}
__device__ __forceinline__ void mma16816(float* c, uint32_t a0, uint32_t a1,
                                         uint32_t a2, uint32_t a3,
                                         uint32_t b0, uint32_t b1) {
    asm volatile(
        "mma.sync.aligned.m16n8k16.row.col.f32.f16.f16.f32 "
        "{%0,%1,%2,%3},{%4,%5,%6,%7},{%8,%9},{%0,%1,%2,%3};"
        : "+f"(c[0]), "+f"(c[1]), "+f"(c[2]), "+f"(c[3])
        : "r"(a0), "r"(a1), "r"(a2), "r"(a3), "r"(b0), "r"(b1));
}
__device__ __forceinline__ uint32_t pack_h2(__half a, __half b) {
    return (uint32_t)__half_as_ushort(a) | ((uint32_t)__half_as_ushort(b) << 16);
}

template <int MODE>
__global__ __launch_bounds__(256, 2)
void hmma_gemm(const __half* __restrict__ Ah, const __half* __restrict__ Al,
               const __half* __restrict__ Bh, const __half* __restrict__ Bl,
               float* __restrict__ C,
               __half* __restrict__ Poh,
               int K, int ldc,
               long long sA, long long sB, long long sC, float scale,
               int skipMode, int nseg) {
    const int z    = blockIdx.z;
    const int row0 = blockIdx.y * 128;
    const int n0   = blockIdx.x * 128;

    if (skipMode == 1) {
        if (row0 >= g_lens[z]) return;
    } else if (skipMode == 2) {
        if ((row0 & (Ln - 1)) >= g_lens[row0 >> 11]) return;
    }

    extern __shared__ char dsm[];
    uint32_t sraw = (uint32_t)__cvta_generic_to_shared(dsm);
    uint32_t sb   = (sraw + 1023) & ~1023u;

    const int tid  = threadIdx.x;
    const int lane = tid & 31;
    const int wid  = tid >> 5;
    const int wr   = wid >> 2;
    const int wc   = wid & 3;

    const int r = tid >> 1;
    const int h = (tid & 1) * 64;

    const char* aRowH = (const char*)(Ah + (size_t)z * sA + (size_t)(row0 + r) * K) + h;
    const char* aRowL = (const char*)(Al + (size_t)z * sA + (size_t)(row0 + r) * K) + h;
    const char* bRowH = (const char*)(Bh + (size_t)z * sB + (size_t)(n0 + r) * K) + h;
    const char* bRowL = (const char*)(Bl + (size_t)z * sB + (size_t)(n0 + r) * K) + h;

    uint32_t swo[4];
    #pragma unroll
    for (int i = 0; i < 4; i++) swo[i] = sw128((uint32_t)r * 128u + h + i * 16);

    float acc[4][4][4];
    #pragma unroll
    for (int a = 0; a < 4; a++)
        #pragma unroll
        for (int b = 0; b < 4; b++)
            #pragma unroll
            for (int cc = 0; cc < 4; cc++) acc[a][b][cc] = 0.0f;

    const int nch = K / 64;
    const int T   = nseg * nch;

    const char* aPtr = aRowH;
    const char* bPtr = bRowH;
    int cIss = 0, segIss = 0, bufIss = 0;

    auto issue_one = [&]() {
        uint32_t sa = sb + bufIss * STAGE_B;
        #pragma unroll
        for (int i = 0; i < 4; i++) {
            cp16(sa + swo[i], aPtr + i * 16);
            cp16(sa + 16384 + swo[i], bPtr + i * 16);
        }
        cp_commit();
        aPtr += 128; bPtr += 128;
        bufIss = (bufIss == NSTAGE - 1) ? 0 : bufIss + 1;
        if (++cIss == nch) {
            cIss = 0; segIss++;
            if (segIss == 1) {
                if (nseg == 2) { aPtr = aRowL; bPtr = bRowH; }
                else           { aPtr = aRowH; bPtr = bRowL; }
            } else if (segIss == 2) {
                aPtr = aRowL; bPtr = bRowH;
            }
        }
    };

    issue_one();
    issue_one();

    int bufC = 0;
    for (int t = 0; t < T; t++) {
        if (t + 2 < T)      { issue_one(); cp_wait<2>(); }
        else if (t + 1 < T) { cp_wait<1>(); }
        else                { cp_wait<0>(); }
        __syncthreads();

        const uint32_t aBase = sb + bufC * STAGE_B;
        const uint32_t bBase = aBase + 16384;

        #pragma unroll
        for (int kk = 0; kk < 4; kk++) {
            uint32_t af[4][4];
            #pragma unroll
            for (int mi = 0; mi < 4; mi++) {
                uint32_t row  = wr * 64 + mi * 16 + (lane & 15);
                uint32_t colb = kk * 32 + ((lane >> 4) << 4);
                ldm4(aBase + sw128(row * 128u + colb), af[mi][0], af[mi][1], af[mi][2], af[mi][3]);
            }
            uint32_t bf[2][4];
            #pragma unroll
            for (int ni = 0; ni < 2; ni++) {
                uint32_t q    = lane >> 3;
                uint32_t row  = wc * 32 + ni * 16 + ((q >> 1) << 3) + (lane & 7);
                uint32_t colb = kk * 32 + ((q & 1) << 4);
                ldm4(bBase + sw128(row * 128u + colb), bf[ni][0], bf[ni][1], bf[ni][2], bf[ni][3]);
            }
            #pragma unroll
            for (int mi = 0; mi < 4; mi++)
                #pragma unroll
                for (int n8 = 0; n8 < 4; n8++) {
                    uint32_t b0 = bf[n8 >> 1][(n8 & 1) * 2 + 0];
                    uint32_t b1 = bf[n8 >> 1][(n8 & 1) * 2 + 1];
                    mma16816(acc[mi][n8], af[mi][0], af[mi][1], af[mi][2], af[mi][3], b0, b1);
                }
        }
        __syncthreads();
        bufC = (bufC == NSTAGE - 1) ? 0 : bufC + 1;
    }

    // ---- epilogue
    const int g  = lane >> 2;
    const int tg = lane & 3;
    const int len = (MODE == 1) ? g_lens[z] : 0;

    #pragma unroll
    for (int mi = 0; mi < 4; mi++) {
        const int rA = row0 + wr * 64 + mi * 16 + g;
        const int rB = rA + 8;
        #pragma unroll
        for (int n8 = 0; n8 < 4; n8++) {
            const int col = n0 + wc * 32 + n8 * 8 + tg * 2;
            float v0 = acc[mi][n8][0], v1 = acc[mi][n8][1];
            float v2 = acc[mi][n8][2], v3 = acc[mi][n8][3];
            if (MODE == 0) {
                float* Cz = C + (size_t)z * sC;
                *(float2*)(Cz + (size_t)rA * ldc + col) = make_float2(v0, v1);
                *(float2*)(Cz + (size_t)rB * ldc + col) = make_float2(v2, v3);
            } else if (MODE == 1) {
                float* Cz = C + (size_t)z * sC;
                bool okA = rA < len, okB = rB < len;
                *(float2*)(Cz + (size_t)rA * ldc + col) =
                    make_float2(okA ? v0 * scale : -1e9f, okA ? v1 * scale : -1e9f);
                *(float2*)(Cz + (size_t)rB * ldc + col) =
                    make_float2(okB ? v2 * scale : -1e9f, okB ? v3 * scale : -1e9f);
            } else {
                __half* PohZ = Poh + (size_t)z * sC;
                *(uint32_t*)(PohZ + (size_t)rA * ldc + col) =
                    pack_h2(__float2half_rn(v0), __float2half_rn(v1));
                *(uint32_t*)(PohZ + (size_t)rB * ldc + col) =
                    pack_h2(__float2half_rn(v2), __float2half_rn(v3));
            }
        }
    }
}

// ---------------------------------------------------------------------------
// Row softmax over Ln=2048, in place + hi fp16 plane output.
// Warp-shuffle reduction (2 barriers). Masked rows: exact uniform 1/2048.
// ---------------------------------------------------------------------------
__global__ __launch_bounds__(256)
void softmax_kernel(float* __restrict__ attn, __half* __restrict__ Ph) {
    const size_t row = blockIdx.x;
    const int b  = (int)(row >> 11);
    const int ql = (int)(row & (Ln - 1));
    float* p = attn + row * Ln;
    const int t = threadIdx.x;

    if (ql >= g_lens[b]) {
        const float u = 1.0f / 2048.0f;
        const unsigned short uh = __half_as_ushort(__float2half_rn(u));
        float4 uv = make_float4(u, u, u, u);
        ((float4*)p)[t * 2]     = uv;
        ((float4*)p)[t * 2 + 1] = uv;
        ushort4 us = make_ushort4(uh, uh, uh, uh);
        __half* ph = Ph + row * Ln + t * 8;
        *(ushort4*)(ph) = us; *(ushort4*)(ph + 4) = us;
        return;
    }

    const int lane = t & 31;
    const int warp = t >> 5;
    __shared__ float wredm[8];
    __shared__ float wreds[8];

    float4 va = ((const float4*)p)[t * 2];
    float4 vb = ((const float4*)p)[t * 2 + 1];
    float v[8] = {va.x, va.y, va.z, va.w, vb.x, vb.y, vb.z, vb.w};

    float m = v[0];
    #pragma unroll
    for (int i = 1; i < 8; i++) m = fmaxf(m, v[i]);
    #pragma unroll
    for (int o = 16; o > 0; o >>= 1)
        m = fmaxf(m, __shfl_xor_sync(0xffffffffu, m, o));
    if (lane == 0) wredm[warp] = m;
    __syncthreads();
    m = wredm[0];
    #pragma unroll
    for (int j = 1; j < 8; j++) m = fmaxf(m, wredm[j]);

    float sum = 0.0f;
    #pragma unroll
    for (int i = 0; i < 8; i++) {
        v[i] = expf(v[i] - m);
        sum += v[i];
    }
    #pragma unroll
    for (int o = 16; o > 0; o >>= 1)
        sum += __shfl_xor_sync(0xffffffffu, sum, o);
    if (lane == 0) wreds[warp] = sum;
    __syncthreads();
    sum = wreds[0];
    #pragma unroll
    for (int j = 1; j < 8; j++) sum += wreds[j];
    const float inv = 1.0f / sum;

    unsigned short hb[8];
    #pragma unroll
    for (int i = 0; i < 8; i++) {
        v[i] *= inv;
        hb[i] = __half_as_ushort(__float2half_rn(v[i]));
    }
    ((float4*)p)[t * 2]     = make_float4(v[0], v[1], v[2], v[3]);
    ((float4*)p)[t * 2 + 1] = make_float4(v[4], v[5], v[6], v[7]);
    __half* ph = Ph + row * Ln + t * 8;
    *(ushort4*)(ph)     = make_ushort4(hb[0], hb[1], hb[2], hb[3]);
    *(ushort4*)(ph + 4) = make_ushort4(hb[4], hb[5], hb[6], hb[7]);
}

// ---------------------------------------------------------------------------
// kernel_launch
// ---------------------------------------------------------------------------
extern "C" void kernel_launch(void* const* d_in, const int* in_sizes, int n_in,
                              void* d_out, int out_size) {
    const float* X  = (const float*)d_in[0];
    const void*  lens_raw = d_in[1];
    const float* O  = (const float*)d_in[2];
    const float* Wk = (const float*)d_in[3];
    const float* Wv = (const float*)d_in[4];
    const float* Wq = (const float*)d_in[5];

    const long long CTX = (long long)Bn * Ln * Dn;
    const long long ATT = (long long)Bn * Ln * Ln;

    float *ctx_s, *attn_s, *vm, *xm;
    __half *Xh, *Oh, *Wvh, *WqTh, *WqTl, *WkTh, *WkTl;
    __half *GTh, *QGh, *XTh, *Ph, *PXh;
    cudaGetSymbolAddress((void**)&ctx_s, g_ctx_scratch);
    cudaGetSymbolAddress((void**)&attn_s, g_attn_scratch);
    cudaGetSymbolAddress((void**)&vm, g_vmean);
    cudaGetSymbolAddress((void**)&xm, g_xmean);
    cudaGetSymbolAddress((void**)&Xh, g_Xh);
    cudaGetSymbolAddress((void**)&Oh, g_Oh);
    cudaGetSymbolAddress((void**)&Wvh, g_Wvh);
    cudaGetSymbolAddress((void**)&WqTh, g_WqTh); cudaGetSymbolAddress((void**)&WqTl, g_WqTl);
    cudaGetSymbolAddress((void**)&WkTh, g_WkTh); cudaGetSymbolAddress((void**)&WkTl, g_WkTl);
    cudaGetSymbolAddress((void**)&GTh, g_GTh);
    cudaGetSymbolAddress((void**)&QGh, g_QGh);
    cudaGetSymbolAddress((void**)&XTh, g_XTh);
    cudaGetSymbolAddress((void**)&Ph, g_Ph);
    cudaGetSymbolAddress((void**)&PXh, g_PXh);

    float* ctx;
    float* attn;
    if ((long long)out_size >= CTX + ATT) {
        ctx  = (float*)d_out;
        attn = (float*)d_out + CTX;
    } else if ((long long)out_size == ATT) {
        attn = (float*)d_out;
        ctx  = ctx_s;
    } else {
        ctx  = (float*)d_out;
        attn = attn_s;
    }

    cudaFuncSetAttribute(hmma_gemm<0>, cudaFuncAttributeMaxDynamicSharedMemorySize, SMEM_REQ);
    cudaFuncSetAttribute(hmma_gemm<1>, cudaFuncAttributeMaxDynamicSharedMemorySize, SMEM_REQ);
    cudaFuncSetAttribute(hmma_gemm<3>, cudaFuncAttributeMaxDynamicSharedMemorySize, SMEM_REQ);

    prep_lens_kernel<<<1, 32>>>(lens_raw);

    // Fused X prep: Xh + XTh + xmean in one pass over X
    xprep_kernel<<<dim3(Dn / 32, Bn), 256>>>(X, Xh, XTh, xm);

    // Other input prep
    {
        long long t4 = (long long)M_ALL * Dn / 4;
        int blocks = (int)((t4 + 255) / 256);
        expand1_kernel<<<blocks, 256>>>(O, Oh, t4);
        long long w4 = (long long)Dn * Dn / 4;
        int wb = (int)((w4 + 255) / 256);
        expand1_kernel<<<wb, 256>>>(Wv, Wvh, w4);
        trans_kernel<<<dim3(Dn / 32, Dn / 32, 1), 256>>>(Wq, WqTh, WqTl, Dn, Dn);
        trans_kernel<<<dim3(Dn / 32, Dn / 32, 1), 256>>>(Wk, WkTh, WkTl, Dn, Dn);
    }

    // vmean = xmean @ Wv^T  (exact fp32 path for masked ctx rows)
    vmeanw_kernel<<<dim3(Dn / 8, Bn), 256>>>(xm, Wv, vm);

    // GT = Wk^T @ Wq   (3 segments; hi plane out)
    hmma_gemm<3><<<dim3(Dn / 128, Dn / 128, 1), 256, SMEM_REQ>>>(
        WkTh, WkTl, WqTh, WqTl, nullptr, GTh, Dn, Dn, 0, 0, 0, 1.0f, 0, 3);

    // QG = Oh @ GTh (1 segment); masked row tiles skipped; hi plane out
    hmma_gemm<3><<<dim3(Dn / 128, M_ALL / 128, 1), 256, SMEM_REQ>>>(
        Oh, nullptr, GTh, nullptr, nullptr, QGh, Dn, Dn, 0, 0, 0, 1.0f, 2, 1);

    // scores = QGh @ Xh^T / 32 per batch (1 segment), mask epilogue, tiles skipped
    hmma_gemm<1><<<dim3(Ln / 128, Ln / 128, Bn), 256, SMEM_REQ>>>(
        QGh, nullptr, Xh, nullptr, attn, nullptr, Dn, Ln,
        (long long)Ln * Dn, (long long)Ln * Dn, (long long)Ln * Ln, 0.03125f, 1, 1);

    // Softmax in place + P hi plane (uniform fill for masked rows)
    softmax_kernel<<<Bn * Ln, 256>>>(attn, Ph);

    // PX = Ph @ XTh per batch (1 segment); masked tiles skipped; hi plane out
    hmma_gemm<3><<<dim3(Dn / 128, Ln / 128, Bn), 256, SMEM_REQ>>>(
        Ph, nullptr, XTh, nullptr, nullptr, PXh, Ln, Dn,
        (long long)Ln * Ln, (long long)Dn * Ln, (long long)Ln * Dn, 1.0f, 1, 1);

    // ctx = PXh @ Wvh^T (1 segment); masked tiles skipped
    hmma_gemm<0><<<dim3(Dn / 128, M_ALL / 128, 1), 256, SMEM_REQ>>>(
        PXh, nullptr, Wvh, nullptr, ctx, nullptr, Dn, Dn, 0, 0, 0, 1.0f, 2, 1);

    // Masked ctx rows = per-batch V mean
    fill_masked_kernel<<<dim3(Dn / 256, Ln, Bn), 256>>>(vm, ctx);
}

// round 15
// speedup vs baseline: 5.0191x; 1.0816x over previous
#include <cuda_runtime.h>
#include <cuda_fp16.h>
#include <math.h>
#include <stdint.h>

#define Bn 8
#define Ln 2048
#define Dn 1024
#define M_ALL (Bn * Ln)   // 16384

// ---------------------------------------------------------------------------
// Device scratch (allocation-free rule -> __device__ globals)
// ---------------------------------------------------------------------------
__device__ float g_ctx_scratch[(size_t)M_ALL * Dn];
__device__ float g_attn_scratch[(size_t)Bn * Ln * Ln];
__device__ float g_vmean[(size_t)Bn * Dn];
__device__ float g_xmean[(size_t)Bn * Dn];
__device__ int   g_lens[Bn];

// fp16 planes (lo planes only where actually consumed: GT inputs)
__device__ __half g_Xh[(size_t)M_ALL * Dn];
__device__ __half g_Oh[(size_t)M_ALL * Dn];
__device__ __half g_Wvh[(size_t)Dn * Dn];
__device__ __half g_WqTh[(size_t)Dn * Dn];
__device__ __half g_WqTl[(size_t)Dn * Dn];
__device__ __half g_WkTh[(size_t)Dn * Dn];
__device__ __half g_WkTl[(size_t)Dn * Dn];
__device__ __half g_GTh[(size_t)Dn * Dn];
__device__ __half g_QGh[(size_t)M_ALL * Dn];
__device__ __half g_XTh[(size_t)Bn * Dn * Ln];
__device__ __half g_Ph[(size_t)M_ALL * Ln];
__device__ __half g_PXh[(size_t)M_ALL * Dn];

// ---------------------------------------------------------------------------
// lens dtype sniffing (int64 vs int32)
// ---------------------------------------------------------------------------
__global__ void prep_lens_kernel(const void* lensraw) {
    if (threadIdx.x == 0 && blockIdx.x == 0) {
        const int* a32 = (const int*)lensraw;
        bool is64 = true;
        #pragma unroll
        for (int i = 0; i < 4; i++) {
            int lo = a32[2 * i], hi = a32[2 * i + 1];
            if (hi != 0 || lo < 1 || lo > Ln) { is64 = false; break; }
        }
        if (is64) {
            const long long* a64 = (const long long*)lensraw;
            for (int i = 0; i < Bn; i++) g_lens[i] = (int)a64[i];
        } else {
            for (int i = 0; i < Bn; i++) g_lens[i] = a32[i];
        }
    }
}

// ---------------------------------------------------------------------------
// Fused X prep: one pass over X produces Xh, XTh, xmean (deterministic).
// Grid: (Dn/32, Bn)
// ---------------------------------------------------------------------------
__global__ __launch_bounds__(256)
void xprep_kernel(const float* __restrict__ X, __half* __restrict__ Xh,
                  __half* __restrict__ XTh, float* __restrict__ xm) {
    __shared__ float tile[32][33];
    __shared__ float red[8][33];
    const int b  = blockIdx.y;
    const int d0 = blockIdx.x * 32;
    const int tx = threadIdx.x & 31;
    const int ty = threadIdx.x >> 5;

    const float* Xb  = X   + (size_t)b * Ln * Dn;
    __half* Xhb      = Xh  + (size_t)b * Ln * Dn;
    __half* XThb     = XTh + (size_t)b * Dn * Ln;

    float csum = 0.0f;
    for (int t0 = 0; t0 < Ln; t0 += 32) {
        #pragma unroll
        for (int j = 0; j < 4; j++) {
            int row = t0 + ty + j * 8;
            float v = Xb[(size_t)row * Dn + d0 + tx];
            tile[ty + j * 8][tx] = v;
            csum += v;
            Xhb[(size_t)row * Dn + d0 + tx] = __float2half_rn(v);
        }
        __syncthreads();
        #pragma unroll
        for (int j = 0; j < 4; j++) {
            XThb[(size_t)(d0 + ty + j * 8) * Ln + t0 + tx] =
                __float2half_rn(tile[tx][ty + j * 8]);
        }
        __syncthreads();
    }

    red[ty][tx] = csum;
    __syncthreads();
    if (ty == 0) {
        float s = red[0][tx];
        #pragma unroll
        for (int j = 1; j < 8; j++) s += red[j][tx];
        xm[b * Dn + d0 + tx] = s * (1.0f / 2048.0f);
    }
}

// ---------------------------------------------------------------------------
// fp32 -> hi fp16 plane only
// ---------------------------------------------------------------------------
__global__ __launch_bounds__(256)
void expand1_kernel(const float* __restrict__ src, __half* __restrict__ dh,
                    long long total4) {
    long long i = (long long)blockIdx.x * blockDim.x + threadIdx.x;
    if (i >= total4) return;
    float4 v = *(const float4*)(src + i * 4);
    ushort4 hu = make_ushort4(
        __half_as_ushort(__float2half_rn(v.x)),
        __half_as_ushort(__float2half_rn(v.y)),
        __half_as_ushort(__float2half_rn(v.z)),
        __half_as_ushort(__float2half_rn(v.w)));
    *(ushort4*)(dh + i * 4) = hu;
}

// ---------------------------------------------------------------------------
// Batched weight transpose: z=0 -> Wq, z=1 -> Wk; fp32 [Dn,Dn] -> hi/lo [Dn,Dn]
// ---------------------------------------------------------------------------
__global__ __launch_bounds__(256)
void wtrans_kernel(const float* __restrict__ Wq, const float* __restrict__ Wk,
                   __half* __restrict__ qh, __half* __restrict__ ql,
                   __half* __restrict__ kh, __half* __restrict__ kl) {
    __shared__ float tile[32][33];
    const float* src = blockIdx.z ? Wk : Wq;
    __half* oh = blockIdx.z ? kh : qh;
    __half* ol = blockIdx.z ? kl : ql;
    int c0 = blockIdx.x * 32;
    int r0 = blockIdx.y * 32;
    int tx = threadIdx.x & 31;
    int ty = threadIdx.x >> 5;

    #pragma unroll
    for (int j = 0; j < 4; j++)
        tile[ty + j * 8][tx] = src[(size_t)(r0 + ty + j * 8) * Dn + c0 + tx];
    __syncthreads();

    #pragma unroll
    for (int j = 0; j < 4; j++) {
        float v = tile[tx][ty + j * 8];
        __half h = __float2half_rn(v);
        __half l = __float2half_rn(v - __half2float(h));
        size_t o = (size_t)(c0 + ty + j * 8) * Dn + r0 + tx;
        oh[o] = h;
        ol[o] = l;
    }
}

// ---------------------------------------------------------------------------
// vmean[b][e] = sum_d xmean[b][d] * Wv[e][d]
// ---------------------------------------------------------------------------
__global__ __launch_bounds__(256)
void vmeanw_kernel(const float* __restrict__ xm, const float* __restrict__ Wv,
                   float* __restrict__ vm) {
    int b = blockIdx.y;
    int e = blockIdx.x * 8 + (threadIdx.x >> 5);
    int lane = threadIdx.x & 31;
    const float* xr = xm + b * Dn;
    const float* wr = Wv + (size_t)e * Dn;
    float s = 0.f;
    for (int d = lane; d < Dn; d += 32) s += xr[d] * wr[d];
    #pragma unroll
    for (int o = 16; o > 0; o >>= 1) s += __shfl_down_sync(0xffffffffu, s, o);
    if (lane == 0) vm[b * Dn + e] = s;
}

// ---------------------------------------------------------------------------
// HMMA GEMM core (mma.sync m16n8k16 fp16, fp32 accum), NT.
// Single-barrier multistage (issue after the leading __syncthreads).
// nseg=3: (Ah,Bh),(Ah,Bl),(Al,Bh).  nseg=1: (Ah,Bh).
// BM=BN=128, BK=64, 3-stage cp.async, 8 warps 2x4, warp tile 64x32.
// MODE 1: scale+mask fp32 C (per-batch z; local rows).
// MODE 3: hi fp16 plane only.
// MODE 4: fp32 C with vmean fill for masked rows (flat M; batch = row>>11;
//         per-row mask uses LOCAL row index (rA & (Ln-1))).
// skipMode 1: skip tile if local row0 >= lens[z]
// skipMode 2: skip tile if (row0 & 2047) >= lens[row0 >> 11]
// ---------------------------------------------------------------------------
__device__ __forceinline__ uint32_t sw128(uint32_t x) { return x ^ ((x >> 3) & 0x70); }

#define STAGE_B 32768
#define NSTAGE  3
#define SMEM_REQ (1024 + NSTAGE * STAGE_B)

__device__ __forceinline__ void cp16(uint32_t saddr, const void* gaddr) {
    asm volatile("cp.async.cg.shared.global [%0], [%1], 16;" :: "r"(saddr), "l"(gaddr));
}
__device__ __forceinline__ void cp_commit() {
    asm volatile("cp.async.commit_group;" ::: "memory");
}
template <int N> __device__ __forceinline__ void cp_wait() {
    asm volatile("cp.async.wait_group %0;" :: "n"(N) : "memory");
}
__device__ __forceinline__ void ldm4(uint32_t addr, uint32_t& r0, uint32_t& r1,
                                     uint32_t& r2, uint32_t& r3) {
    asm volatile("ldmatrix.sync.aligned.m8n8.x4.shared.b16 {%0,%1,%2,%3}, [%4];"
                 : "=r"(r0), "=r"(r1), "=r"(r2), "=r"(r3) : "r"(addr));
}
__device__ __forceinline__ void mma16816(float* c, uint32_t a0, uint32_t a1,
                                         uint32_t a2, uint32_t a3,
                                         uint32_t b0, uint32_t b1) {
    asm volatile(
        "mma.sync.aligned.m16n8k16.row.col.f32.f16.f16.f32 "
        "{%0,%1,%2,%3},{%4,%5,%6,%7},{%8,%9},{%0,%1,%2,%3};"
        : "+f"(c[0]), "+f"(c[1]), "+f"(c[2]), "+f"(c[3])
        : "r"(a0), "r"(a1), "r"(a2), "r"(a3), "r"(b0), "r"(b1));
}
__device__ __forceinline__ uint32_t pack_h2(__half a, __half b) {
    return (uint32_t)__half_as_ushort(a) | ((uint32_t)__half_as_ushort(b) << 16);
}

template <int MODE>
__global__ __launch_bounds__(256, 2)
void hmma_gemm(const __half* __restrict__ Ah, const __half* __restrict__ Al,
               const __half* __restrict__ Bh, const __half* __restrict__ Bl,
               float* __restrict__ C,
               __half* __restrict__ Poh,
               const float* __restrict__ vmean,
               int K, int ldc,
               long long sA, long long sB, long long sC, float scale,
               int skipMode, int nseg) {
    const int z    = blockIdx.z;
    const int row0 = blockIdx.y * 128;
    const int n0   = blockIdx.x * 128;
    const int tid  = threadIdx.x;

    bool fullMasked = false;
    if (skipMode == 1) {
        fullMasked = (row0 >= g_lens[z]);
    } else if (skipMode == 2) {
        fullMasked = ((row0 & (Ln - 1)) >= g_lens[row0 >> 11]);
    }
    if (fullMasked) {
        if (MODE == 4) {
            // store-only fast path: every row of the tile = vmean[batch]
            const int bb = row0 >> 11;
            const int cq = (tid & 31) * 4;           // 32 threads x float4 = 128 cols
            const int rr0 = tid >> 5;                // 8 rows in parallel
            float4 v = *(const float4*)(vmean + (size_t)bb * Dn + n0 + cq);
            float* Cz = C + (size_t)z * sC;
            #pragma unroll
            for (int i = 0; i < 16; i++) {
                int row = row0 + rr0 + i * 8;
                *(float4*)(Cz + (size_t)row * ldc + n0 + cq) = v;
            }
        }
        return;
    }

    extern __shared__ char dsm[];
    uint32_t sraw = (uint32_t)__cvta_generic_to_shared(dsm);
    uint32_t sb   = (sraw + 1023) & ~1023u;

    const int lane = tid & 31;
    const int wid  = tid >> 5;
    const int wr   = wid >> 2;
    const int wc   = wid & 3;

    const int r = tid >> 1;
    const int h = (tid & 1) * 64;

    const char* aRowH = (const char*)(Ah + (size_t)z * sA + (size_t)(row0 + r) * K) + h;
    const char* aRowL = (const char*)(Al + (size_t)z * sA + (size_t)(row0 + r) * K) + h;
    const char* bRowH = (const char*)(Bh + (size_t)z * sB + (size_t)(n0 + r) * K) + h;
    const char* bRowL = (const char*)(Bl + (size_t)z * sB + (size_t)(n0 + r) * K) + h;

    uint32_t swo[4];
    #pragma unroll
    for (int i = 0; i < 4; i++) swo[i] = sw128((uint32_t)r * 128u + h + i * 16);

    float acc[4][4][4];
    #pragma unroll
    for (int a = 0; a < 4; a++)
        #pragma unroll
        for (int b = 0; b < 4; b++)
            #pragma unroll
            for (int cc = 0; cc < 4; cc++) acc[a][b][cc] = 0.0f;

    const int nch = K / 64;
    const int T   = nseg * nch;

    const char* aPtr = aRowH;
    const char* bPtr = bRowH;
    int cIss = 0, segIss = 0, bufIss = 0;

    auto issue_one = [&]() {
        uint32_t sa = sb + bufIss * STAGE_B;
        #pragma unroll
        for (int i = 0; i < 4; i++) {
            cp16(sa + swo[i], aPtr + i * 16);
            cp16(sa + 16384 + swo[i], bPtr + i * 16);
        }
        cp_commit();
        aPtr += 128; bPtr += 128;
        bufIss = (bufIss == NSTAGE - 1) ? 0 : bufIss + 1;
        if (++cIss == nch) {
            cIss = 0; segIss++;
            if (segIss == 1) {
                if (nseg == 2) { aPtr = aRowL; bPtr = bRowH; }
                else           { aPtr = aRowH; bPtr = bRowL; }
            } else if (segIss == 2) {
                aPtr = aRowL; bPtr = bRowH;
            }
        }
    };

    issue_one();
    issue_one();

    int bufC = 0;
    for (int t = 0; t < T; t++) {
        if (t + 1 < T) cp_wait<1>(); else cp_wait<0>();
        __syncthreads();
        if (t + 2 < T) issue_one();   // safe: buffer (t+2)%3 last read at t-1, synced

        const uint32_t aBase = sb + bufC * STAGE_B;
        const uint32_t bBase = aBase + 16384;

        #pragma unroll
        for (int kk = 0; kk < 4; kk++) {
            uint32_t af[4][4];
            #pragma unroll
            for (int mi = 0; mi < 4; mi++) {
                uint32_t row  = wr * 64 + mi * 16 + (lane & 15);
                uint32_t colb = kk * 32 + ((lane >> 4) << 4);
                ldm4(aBase + sw128(row * 128u + colb), af[mi][0], af[mi][1], af[mi][2], af[mi][3]);
            }
            uint32_t bf[2][4];
            #pragma unroll
            for (int ni = 0; ni < 2; ni++) {
                uint32_t q    = lane >> 3;
                uint32_t row  = wc * 32 + ni * 16 + ((q >> 1) << 3) + (lane & 7);
                uint32_t colb = kk * 32 + ((q & 1) << 4);
                ldm4(bBase + sw128(row * 128u + colb), bf[ni][0], bf[ni][1], bf[ni][2], bf[ni][3]);
            }
            #pragma unroll
            for (int mi = 0; mi < 4; mi++)
                #pragma unroll
                for (int n8 = 0; n8 < 4; n8++) {
                    uint32_t b0 = bf[n8 >> 1][(n8 & 1) * 2 + 0];
                    uint32_t b1 = bf[n8 >> 1][(n8 & 1) * 2 + 1];
                    mma16816(acc[mi][n8], af[mi][0], af[mi][1], af[mi][2], af[mi][3], b0, b1);
                }
        }
        bufC = (bufC == NSTAGE - 1) ? 0 : bufC + 1;
    }

    // ---- epilogue
    const int g  = lane >> 2;
    const int tg = lane & 3;
    int len = 0;
    if (MODE == 1) len = g_lens[z];
    if (MODE == 4) len = g_lens[row0 >> 11];

    #pragma unroll
    for (int mi = 0; mi < 4; mi++) {
        const int rA = row0 + wr * 64 + mi * 16 + g;
        const int rB = rA + 8;
        #pragma unroll
        for (int n8 = 0; n8 < 4; n8++) {
            const int col = n0 + wc * 32 + n8 * 8 + tg * 2;
            float v0 = acc[mi][n8][0], v1 = acc[mi][n8][1];
            float v2 = acc[mi][n8][2], v3 = acc[mi][n8][3];
            if (MODE == 1) {
                float* Cz = C + (size_t)z * sC;
                bool okA = rA < len, okB = rB < len;
                *(float2*)(Cz + (size_t)rA * ldc + col) =
                    make_float2(okA ? v0 * scale : -1e9f, okA ? v1 * scale : -1e9f);
                *(float2*)(Cz + (size_t)rB * ldc + col) =
                    make_float2(okB ? v2 * scale : -1e9f, okB ? v3 * scale : -1e9f);
            } else if (MODE == 4) {
                float* Cz = C + (size_t)z * sC;
                const int bb = row0 >> 11;
                // LOCAL row index vs per-batch len (R14 bug: used flat rA)
                bool okA = (rA & (Ln - 1)) < len;
                bool okB = (rB & (Ln - 1)) < len;
                float m0 = vmean[(size_t)bb * Dn + col];
                float m1 = vmean[(size_t)bb * Dn + col + 1];
                *(float2*)(Cz + (size_t)rA * ldc + col) =
                    make_float2(okA ? v0 : m0, okA ? v1 : m1);
                *(float2*)(Cz + (size_t)rB * ldc + col) =
                    make_float2(okB ? v2 : m0, okB ? v3 : m1);
            } else {
                __half* PohZ = Poh + (size_t)z * sC;
                *(uint32_t*)(PohZ + (size_t)rA * ldc + col) =
                    pack_h2(__float2half_rn(v0), __float2half_rn(v1));
                *(uint32_t*)(PohZ + (size_t)rB * ldc + col) =
                    pack_h2(__float2half_rn(v2), __float2half_rn(v3));
            }
        }
    }
}

// ---------------------------------------------------------------------------
// Row softmax over Ln=2048, in place + hi fp16 plane output.
// Warp-shuffle reduction. Masked rows: uniform attn fill only (Ph masked rows
// are provably dead: consumed only by masked PX/ctx rows, overwritten later).
// ---------------------------------------------------------------------------
__global__ __launch_bounds__(256)
void softmax_kernel(float* __restrict__ attn, __half* __restrict__ Ph) {
    const size_t row = blockIdx.x;
    const int b  = (int)(row >> 11);
    const int ql = (int)(row & (Ln - 1));
    float* p = attn + row * Ln;
    const int t = threadIdx.x;

    if (ql >= g_lens[b]) {
        const float u = 1.0f / 2048.0f;
        float4 uv = make_float4(u, u, u, u);
        ((float4*)p)[t * 2]     = uv;
        ((float4*)p)[t * 2 + 1] = uv;
        return;
    }

    const int lane = t & 31;
    const int warp = t >> 5;
    __shared__ float wredm[8];
    __shared__ float wreds[8];

    float4 va = ((const float4*)p)[t * 2];
    float4 vb = ((const float4*)p)[t * 2 + 1];
    float v[8] = {va.x, va.y, va.z, va.w, vb.x, vb.y, vb.z, vb.w};

    float m = v[0];
    #pragma unroll
    for (int i = 1; i < 8; i++) m = fmaxf(m, v[i]);
    #pragma unroll
    for (int o = 16; o > 0; o >>= 1)
        m = fmaxf(m, __shfl_xor_sync(0xffffffffu, m, o));
    if (lane == 0) wredm[warp] = m;
    __syncthreads();
    m = wredm[0];
    #pragma unroll
    for (int j = 1; j < 8; j++) m = fmaxf(m, wredm[j]);

    float sum = 0.0f;
    #pragma unroll
    for (int i = 0; i < 8; i++) {
        v[i] = expf(v[i] - m);
        sum += v[i];
    }
    #pragma unroll
    for (int o = 16; o > 0; o >>= 1)
        sum += __shfl_xor_sync(0xffffffffu, sum, o);
    if (lane == 0) wreds[warp] = sum;
    __syncthreads();
    sum = wreds[0];
    #pragma unroll
    for (int j = 1; j < 8; j++) sum += wreds[j];
    const float inv = 1.0f / sum;

    unsigned short hb[8];
    #pragma unroll
    for (int i = 0; i < 8; i++) {
        v[i] *= inv;
        hb[i] = __half_as_ushort(__float2half_rn(v[i]));
    }
    ((float4*)p)[t * 2]     = make_float4(v[0], v[1], v[2], v[3]);
    ((float4*)p)[t * 2 + 1] = make_float4(v[4], v[5], v[6], v[7]);
    __half* ph = Ph + row * Ln + t * 8;
    *(ushort4*)(ph)     = make_ushort4(hb[0], hb[1], hb[2], hb[3]);
    *(ushort4*)(ph + 4) = make_ushort4(hb[4], hb[5], hb[6], hb[7]);
}

// ---------------------------------------------------------------------------
// kernel_launch
// ---------------------------------------------------------------------------
extern "C" void kernel_launch(void* const* d_in, const int* in_sizes, int n_in,
                              void* d_out, int out_size) {
    const float* X  = (const float*)d_in[0];
    const void*  lens_raw = d_in[1];
    const float* O  = (const float*)d_in[2];
    const float* Wk = (const float*)d_in[3];
    const float* Wv = (const float*)d_in[4];
    const float* Wq = (const float*)d_in[5];

    const long long CTX = (long long)Bn * Ln * Dn;
    const long long ATT = (long long)Bn * Ln * Ln;

    float *ctx_s, *attn_s, *vm, *xm;
    __half *Xh, *Oh, *Wvh, *WqTh, *WqTl, *WkTh, *WkTl;
    __half *GTh, *QGh, *XTh, *Ph, *PXh;
    cudaGetSymbolAddress((void**)&ctx_s, g_ctx_scratch);
    cudaGetSymbolAddress((void**)&attn_s, g_attn_scratch);
    cudaGetSymbolAddress((void**)&vm, g_vmean);
    cudaGetSymbolAddress((void**)&xm, g_xmean);
    cudaGetSymbolAddress((void**)&Xh, g_Xh);
    cudaGetSymbolAddress((void**)&Oh, g_Oh);
    cudaGetSymbolAddress((void**)&Wvh, g_Wvh);
    cudaGetSymbolAddress((void**)&WqTh, g_WqTh); cudaGetSymbolAddress((void**)&WqTl, g_WqTl);
    cudaGetSymbolAddress((void**)&WkTh, g_WkTh); cudaGetSymbolAddress((void**)&WkTl, g_WkTl);
    cudaGetSymbolAddress((void**)&GTh, g_GTh);
    cudaGetSymbolAddress((void**)&QGh, g_QGh);
    cudaGetSymbolAddress((void**)&XTh, g_XTh);
    cudaGetSymbolAddress((void**)&Ph, g_Ph);
    cudaGetSymbolAddress((void**)&PXh, g_PXh);

    float* ctx;
    float* attn;
    if ((long long)out_size >= CTX + ATT) {
        ctx  = (float*)d_out;
        attn = (float*)d_out + CTX;
    } else if ((long long)out_size == ATT) {
        attn = (float*)d_out;
        ctx  = ctx_s;
    } else {
        ctx  = (float*)d_out;
        attn = attn_s;
    }

    cudaFuncSetAttribute(hmma_gemm<1>, cudaFuncAttributeMaxDynamicSharedMemorySize, SMEM_REQ);
    cudaFuncSetAttribute(hmma_gemm<3>, cudaFuncAttributeMaxDynamicSharedMemorySize, SMEM_REQ);
    cudaFuncSetAttribute(hmma_gemm<4>, cudaFuncAttributeMaxDynamicSharedMemorySize, SMEM_REQ);

    prep_lens_kernel<<<1, 32>>>(lens_raw);

    // Fused X prep: Xh + XTh + xmean in one pass over X
    xprep_kernel<<<dim3(Dn / 32, Bn), 256>>>(X, Xh, XTh, xm);

    // Other input prep
    {
        long long t4 = (long long)M_ALL * Dn / 4;
        int blocks = (int)((t4 + 255) / 256);
        expand1_kernel<<<blocks, 256>>>(O, Oh, t4);
        long long w4 = (long long)Dn * Dn / 4;
        int wb = (int)((w4 + 255) / 256);
        expand1_kernel<<<wb, 256>>>(Wv, Wvh, w4);
        wtrans_kernel<<<dim3(Dn / 32, Dn / 32, 2), 256>>>(Wq, Wk, WqTh, WqTl, WkTh, WkTl);
    }

    // vmean = xmean @ Wv^T  (exact fp32 path for masked ctx rows)
    vmeanw_kernel<<<dim3(Dn / 8, Bn), 256>>>(xm, Wv, vm);

    // GT = Wk^T @ Wq   (3 segments; hi plane out)
    hmma_gemm<3><<<dim3(Dn / 128, Dn / 128, 1), 256, SMEM_REQ>>>(
        WkTh, WkTl, WqTh, WqTl, nullptr, GTh, nullptr, Dn, Dn, 0, 0, 0, 1.0f, 0, 3);

    // QG = Oh @ GTh (1 segment); masked row tiles skipped; hi plane out
    hmma_gemm<3><<<dim3(Dn / 128, M_ALL / 128, 1), 256, SMEM_REQ>>>(
        Oh, nullptr, GTh, nullptr, nullptr, QGh, nullptr, Dn, Dn, 0, 0, 0, 1.0f, 2, 1);

    // scores = QGh @ Xh^T / 32 per batch (1 segment), mask epilogue, tiles skipped
    hmma_gemm<1><<<dim3(Ln / 128, Ln / 128, Bn), 256, SMEM_REQ>>>(
        QGh, nullptr, Xh, nullptr, attn, nullptr, nullptr, Dn, Ln,
        (long long)Ln * Dn, (long long)Ln * Dn, (long long)Ln * Ln, 0.03125f, 1, 1);

    // Softmax in place + P hi plane (masked rows: attn uniform fill only)
    softmax_kernel<<<Bn * Ln, 256>>>(attn, Ph);

    // PX = Ph @ XTh per batch (1 segment); masked tiles skipped; hi plane out
    hmma_gemm<3><<<dim3(Dn / 128, Ln / 128, Bn), 256, SMEM_REQ>>>(
        Ph, nullptr, XTh, nullptr, nullptr, PXh, nullptr, Ln, Dn,
        (long long)Ln * Ln, (long long)Dn * Ln, (long long)Ln * Dn, 1.0f, 1, 1);

    // ctx = PXh @ Wvh^T (1 segment); masked rows/tiles filled with vmean in-kernel
    hmma_gemm<4><<<dim3(Dn / 128, M_ALL / 128, 1), 256, SMEM_REQ>>>(
        PXh, nullptr, Wvh, nullptr, ctx, nullptr, vm, Dn, Dn, 0, 0, 0, 1.0f, 2, 1);
}

// round 16
// speedup vs baseline: 5.2064x; 1.0373x over previous
#include <cuda_runtime.h>
#include <cuda_fp16.h>
#include <math.h>
#include <stdint.h>

#define Bn 8
#define Ln 2048
#define Dn 1024
#define M_ALL (Bn * Ln)   // 16384

// ---------------------------------------------------------------------------
// Device scratch (allocation-free rule -> __device__ globals)
// ---------------------------------------------------------------------------
__device__ float g_ctx_scratch[(size_t)M_ALL * Dn];
__device__ float g_attn_scratch[(size_t)Bn * Ln * Ln];
__device__ float g_vmean[(size_t)Bn * Dn];
__device__ float g_xmean[(size_t)Bn * Dn];
__device__ int   g_lens[Bn];

// fp16 planes (lo planes only where actually consumed: GT inputs)
__device__ __half g_Xh[(size_t)M_ALL * Dn];
__device__ __half g_Oh[(size_t)M_ALL * Dn];
__device__ __half g_Wvh[(size_t)Dn * Dn];
__device__ __half g_WqTh[(size_t)Dn * Dn];
__device__ __half g_WqTl[(size_t)Dn * Dn];
__device__ __half g_WkTh[(size_t)Dn * Dn];
__device__ __half g_WkTl[(size_t)Dn * Dn];
__device__ __half g_GTh[(size_t)Dn * Dn];
__device__ __half g_QGh[(size_t)M_ALL * Dn];
__device__ __half g_XTh[(size_t)Bn * Dn * Ln];
__device__ __half g_Ph[(size_t)M_ALL * Ln];
__device__ __half g_PXh[(size_t)M_ALL * Dn];

// ---------------------------------------------------------------------------
// lens dtype sniffing (int64 vs int32)
// ---------------------------------------------------------------------------
__global__ void prep_lens_kernel(const void* lensraw) {
    if (threadIdx.x == 0 && blockIdx.x == 0) {
        const int* a32 = (const int*)lensraw;
        bool is64 = true;
        #pragma unroll
        for (int i = 0; i < 4; i++) {
            int lo = a32[2 * i], hi = a32[2 * i + 1];
            if (hi != 0 || lo < 1 || lo > Ln) { is64 = false; break; }
        }
        if (is64) {
            const long long* a64 = (const long long*)lensraw;
            for (int i = 0; i < Bn; i++) g_lens[i] = (int)a64[i];
        } else {
            for (int i = 0; i < Bn; i++) g_lens[i] = a32[i];
        }
    }
}

// ---------------------------------------------------------------------------
// Megaprep: ALL independent input prep in one full-chip launch.
//   Region A (256 blk):   X -> Xh, XTh (transposed), xmean
//   Region B (16384 blk): O -> Oh (fp16 hi cast)
//   Region C (1024 blk):  Wv -> Wvh
//   Region D (2048 blk):  Wq/Wk -> WqTh/l, WkTh/l (transposed hi/lo)
// ---------------------------------------------------------------------------
#define MP_A 256
#define MP_B 16384
#define MP_C 1024
#define MP_D 2048
#define MP_TOTAL (MP_A + MP_B + MP_C + MP_D)

__global__ __launch_bounds__(256)
void megaprep_kernel(const float* __restrict__ X, const float* __restrict__ O,
                     const float* __restrict__ Wq, const float* __restrict__ Wk,
                     const float* __restrict__ Wv,
                     __half* __restrict__ Xh, __half* __restrict__ XTh,
                     float* __restrict__ xm,
                     __half* __restrict__ Oh, __half* __restrict__ Wvh,
                     __half* __restrict__ WqTh, __half* __restrict__ WqTl,
                     __half* __restrict__ WkTh, __half* __restrict__ WkTl) {
    __shared__ float tile[32][33];
    __shared__ float red[8][33];
    const int bid = blockIdx.x;
    const int tid = threadIdx.x;
    const int tx = tid & 31;
    const int ty = tid >> 5;

    if (bid < MP_A) {
        // ---- X prep: Xh + XTh + xmean
        const int b  = bid >> 5;
        const int d0 = (bid & 31) * 32;
        const float* Xb  = X   + (size_t)b * Ln * Dn;
        __half* Xhb      = Xh  + (size_t)b * Ln * Dn;
        __half* XThb     = XTh + (size_t)b * Dn * Ln;

        float csum = 0.0f;
        for (int t0 = 0; t0 < Ln; t0 += 32) {
            #pragma unroll
            for (int j = 0; j < 4; j++) {
                int row = t0 + ty + j * 8;
                float v = Xb[(size_t)row * Dn + d0 + tx];
                tile[ty + j * 8][tx] = v;
                csum += v;
                Xhb[(size_t)row * Dn + d0 + tx] = __float2half_rn(v);
            }
            __syncthreads();
            #pragma unroll
            for (int j = 0; j < 4; j++) {
                XThb[(size_t)(d0 + ty + j * 8) * Ln + t0 + tx] =
                    __float2half_rn(tile[tx][ty + j * 8]);
            }
            __syncthreads();
        }
        red[ty][tx] = csum;
        __syncthreads();
        if (ty == 0) {
            float s = red[0][tx];
            #pragma unroll
            for (int j = 1; j < 8; j++) s += red[j][tx];
            xm[b * Dn + d0 + tx] = s * (1.0f / 2048.0f);
        }
    } else if (bid < MP_A + MP_B) {
        // ---- O -> Oh
        long long i = (long long)(bid - MP_A) * 256 + tid;
        float4 v = *(const float4*)(O + i * 4);
        *(ushort4*)(Oh + i * 4) = make_ushort4(
            __half_as_ushort(__float2half_rn(v.x)),
            __half_as_ushort(__float2half_rn(v.y)),
            __half_as_ushort(__float2half_rn(v.z)),
            __half_as_ushort(__float2half_rn(v.w)));
    } else if (bid < MP_A + MP_B + MP_C) {
        // ---- Wv -> Wvh
        long long i = (long long)(bid - MP_A - MP_B) * 256 + tid;
        float4 v = *(const float4*)(Wv + i * 4);
        *(ushort4*)(Wvh + i * 4) = make_ushort4(
            __half_as_ushort(__float2half_rn(v.x)),
            __half_as_ushort(__float2half_rn(v.y)),
            __half_as_ushort(__float2half_rn(v.z)),
            __half_as_ushort(__float2half_rn(v.w)));
    } else {
        // ---- Wq / Wk transpose -> hi/lo planes
        const int wbid = bid - MP_A - MP_B - MP_C;
        const int zz   = wbid >> 10;                // 0: Wq, 1: Wk
        const int rem  = wbid & 1023;
        const int c0 = (rem & 31) * 32;
        const int r0 = (rem >> 5) * 32;
        const float* src = zz ? Wk : Wq;
        __half* oh = zz ? WkTh : WqTh;
        __half* ol = zz ? WkTl : WqTl;

        #pragma unroll
        for (int j = 0; j < 4; j++)
            tile[ty + j * 8][tx] = src[(size_t)(r0 + ty + j * 8) * Dn + c0 + tx];
        __syncthreads();
        #pragma unroll
        for (int j = 0; j < 4; j++) {
            float v = tile[tx][ty + j * 8];
            __half h = __float2half_rn(v);
            __half l = __float2half_rn(v - __half2float(h));
            size_t o = (size_t)(c0 + ty + j * 8) * Dn + r0 + tx;
            oh[o] = h;
            ol[o] = l;
        }
    }
}

// ---------------------------------------------------------------------------
// vmean[b][e] = sum_d xmean[b][d] * Wv[e][d]
// ---------------------------------------------------------------------------
__global__ __launch_bounds__(256)
void vmeanw_kernel(const float* __restrict__ xm, const float* __restrict__ Wv,
                   float* __restrict__ vm) {
    int b = blockIdx.y;
    int e = blockIdx.x * 8 + (threadIdx.x >> 5);
    int lane = threadIdx.x & 31;
    const float* xr = xm + b * Dn;
    const float* wr = Wv + (size_t)e * Dn;
    float s = 0.f;
    for (int d = lane; d < Dn; d += 32) s += xr[d] * wr[d];
    #pragma unroll
    for (int o = 16; o > 0; o >>= 1) s += __shfl_down_sync(0xffffffffu, s, o);
    if (lane == 0) vm[b * Dn + e] = s;
}

// ---------------------------------------------------------------------------
// HMMA GEMM core (mma.sync m16n8k16 fp16, fp32 accum), NT.
// Single-barrier multistage. nseg=3 or 1.
// MODE 1: scale fp32 C; masked rows get the FINAL uniform 1/2048 (fully-masked
//         tiles via store-only fast path) so softmax can skip them.
// MODE 3: hi fp16 plane only.
// MODE 4: fp32 C, masked rows -> vmean (local-row mask!).
// skipMode 1: tile skip if local row0 >= lens[z]
// skipMode 2: tile skip if (row0 & 2047) >= lens[row0 >> 11]
// ---------------------------------------------------------------------------
__device__ __forceinline__ uint32_t sw128(uint32_t x) { return x ^ ((x >> 3) & 0x70); }

#define STAGE_B 32768
#define NSTAGE  3
#define SMEM_REQ (1024 + NSTAGE * STAGE_B)
#define UNI (1.0f / 2048.0f)

__device__ __forceinline__ void cp16(uint32_t saddr, const void* gaddr) {
    asm volatile("cp.async.cg.shared.global [%0], [%1], 16;" :: "r"(saddr), "l"(gaddr));
}
__device__ __forceinline__ void cp_commit() {
    asm volatile("cp.async.commit_group;" ::: "memory");
}
template <int N> __device__ __forceinline__ void cp_wait() {
    asm volatile("cp.async.wait_group %0;" :: "n"(N) : "memory");
}
__device__ __forceinline__ void ldm4(uint32_t addr, uint32_t& r0, uint32_t& r1,
                                     uint32_t& r2, uint32_t& r3) {
    asm volatile("ldmatrix.sync.aligned.m8n8.x4.shared.b16 {%0,%1,%2,%3}, [%4];"
                 : "=r"(r0), "=r"(r1), "=r"(r2), "=r"(r3) : "r"(addr));
}
__device__ __forceinline__ void mma16816(float* c, uint32_t a0, uint32_t a1,
                                         uint32_t a2, uint32_t a3,
                                         uint32_t b0, uint32_t b1) {
    asm volatile(
        "mma.sync.aligned.m16n8k16.row.col.f32.f16.f16.f32 "
        "{%0,%1,%2,%3},{%4,%5,%6,%7},{%8,%9},{%0,%1,%2,%3};"
        : "+f"(c[0]), "+f"(c[1]), "+f"(c[2]), "+f"(c[3])
        : "r"(a0), "r"(a1), "r"(a2), "r"(a3), "r"(b0), "r"(b1));
}
__device__ __forceinline__ uint32_t pack_h2(__half a, __half b) {
    return (uint32_t)__half_as_ushort(a) | ((uint32_t)__half_as_ushort(b) << 16);
}

template <int MODE>
__global__ __launch_bounds__(256, 2)
void hmma_gemm(const __half* __restrict__ Ah, const __half* __restrict__ Al,
               const __half* __restrict__ Bh, const __half* __restrict__ Bl,
               float* __restrict__ C,
               __half* __restrict__ Poh,
               const float* __restrict__ vmean,
               int K, int ldc,
               long long sA, long long sB, long long sC, float scale,
               int skipMode, int nseg) {
    const int z    = blockIdx.z;
    const int row0 = blockIdx.y * 128;
    const int n0   = blockIdx.x * 128;
    const int tid  = threadIdx.x;

    bool fullMasked = false;
    if (skipMode == 1) {
        fullMasked = (row0 >= g_lens[z]);
    } else if (skipMode == 2) {
        fullMasked = ((row0 & (Ln - 1)) >= g_lens[row0 >> 11]);
    }
    if (fullMasked) {
        if (MODE == 4 || MODE == 1) {
            // store-only fast path: fill the tile with final masked values
            const int cq  = (tid & 31) * 4;
            const int rr0 = tid >> 5;
            float4 v;
            if (MODE == 4) {
                const int bb = row0 >> 11;
                v = *(const float4*)(vmean + (size_t)bb * Dn + n0 + cq);
            } else {
                v = make_float4(UNI, UNI, UNI, UNI);
            }
            float* Cz = C + (size_t)z * sC;
            #pragma unroll
            for (int i = 0; i < 16; i++) {
                int row = row0 + rr0 + i * 8;
                *(float4*)(Cz + (size_t)row * ldc + n0 + cq) = v;
            }
        }
        return;
    }

    extern __shared__ char dsm[];
    uint32_t sraw = (uint32_t)__cvta_generic_to_shared(dsm);
    uint32_t sb   = (sraw + 1023) & ~1023u;

    const int lane = tid & 31;
    const int wid  = tid >> 5;
    const int wr   = wid >> 2;
    const int wc   = wid & 3;

    const int r = tid >> 1;
    const int h = (tid & 1) * 64;

    const char* aRowH = (const char*)(Ah + (size_t)z * sA + (size_t)(row0 + r) * K) + h;
    const char* aRowL = (const char*)(Al + (size_t)z * sA + (size_t)(row0 + r) * K) + h;
    const char* bRowH = (const char*)(Bh + (size_t)z * sB + (size_t)(n0 + r) * K) + h;
    const char* bRowL = (const char*)(Bl + (size_t)z * sB + (size_t)(n0 + r) * K) + h;

    uint32_t swo[4];
    #pragma unroll
    for (int i = 0; i < 4; i++) swo[i] = sw128((uint32_t)r * 128u + h + i * 16);

    float acc[4][4][4];
    #pragma unroll
    for (int a = 0; a < 4; a++)
        #pragma unroll
        for (int b = 0; b < 4; b++)
            #pragma unroll
            for (int cc = 0; cc < 4; cc++) acc[a][b][cc] = 0.0f;

    const int nch = K / 64;
    const int T   = nseg * nch;

    const char* aPtr = aRowH;
    const char* bPtr = bRowH;
    int cIss = 0, segIss = 0, bufIss = 0;

    auto issue_one = [&]() {
        uint32_t sa = sb + bufIss * STAGE_B;
        #pragma unroll
        for (int i = 0; i < 4; i++) {
            cp16(sa + swo[i], aPtr + i * 16);
            cp16(sa + 16384 + swo[i], bPtr + i * 16);
        }
        cp_commit();
        aPtr += 128; bPtr += 128;
        bufIss = (bufIss == NSTAGE - 1) ? 0 : bufIss + 1;
        if (++cIss == nch) {
            cIss = 0; segIss++;
            if (segIss == 1) {
                if (nseg == 2) { aPtr = aRowL; bPtr = bRowH; }
                else           { aPtr = aRowH; bPtr = bRowL; }
            } else if (segIss == 2) {
                aPtr = aRowL; bPtr = bRowH;
            }
        }
    };

    issue_one();
    issue_one();

    int bufC = 0;
    for (int t = 0; t < T; t++) {
        if (t + 1 < T) cp_wait<1>(); else cp_wait<0>();
        __syncthreads();
        if (t + 2 < T) issue_one();   // safe: buffer (t+2)%3 last read at t-1, synced

        const uint32_t aBase = sb + bufC * STAGE_B;
        const uint32_t bBase = aBase + 16384;

        #pragma unroll
        for (int kk = 0; kk < 4; kk++) {
            uint32_t af[4][4];
            #pragma unroll
            for (int mi = 0; mi < 4; mi++) {
                uint32_t row  = wr * 64 + mi * 16 + (lane & 15);
                uint32_t colb = kk * 32 + ((lane >> 4) << 4);
                ldm4(aBase + sw128(row * 128u + colb), af[mi][0], af[mi][1], af[mi][2], af[mi][3]);
            }
            uint32_t bf[2][4];
            #pragma unroll
            for (int ni = 0; ni < 2; ni++) {
                uint32_t q    = lane >> 3;
                uint32_t row  = wc * 32 + ni * 16 + ((q >> 1) << 3) + (lane & 7);
                uint32_t colb = kk * 32 + ((q & 1) << 4);
                ldm4(bBase + sw128(row * 128u + colb), bf[ni][0], bf[ni][1], bf[ni][2], bf[ni][3]);
            }
            #pragma unroll
            for (int mi = 0; mi < 4; mi++)
                #pragma unroll
                for (int n8 = 0; n8 < 4; n8++) {
                    uint32_t b0 = bf[n8 >> 1][(n8 & 1) * 2 + 0];
                    uint32_t b1 = bf[n8 >> 1][(n8 & 1) * 2 + 1];
                    mma16816(acc[mi][n8], af[mi][0], af[mi][1], af[mi][2], af[mi][3], b0, b1);
                }
        }
        bufC = (bufC == NSTAGE - 1) ? 0 : bufC + 1;
    }

    // ---- epilogue
    const int g  = lane >> 2;
    const int tg = lane & 3;
    int len = 0;
    if (MODE == 1) len = g_lens[z];
    if (MODE == 4) len = g_lens[row0 >> 11];

    #pragma unroll
    for (int mi = 0; mi < 4; mi++) {
        const int rA = row0 + wr * 64 + mi * 16 + g;
        const int rB = rA + 8;
        #pragma unroll
        for (int n8 = 0; n8 < 4; n8++) {
            const int col = n0 + wc * 32 + n8 * 8 + tg * 2;
            float v0 = acc[mi][n8][0], v1 = acc[mi][n8][1];
            float v2 = acc[mi][n8][2], v3 = acc[mi][n8][3];
            if (MODE == 1) {
                float* Cz = C + (size_t)z * sC;
                bool okA = rA < len, okB = rB < len;
                // masked rows: final uniform attn value (softmax skips them)
                *(float2*)(Cz + (size_t)rA * ldc + col) =
                    make_float2(okA ? v0 * scale : UNI, okA ? v1 * scale : UNI);
                *(float2*)(Cz + (size_t)rB * ldc + col) =
                    make_float2(okB ? v2 * scale : UNI, okB ? v3 * scale : UNI);
            } else if (MODE == 4) {
                float* Cz = C + (size_t)z * sC;
                const int bb = row0 >> 11;
                bool okA = (rA & (Ln - 1)) < len;
                bool okB = (rB & (Ln - 1)) < len;
                float m0 = vmean[(size_t)bb * Dn + col];
                float m1 = vmean[(size_t)bb * Dn + col + 1];
                *(float2*)(Cz + (size_t)rA * ldc + col) =
                    make_float2(okA ? v0 : m0, okA ? v1 : m1);
                *(float2*)(Cz + (size_t)rB * ldc + col) =
                    make_float2(okB ? v2 : m0, okB ? v3 : m1);
            } else {
                __half* PohZ = Poh + (size_t)z * sC;
                *(uint32_t*)(PohZ + (size_t)rA * ldc + col) =
                    pack_h2(__float2half_rn(v0), __float2half_rn(v1));
                *(uint32_t*)(PohZ + (size_t)rB * ldc + col) =
                    pack_h2(__float2half_rn(v2), __float2half_rn(v3));
            }
        }
    }
}

// ---------------------------------------------------------------------------
// Row softmax over Ln=2048, in place + hi fp16 plane output.
// Masked rows: ALREADY final (scores wrote uniform) -> zero-work return.
// (Ph masked rows are dead: consumed only by masked PX/ctx rows.)
// ---------------------------------------------------------------------------
__global__ __launch_bounds__(256)
void softmax_kernel(float* __restrict__ attn, __half* __restrict__ Ph) {
    const size_t row = blockIdx.x;
    const int b  = (int)(row >> 11);
    const int ql = (int)(row & (Ln - 1));
    if (ql >= g_lens[b]) return;

    float* p = attn + row * Ln;
    const int t = threadIdx.x;
    const int lane = t & 31;
    const int warp = t >> 5;
    __shared__ float wredm[8];
    __shared__ float wreds[8];

    float4 va = ((const float4*)p)[t * 2];
    float4 vb = ((const float4*)p)[t * 2 + 1];
    float v[8] = {va.x, va.y, va.z, va.w, vb.x, vb.y, vb.z, vb.w};

    float m = v[0];
    #pragma unroll
    for (int i = 1; i < 8; i++) m = fmaxf(m, v[i]);
    #pragma unroll
    for (int o = 16; o > 0; o >>= 1)
        m = fmaxf(m, __shfl_xor_sync(0xffffffffu, m, o));
    if (lane == 0) wredm[warp] = m;
    __syncthreads();
    m = wredm[0];
    #pragma unroll
    for (int j = 1; j < 8; j++) m = fmaxf(m, wredm[j]);

    float sum = 0.0f;
    #pragma unroll
    for (int i = 0; i < 8; i++) {
        v[i] = expf(v[i] - m);
        sum += v[i];
    }
    #pragma unroll
    for (int o = 16; o > 0; o >>= 1)
        sum += __shfl_xor_sync(0xffffffffu, sum, o);
    if (lane == 0) wreds[warp] = sum;
    __syncthreads();
    sum = wreds[0];
    #pragma unroll
    for (int j = 1; j < 8; j++) sum += wreds[j];
    const float inv = 1.0f / sum;

    unsigned short hb[8];
    #pragma unroll
    for (int i = 0; i < 8; i++) {
        v[i] *= inv;
        hb[i] = __half_as_ushort(__float2half_rn(v[i]));
    }
    ((float4*)p)[t * 2]     = make_float4(v[0], v[1], v[2], v[3]);
    ((float4*)p)[t * 2 + 1] = make_float4(v[4], v[5], v[6], v[7]);
    __half* ph = Ph + row * Ln + t * 8;
    *(ushort4*)(ph)     = make_ushort4(hb[0], hb[1], hb[2], hb[3]);
    *(ushort4*)(ph + 4) = make_ushort4(hb[4], hb[5], hb[6], hb[7]);
}

// ---------------------------------------------------------------------------
// kernel_launch
// ---------------------------------------------------------------------------
extern "C" void kernel_launch(void* const* d_in, const int* in_sizes, int n_in,
                              void* d_out, int out_size) {
    const float* X  = (const float*)d_in[0];
    const void*  lens_raw = d_in[1];
    const float* O  = (const float*)d_in[2];
    const float* Wk = (const float*)d_in[3];
    const float* Wv = (const float*)d_in[4];
    const float* Wq = (const float*)d_in[5];

    const long long CTX = (long long)Bn * Ln * Dn;
    const long long ATT = (long long)Bn * Ln * Ln;

    float *ctx_s, *attn_s, *vm, *xm;
    __half *Xh, *Oh, *Wvh, *WqTh, *WqTl, *WkTh, *WkTl;
    __half *GTh, *QGh, *XTh, *Ph, *PXh;
    cudaGetSymbolAddress((void**)&ctx_s, g_ctx_scratch);
    cudaGetSymbolAddress((void**)&attn_s, g_attn_scratch);
    cudaGetSymbolAddress((void**)&vm, g_vmean);
    cudaGetSymbolAddress((void**)&xm, g_xmean);
    cudaGetSymbolAddress((void**)&Xh, g_Xh);
    cudaGetSymbolAddress((void**)&Oh, g_Oh);
    cudaGetSymbolAddress((void**)&Wvh, g_Wvh);
    cudaGetSymbolAddress((void**)&WqTh, g_WqTh); cudaGetSymbolAddress((void**)&WqTl, g_WqTl);
    cudaGetSymbolAddress((void**)&WkTh, g_WkTh); cudaGetSymbolAddress((void**)&WkTl, g_WkTl);
    cudaGetSymbolAddress((void**)&GTh, g_GTh);
    cudaGetSymbolAddress((void**)&QGh, g_QGh);
    cudaGetSymbolAddress((void**)&XTh, g_XTh);
    cudaGetSymbolAddress((void**)&Ph, g_Ph);
    cudaGetSymbolAddress((void**)&PXh, g_PXh);

    float* ctx;
    float* attn;
    if ((long long)out_size >= CTX + ATT) {
        ctx  = (float*)d_out;
        attn = (float*)d_out + CTX;
    } else if ((long long)out_size == ATT) {
        attn = (float*)d_out;
        ctx  = ctx_s;
    } else {
        ctx  = (float*)d_out;
        attn = attn_s;
    }

    cudaFuncSetAttribute(hmma_gemm<1>, cudaFuncAttributeMaxDynamicSharedMemorySize, SMEM_REQ);
    cudaFuncSetAttribute(hmma_gemm<3>, cudaFuncAttributeMaxDynamicSharedMemorySize, SMEM_REQ);
    cudaFuncSetAttribute(hmma_gemm<4>, cudaFuncAttributeMaxDynamicSharedMemorySize, SMEM_REQ);

    prep_lens_kernel<<<1, 32>>>(lens_raw);

    // All independent input prep in one full-chip launch
    megaprep_kernel<<<MP_TOTAL, 256>>>(X, O, Wq, Wk, Wv,
                                       Xh, XTh, xm, Oh, Wvh,
                                       WqTh, WqTl, WkTh, WkTl);

    // vmean = xmean @ Wv^T  (exact fp32 path for masked ctx rows)
    vmeanw_kernel<<<dim3(Dn / 8, Bn), 256>>>(xm, Wv, vm);

    // GT = Wk^T @ Wq   (3 segments; hi plane out)
    hmma_gemm<3><<<dim3(Dn / 128, Dn / 128, 1), 256, SMEM_REQ>>>(
        WkTh, WkTl, WqTh, WqTl, nullptr, GTh, nullptr, Dn, Dn, 0, 0, 0, 1.0f, 0, 3);

    // QG = Oh @ GTh (1 segment); masked row tiles skipped; hi plane out
    hmma_gemm<3><<<dim3(Dn / 128, M_ALL / 128, 1), 256, SMEM_REQ>>>(
        Oh, nullptr, GTh, nullptr, nullptr, QGh, nullptr, Dn, Dn, 0, 0, 0, 1.0f, 2, 1);

    // scores = QGh @ Xh^T / 32 per batch (1 segment); masked rows/tiles get
    // the FINAL uniform 1/2048 in-kernel
    hmma_gemm<1><<<dim3(Ln / 128, Ln / 128, Bn), 256, SMEM_REQ>>>(
        QGh, nullptr, Xh, nullptr, attn, nullptr, nullptr, Dn, Ln,
        (long long)Ln * Dn, (long long)Ln * Dn, (long long)Ln * Ln, 0.03125f, 1, 1);

    // Softmax in place + P hi plane (masked rows: zero work)
    softmax_kernel<<<Bn * Ln, 256>>>(attn, Ph);

    // PX = Ph @ XTh per batch (1 segment); masked tiles skipped; hi plane out
    hmma_gemm<3><<<dim3(Dn / 128, Ln / 128, Bn), 256, SMEM_REQ>>>(
        Ph, nullptr, XTh, nullptr, nullptr, PXh, nullptr, Ln, Dn,
        (long long)Ln * Ln, (long long)Dn * Ln, (long long)Ln * Dn, 1.0f, 1, 1);

    // ctx = PXh @ Wvh^T (1 segment); masked rows/tiles filled with vmean in-kernel
    hmma_gemm<4><<<dim3(Dn / 128, M_ALL / 128, 1), 256, SMEM_REQ>>>(
        PXh, nullptr, Wvh, nullptr, ctx, nullptr, vm, Dn, Dn, 0, 0, 0, 1.0f, 2, 1);
}

// round 17
// speedup vs baseline: 5.4282x; 1.0426x over previous
#include <cuda_runtime.h>
#include <cuda_fp16.h>
#include <math.h>
#include <stdint.h>

#define Bn 8
#define Ln 2048
#define Dn 1024
#define M_ALL (Bn * Ln)   // 16384

// ---------------------------------------------------------------------------
// Device scratch (allocation-free rule -> __device__ globals)
// ---------------------------------------------------------------------------
__device__ float g_ctx_scratch[(size_t)M_ALL * Dn];
__device__ float g_attn_scratch[(size_t)Bn * Ln * Ln];
__device__ float g_vmean[(size_t)Bn * Dn];
__device__ float g_xmean[(size_t)Bn * Dn];
__device__ int   g_lens[Bn];

// fp16 planes (lo planes only where actually consumed: GT inputs)
__device__ __half g_Xh[(size_t)M_ALL * Dn];
__device__ __half g_Oh[(size_t)M_ALL * Dn];
__device__ __half g_Wvh[(size_t)Dn * Dn];
__device__ __half g_WqTh[(size_t)Dn * Dn];
__device__ __half g_WqTl[(size_t)Dn * Dn];
__device__ __half g_WkTh[(size_t)Dn * Dn];
__device__ __half g_WkTl[(size_t)Dn * Dn];
__device__ __half g_GTh[(size_t)Dn * Dn];
__device__ __half g_QGh[(size_t)M_ALL * Dn];
__device__ __half g_XTh[(size_t)Bn * Dn * Ln];
__device__ __half g_Ph[(size_t)M_ALL * Ln];
__device__ __half g_PXh[(size_t)M_ALL * Dn];

// ---------------------------------------------------------------------------
// lens dtype sniffing (int64 vs int32)
// ---------------------------------------------------------------------------
__global__ void prep_lens_kernel(const void* lensraw) {
    if (threadIdx.x == 0 && blockIdx.x == 0) {
        const int* a32 = (const int*)lensraw;
        bool is64 = true;
        #pragma unroll
        for (int i = 0; i < 4; i++) {
            int lo = a32[2 * i], hi = a32[2 * i + 1];
            if (hi != 0 || lo < 1 || lo > Ln) { is64 = false; break; }
        }
        if (is64) {
            const long long* a64 = (const long long*)lensraw;
            for (int i = 0; i < Bn; i++) g_lens[i] = (int)a64[i];
        } else {
            for (int i = 0; i < Bn; i++) g_lens[i] = a32[i];
        }
    }
}

// ---------------------------------------------------------------------------
// Megaprep: ALL independent input prep in one full-chip launch.
// ---------------------------------------------------------------------------
#define MP_A 256
#define MP_B 16384
#define MP_C 1024
#define MP_D 2048
#define MP_TOTAL (MP_A + MP_B + MP_C + MP_D)

__global__ __launch_bounds__(256)
void megaprep_kernel(const float* __restrict__ X, const float* __restrict__ O,
                     const float* __restrict__ Wq, const float* __restrict__ Wk,
                     const float* __restrict__ Wv,
                     __half* __restrict__ Xh, __half* __restrict__ XTh,
                     float* __restrict__ xm,
                     __half* __restrict__ Oh, __half* __restrict__ Wvh,
                     __half* __restrict__ WqTh, __half* __restrict__ WqTl,
                     __half* __restrict__ WkTh, __half* __restrict__ WkTl) {
    __shared__ float tile[32][33];
    __shared__ float red[8][33];
    const int bid = blockIdx.x;
    const int tid = threadIdx.x;
    const int tx = tid & 31;
    const int ty = tid >> 5;

    if (bid < MP_A) {
        const int b  = bid >> 5;
        const int d0 = (bid & 31) * 32;
        const float* Xb  = X   + (size_t)b * Ln * Dn;
        __half* Xhb      = Xh  + (size_t)b * Ln * Dn;
        __half* XThb     = XTh + (size_t)b * Dn * Ln;

        float csum = 0.0f;
        for (int t0 = 0; t0 < Ln; t0 += 32) {
            #pragma unroll
            for (int j = 0; j < 4; j++) {
                int row = t0 + ty + j * 8;
                float v = Xb[(size_t)row * Dn + d0 + tx];
                tile[ty + j * 8][tx] = v;
                csum += v;
                Xhb[(size_t)row * Dn + d0 + tx] = __float2half_rn(v);
            }
            __syncthreads();
            #pragma unroll
            for (int j = 0; j < 4; j++) {
                XThb[(size_t)(d0 + ty + j * 8) * Ln + t0 + tx] =
                    __float2half_rn(tile[tx][ty + j * 8]);
            }
            __syncthreads();
        }
        red[ty][tx] = csum;
        __syncthreads();
        if (ty == 0) {
            float s = red[0][tx];
            #pragma unroll
            for (int j = 1; j < 8; j++) s += red[j][tx];
            xm[b * Dn + d0 + tx] = s * (1.0f / 2048.0f);
        }
    } else if (bid < MP_A + MP_B) {
        long long i = (long long)(bid - MP_A) * 256 + tid;
        float4 v = *(const float4*)(O + i * 4);
        *(ushort4*)(Oh + i * 4) = make_ushort4(
            __half_as_ushort(__float2half_rn(v.x)),
            __half_as_ushort(__float2half_rn(v.y)),
            __half_as_ushort(__float2half_rn(v.z)),
            __half_as_ushort(__float2half_rn(v.w)));
    } else if (bid < MP_A + MP_B + MP_C) {
        long long i = (long long)(bid - MP_A - MP_B) * 256 + tid;
        float4 v = *(const float4*)(Wv + i * 4);
        *(ushort4*)(Wvh + i * 4) = make_ushort4(
            __half_as_ushort(__float2half_rn(v.x)),
            __half_as_ushort(__float2half_rn(v.y)),
            __half_as_ushort(__float2half_rn(v.z)),
            __half_as_ushort(__float2half_rn(v.w)));
    } else {
        const int wbid = bid - MP_A - MP_B - MP_C;
        const int zz   = wbid >> 10;
        const int rem  = wbid & 1023;
        const int c0 = (rem & 31) * 32;
        const int r0 = (rem >> 5) * 32;
        const float* src = zz ? Wk : Wq;
        __half* oh = zz ? WkTh : WqTh;
        __half* ol = zz ? WkTl : WqTl;

        #pragma unroll
        for (int j = 0; j < 4; j++)
            tile[ty + j * 8][tx] = src[(size_t)(r0 + ty + j * 8) * Dn + c0 + tx];
        __syncthreads();
        #pragma unroll
        for (int j = 0; j < 4; j++) {
            float v = tile[tx][ty + j * 8];
            __half h = __float2half_rn(v);
            __half l = __float2half_rn(v - __half2float(h));
            size_t o = (size_t)(c0 + ty + j * 8) * Dn + r0 + tx;
            oh[o] = h;
            ol[o] = l;
        }
    }
}

// ---------------------------------------------------------------------------
// vmean[b][e] = sum_d xmean[b][d] * Wv[e][d]
// ---------------------------------------------------------------------------
__global__ __launch_bounds__(256)
void vmeanw_kernel(const float* __restrict__ xm, const float* __restrict__ Wv,
                   float* __restrict__ vm) {
    int b = blockIdx.y;
    int e = blockIdx.x * 8 + (threadIdx.x >> 5);
    int lane = threadIdx.x & 31;
    const float* xr = xm + b * Dn;
    const float* wr = Wv + (size_t)e * Dn;
    float s = 0.f;
    for (int d = lane; d < Dn; d += 32) s += xr[d] * wr[d];
    #pragma unroll
    for (int o = 16; o > 0; o >>= 1) s += __shfl_down_sync(0xffffffffu, s, o);
    if (lane == 0) vm[b * Dn + e] = s;
}

// ---------------------------------------------------------------------------
// Common PTX helpers
// ---------------------------------------------------------------------------
__device__ __forceinline__ uint32_t sw128(uint32_t x) { return x ^ ((x >> 3) & 0x70); }

#define STAGE_B 32768
#define NSTAGE  3
#define SMEM_REQ (1024 + NSTAGE * STAGE_B)
#define UNI (1.0f / 2048.0f)

__device__ __forceinline__ void cp16(uint32_t saddr, const void* gaddr) {
    asm volatile("cp.async.cg.shared.global [%0], [%1], 16;" :: "r"(saddr), "l"(gaddr));
}
__device__ __forceinline__ void cp_commit() {
    asm volatile("cp.async.commit_group;" ::: "memory");
}
template <int N> __device__ __forceinline__ void cp_wait() {
    asm volatile("cp.async.wait_group %0;" :: "n"(N) : "memory");
}
__device__ __forceinline__ void ldm4(uint32_t addr, uint32_t& r0, uint32_t& r1,
                                     uint32_t& r2, uint32_t& r3) {
    asm volatile("ldmatrix.sync.aligned.m8n8.x4.shared.b16 {%0,%1,%2,%3}, [%4];"
                 : "=r"(r0), "=r"(r1), "=r"(r2), "=r"(r3) : "r"(addr));
}
__device__ __forceinline__ void mma16816(float* c, uint32_t a0, uint32_t a1,
                                         uint32_t a2, uint32_t a3,
                                         uint32_t b0, uint32_t b1) {
    asm volatile(
        "mma.sync.aligned.m16n8k16.row.col.f32.f16.f16.f32 "
        "{%0,%1,%2,%3},{%4,%5,%6,%7},{%8,%9},{%0,%1,%2,%3};"
        : "+f"(c[0]), "+f"(c[1]), "+f"(c[2]), "+f"(c[3])
        : "r"(a0), "r"(a1), "r"(a2), "r"(a3), "r"(b0), "r"(b1));
}
__device__ __forceinline__ uint32_t pack_h2(__half a, __half b) {
    return (uint32_t)__half_as_ushort(a) | ((uint32_t)__half_as_ushort(b) << 16);
}

// ---------------------------------------------------------------------------
// GT small GEMM: GT = WkT · WqT^T (NT), 3 hi/lo segments, fp16 hi out.
// BM=BN=64, BK=64 -> grid (16,16)=256 CTAs (fills the chip; GT was 64-CTA
// latency-bound at 57us). Threads 0-127 load A, 128-255 load B.
// ---------------------------------------------------------------------------
#define GT_STAGE 16384
#define GT_SMEM (1024 + NSTAGE * GT_STAGE)

__global__ __launch_bounds__(256, 2)
void gt_gemm(const __half* __restrict__ Ah, const __half* __restrict__ Al,
             const __half* __restrict__ Bh, const __half* __restrict__ Bl,
             __half* __restrict__ Out) {
    const int row0 = blockIdx.y * 64;
    const int n0   = blockIdx.x * 64;
    const int tid  = threadIdx.x;

    extern __shared__ char dsm[];
    uint32_t sraw = (uint32_t)__cvta_generic_to_shared(dsm);
    uint32_t sb   = (sraw + 1023) & ~1023u;

    const int lane = tid & 31;
    const int wid  = tid >> 5;
    const int wr   = wid >> 2;      // 0..1 : 32-row half
    const int wc   = wid & 3;       // 0..3 : 16-col quarter

    // loader: role split
    const bool isB = tid >= 128;
    const int lt = tid & 127;
    const int r  = lt >> 1;          // 0..63
    const int h  = (lt & 1) * 64;

    const char* rowH = isB
        ? (const char*)(Bh + (size_t)(n0 + r) * Dn) + h
        : (const char*)(Ah + (size_t)(row0 + r) * Dn) + h;
    const char* rowL = isB
        ? (const char*)(Bl + (size_t)(n0 + r) * Dn) + h
        : (const char*)(Al + (size_t)(row0 + r) * Dn) + h;

    uint32_t swo[4];
    #pragma unroll
    for (int i = 0; i < 4; i++) swo[i] = sw128((uint32_t)r * 128u + h + i * 16);
    const uint32_t roleOff = isB ? 8192u : 0u;

    float acc[2][2][4];
    #pragma unroll
    for (int a = 0; a < 2; a++)
        #pragma unroll
        for (int b = 0; b < 2; b++)
            #pragma unroll
            for (int cc = 0; cc < 4; cc++) acc[a][b][cc] = 0.0f;

    const int nch = Dn / 64;   // 16
    const int T   = 3 * nch;   // 48

    const char* ptr = rowH;
    int cIss = 0, segIss = 0, bufIss = 0;

    auto issue_one = [&]() {
        uint32_t sa = sb + bufIss * GT_STAGE + roleOff;
        #pragma unroll
        for (int i = 0; i < 4; i++) cp16(sa + swo[i], ptr + i * 16);
        cp_commit();
        ptr += 128;
        bufIss = (bufIss == NSTAGE - 1) ? 0 : bufIss + 1;
        if (++cIss == nch) {
            cIss = 0; segIss++;
            // seg0: (Ah,Bh)  seg1: (Ah,Bl)  seg2: (Al,Bh)
            if (segIss == 1)      ptr = isB ? rowL : rowH;
            else if (segIss == 2) ptr = isB ? rowH : rowL;
        }
    };

    issue_one();
    issue_one();

    int bufC = 0;
    for (int t = 0; t < T; t++) {
        if (t + 1 < T) cp_wait<1>(); else cp_wait<0>();
        __syncthreads();
        if (t + 2 < T) issue_one();

        const uint32_t aBase = sb + bufC * GT_STAGE;
        const uint32_t bBase = aBase + 8192;

        #pragma unroll
        for (int kk = 0; kk < 4; kk++) {
            uint32_t af[2][4];
            #pragma unroll
            for (int mi = 0; mi < 2; mi++) {
                uint32_t row  = wr * 32 + mi * 16 + (lane & 15);
                uint32_t colb = kk * 32 + ((lane >> 4) << 4);
                ldm4(aBase + sw128(row * 128u + colb), af[mi][0], af[mi][1], af[mi][2], af[mi][3]);
            }
            uint32_t bf[4];
            {
                uint32_t q    = lane >> 3;
                uint32_t row  = wc * 16 + ((q >> 1) << 3) + (lane & 7);
                uint32_t colb = kk * 32 + ((q & 1) << 4);
                ldm4(bBase + sw128(row * 128u + colb), bf[0], bf[1], bf[2], bf[3]);
            }
            #pragma unroll
            for (int mi = 0; mi < 2; mi++)
                #pragma unroll
                for (int n8 = 0; n8 < 2; n8++)
                    mma16816(acc[mi][n8], af[mi][0], af[mi][1], af[mi][2], af[mi][3],
                             bf[n8 * 2], bf[n8 * 2 + 1]);
        }
        bufC = (bufC == NSTAGE - 1) ? 0 : bufC + 1;
    }

    const int g  = lane >> 2;
    const int tg = lane & 3;
    #pragma unroll
    for (int mi = 0; mi < 2; mi++) {
        const int rA = row0 + wr * 32 + mi * 16 + g;
        const int rB = rA + 8;
        #pragma unroll
        for (int n8 = 0; n8 < 2; n8++) {
            const int col = n0 + wc * 16 + n8 * 8 + tg * 2;
            *(uint32_t*)(Out + (size_t)rA * Dn + col) =
                pack_h2(__float2half_rn(acc[mi][n8][0]), __float2half_rn(acc[mi][n8][1]));
            *(uint32_t*)(Out + (size_t)rB * Dn + col) =
                pack_h2(__float2half_rn(acc[mi][n8][2]), __float2half_rn(acc[mi][n8][3]));
        }
    }
}

// ---------------------------------------------------------------------------
// HMMA GEMM core (mma.sync m16n8k16 fp16, fp32 accum), NT. 128x128 tiles.
// Single-barrier multistage. nseg = 1 only (segments beyond handled by gt_gemm).
// MODE 1: scale fp32 C; masked rows -> FINAL uniform 1/2048.
// MODE 3: hi fp16 plane only.
// MODE 4: fp32 C, masked rows -> vmean (local-row mask).
// skipMode 1: tile skip if local row0 >= lens[z]
// skipMode 2: tile skip if (row0 & 2047) >= lens[row0 >> 11]
// ---------------------------------------------------------------------------
template <int MODE>
__global__ __launch_bounds__(256, 2)
void hmma_gemm(const __half* __restrict__ Ah,
               const __half* __restrict__ Bh,
               float* __restrict__ C,
               __half* __restrict__ Poh,
               const float* __restrict__ vmean,
               int K, int ldc,
               long long sA, long long sB, long long sC, float scale,
               int skipMode) {
    const int z    = blockIdx.z;
    const int row0 = blockIdx.y * 128;
    const int n0   = blockIdx.x * 128;
    const int tid  = threadIdx.x;

    bool fullMasked = false;
    if (skipMode == 1) {
        fullMasked = (row0 >= g_lens[z]);
    } else if (skipMode == 2) {
        fullMasked = ((row0 & (Ln - 1)) >= g_lens[row0 >> 11]);
    }
    if (fullMasked) {
        if (MODE == 4 || MODE == 1) {
            const int cq  = (tid & 31) * 4;
            const int rr0 = tid >> 5;
            float4 v;
            if (MODE == 4) {
                const int bb = row0 >> 11;
                v = *(const float4*)(vmean + (size_t)bb * Dn + n0 + cq);
            } else {
                v = make_float4(UNI, UNI, UNI, UNI);
            }
            float* Cz = C + (size_t)z * sC;
            #pragma unroll
            for (int i = 0; i < 16; i++) {
                int row = row0 + rr0 + i * 8;
                *(float4*)(Cz + (size_t)row * ldc + n0 + cq) = v;
            }
        }
        return;
    }

    extern __shared__ char dsm[];
    uint32_t sraw = (uint32_t)__cvta_generic_to_shared(dsm);
    uint32_t sb   = (sraw + 1023) & ~1023u;

    const int lane = tid & 31;
    const int wid  = tid >> 5;
    const int wr   = wid >> 2;
    const int wc   = wid & 3;

    const int r = tid >> 1;
    const int h = (tid & 1) * 64;

    const char* aRow = (const char*)(Ah + (size_t)z * sA + (size_t)(row0 + r) * K) + h;
    const char* bRow = (const char*)(Bh + (size_t)z * sB + (size_t)(n0 + r) * K) + h;

    uint32_t swo[4];
    #pragma unroll
    for (int i = 0; i < 4; i++) swo[i] = sw128((uint32_t)r * 128u + h + i * 16);

    float acc[4][4][4];
    #pragma unroll
    for (int a = 0; a < 4; a++)
        #pragma unroll
        for (int b = 0; b < 4; b++)
            #pragma unroll
            for (int cc = 0; cc < 4; cc++) acc[a][b][cc] = 0.0f;

    const int T = K / 64;
    int bufIss = 0, chIss = 0;

    auto issue_one = [&]() {
        uint32_t sa = sb + bufIss * STAGE_B;
        const char* ag = aRow + (size_t)chIss * 128;
        const char* bg = bRow + (size_t)chIss * 128;
        #pragma unroll
        for (int i = 0; i < 4; i++) {
            cp16(sa + swo[i], ag + i * 16);
            cp16(sa + 16384 + swo[i], bg + i * 16);
        }
        cp_commit();
        chIss++;
        bufIss = (bufIss == NSTAGE - 1) ? 0 : bufIss + 1;
    };

    issue_one();
    issue_one();

    int bufC = 0;
    for (int t = 0; t < T; t++) {
        if (t + 1 < T) cp_wait<1>(); else cp_wait<0>();
        __syncthreads();
        if (t + 2 < T) issue_one();

        const uint32_t aBase = sb + bufC * STAGE_B;
        const uint32_t bBase = aBase + 16384;

        #pragma unroll
        for (int kk = 0; kk < 4; kk++) {
            uint32_t af[4][4];
            #pragma unroll
            for (int mi = 0; mi < 4; mi++) {
                uint32_t row  = wr * 64 + mi * 16 + (lane & 15);
                uint32_t colb = kk * 32 + ((lane >> 4) << 4);
                ldm4(aBase + sw128(row * 128u + colb), af[mi][0], af[mi][1], af[mi][2], af[mi][3]);
            }
            uint32_t bf[2][4];
            #pragma unroll
            for (int ni = 0; ni < 2; ni++) {
                uint32_t q    = lane >> 3;
                uint32_t row  = wc * 32 + ni * 16 + ((q >> 1) << 3) + (lane & 7);
                uint32_t colb = kk * 32 + ((q & 1) << 4);
                ldm4(bBase + sw128(row * 128u + colb), bf[ni][0], bf[ni][1], bf[ni][2], bf[ni][3]);
            }
            #pragma unroll
            for (int mi = 0; mi < 4; mi++)
                #pragma unroll
                for (int n8 = 0; n8 < 4; n8++) {
                    uint32_t b0 = bf[n8 >> 1][(n8 & 1) * 2 + 0];
                    uint32_t b1 = bf[n8 >> 1][(n8 & 1) * 2 + 1];
                    mma16816(acc[mi][n8], af[mi][0], af[mi][1], af[mi][2], af[mi][3], b0, b1);
                }
        }
        bufC = (bufC == NSTAGE - 1) ? 0 : bufC + 1;
    }

    // ---- epilogue
    const int g  = lane >> 2;
    const int tg = lane & 3;
    int len = 0;
    if (MODE == 1) len = g_lens[z];
    if (MODE == 4) len = g_lens[row0 >> 11];

    #pragma unroll
    for (int mi = 0; mi < 4; mi++) {
        const int rA = row0 + wr * 64 + mi * 16 + g;
        const int rB = rA + 8;
        #pragma unroll
        for (int n8 = 0; n8 < 4; n8++) {
            const int col = n0 + wc * 32 + n8 * 8 + tg * 2;
            float v0 = acc[mi][n8][0], v1 = acc[mi][n8][1];
            float v2 = acc[mi][n8][2], v3 = acc[mi][n8][3];
            if (MODE == 1) {
                float* Cz = C + (size_t)z * sC;
                bool okA = rA < len, okB = rB < len;
                *(float2*)(Cz + (size_t)rA * ldc + col) =
                    make_float2(okA ? v0 * scale : UNI, okA ? v1 * scale : UNI);
                *(float2*)(Cz + (size_t)rB * ldc + col) =
                    make_float2(okB ? v2 * scale : UNI, okB ? v3 * scale : UNI);
            } else if (MODE == 4) {
                float* Cz = C + (size_t)z * sC;
                const int bb = row0 >> 11;
                bool okA = (rA & (Ln - 1)) < len;
                bool okB = (rB & (Ln - 1)) < len;
                float m0 = vmean[(size_t)bb * Dn + col];
                float m1 = vmean[(size_t)bb * Dn + col + 1];
                *(float2*)(Cz + (size_t)rA * ldc + col) =
                    make_float2(okA ? v0 : m0, okA ? v1 : m1);
                *(float2*)(Cz + (size_t)rB * ldc + col) =
                    make_float2(okB ? v2 : m0, okB ? v3 : m1);
            } else {
                __half* PohZ = Poh + (size_t)z * sC;
                *(uint32_t*)(PohZ + (size_t)rA * ldc + col) =
                    pack_h2(__float2half_rn(v0), __float2half_rn(v1));
                *(uint32_t*)(PohZ + (size_t)rB * ldc + col) =
                    pack_h2(__float2half_rn(v2), __float2half_rn(v3));
            }
        }
    }
}

// ---------------------------------------------------------------------------
// Row softmax over Ln=2048, in place + hi fp16 plane output.
// Masked rows already final from scores -> zero-work return.
// ---------------------------------------------------------------------------
__global__ __launch_bounds__(256)
void softmax_kernel(float* __restrict__ attn, __half* __restrict__ Ph) {
    const size_t row = blockIdx.x;
    const int b  = (int)(row >> 11);
    const int ql = (int)(row & (Ln - 1));
    if (ql >= g_lens[b]) return;

    float* p = attn + row * Ln;
    const int t = threadIdx.x;
    const int lane = t & 31;
    const int warp = t >> 5;
    __shared__ float wredm[8];
    __shared__ float wreds[8];

    float4 va = ((const float4*)p)[t * 2];
    float4 vb = ((const float4*)p)[t * 2 + 1];
    float v[8] = {va.x, va.y, va.z, va.w, vb.x, vb.y, vb.z, vb.w};

    float m = v[0];
    #pragma unroll
    for (int i = 1; i < 8; i++) m = fmaxf(m, v[i]);
    #pragma unroll
    for (int o = 16; o > 0; o >>= 1)
        m = fmaxf(m, __shfl_xor_sync(0xffffffffu, m, o));
    if (lane == 0) wredm[warp] = m;
    __syncthreads();
    m = wredm[0];
    #pragma unroll
    for (int j = 1; j < 8; j++) m = fmaxf(m, wredm[j]);

    float sum = 0.0f;
    #pragma unroll
    for (int i = 0; i < 8; i++) {
        v[i] = expf(v[i] - m);
        sum += v[i];
    }
    #pragma unroll
    for (int o = 16; o > 0; o >>= 1)
        sum += __shfl_xor_sync(0xffffffffu, sum, o);
    if (lane == 0) wreds[warp] = sum;
    __syncthreads();
    sum = wreds[0];
    #pragma unroll
    for (int j = 1; j < 8; j++) sum += wreds[j];
    const float inv = 1.0f / sum;

    unsigned short hb[8];
    #pragma unroll
    for (int i = 0; i < 8; i++) {
        v[i] *= inv;
        hb[i] = __half_as_ushort(__float2half_rn(v[i]));
    }
    ((float4*)p)[t * 2]     = make_float4(v[0], v[1], v[2], v[3]);
    ((float4*)p)[t * 2 + 1] = make_float4(v[4], v[5], v[6], v[7]);
    __half* ph = Ph + row * Ln + t * 8;
    *(ushort4*)(ph)     = make_ushort4(hb[0], hb[1], hb[2], hb[3]);
    *(ushort4*)(ph + 4) = make_ushort4(hb[4], hb[5], hb[6], hb[7]);
}

// ---------------------------------------------------------------------------
// kernel_launch
// ---------------------------------------------------------------------------
extern "C" void kernel_launch(void* const* d_in, const int* in_sizes, int n_in,
                              void* d_out, int out_size) {
    const float* X  = (const float*)d_in[0];
    const void*  lens_raw = d_in[1];
    const float* O  = (const float*)d_in[2];
    const float* Wk = (const float*)d_in[3];
    const float* Wv = (const float*)d_in[4];
    const float* Wq = (const float*)d_in[5];

    const long long CTX = (long long)Bn * Ln * Dn;
    const long long ATT = (long long)Bn * Ln * Ln;

    float *ctx_s, *attn_s, *vm, *xm;
    __half *Xh, *Oh, *Wvh, *WqTh, *WqTl, *WkTh, *WkTl;
    __half *GTh, *QGh, *XTh, *Ph, *PXh;
    cudaGetSymbolAddress((void**)&ctx_s, g_ctx_scratch);
    cudaGetSymbolAddress((void**)&attn_s, g_attn_scratch);
    cudaGetSymbolAddress((void**)&vm, g_vmean);
    cudaGetSymbolAddress((void**)&xm, g_xmean);
    cudaGetSymbolAddress((void**)&Xh, g_Xh);
    cudaGetSymbolAddress((void**)&Oh, g_Oh);
    cudaGetSymbolAddress((void**)&Wvh, g_Wvh);
    cudaGetSymbolAddress((void**)&WqTh, g_WqTh); cudaGetSymbolAddress((void**)&WqTl, g_WqTl);
    cudaGetSymbolAddress((void**)&WkTh, g_WkTh); cudaGetSymbolAddress((void**)&WkTl, g_WkTl);
    cudaGetSymbolAddress((void**)&GTh, g_GTh);
    cudaGetSymbolAddress((void**)&QGh, g_QGh);
    cudaGetSymbolAddress((void**)&XTh, g_XTh);
    cudaGetSymbolAddress((void**)&Ph, g_Ph);
    cudaGetSymbolAddress((void**)&PXh, g_PXh);

    float* ctx;
    float* attn;
    if ((long long)out_size >= CTX + ATT) {
        ctx  = (float*)d_out;
        attn = (float*)d_out + CTX;
    } else if ((long long)out_size == ATT) {
        attn = (float*)d_out;
        ctx  = ctx_s;
    } else {
        ctx  = (float*)d_out;
        attn = attn_s;
    }

    cudaFuncSetAttribute(hmma_gemm<1>, cudaFuncAttributeMaxDynamicSharedMemorySize, SMEM_REQ);
    cudaFuncSetAttribute(hmma_gemm<3>, cudaFuncAttributeMaxDynamicSharedMemorySize, SMEM_REQ);
    cudaFuncSetAttribute(hmma_gemm<4>, cudaFuncAttributeMaxDynamicSharedMemorySize, SMEM_REQ);
    cudaFuncSetAttribute(gt_gemm, cudaFuncAttributeMaxDynamicSharedMemorySize, GT_SMEM);

    prep_lens_kernel<<<1, 32>>>(lens_raw);

    // All independent input prep in one full-chip launch
    megaprep_kernel<<<MP_TOTAL, 256>>>(X, O, Wq, Wk, Wv,
                                       Xh, XTh, xm, Oh, Wvh,
                                       WqTh, WqTl, WkTh, WkTl);

    // vmean = xmean @ Wv^T
    vmeanw_kernel<<<dim3(Dn / 8, Bn), 256>>>(xm, Wv, vm);

    // GT = WkT @ WqT^T  (3 hi/lo segments; 64x64 tiles -> 256 CTAs)
    gt_gemm<<<dim3(Dn / 64, Dn / 64), 256, GT_SMEM>>>(WkTh, WkTl, WqTh, WqTl, GTh);

    // QG = Oh @ GTh; masked row tiles skipped; hi plane out
    hmma_gemm<3><<<dim3(Dn / 128, M_ALL / 128, 1), 256, SMEM_REQ>>>(
        Oh, GTh, nullptr, QGh, nullptr, Dn, Dn, 0, 0, 0, 1.0f, 2);

    // scores = QGh @ Xh^T / 32 per batch; masked rows/tiles -> final 1/2048
    hmma_gemm<1><<<dim3(Ln / 128, Ln / 128, Bn), 256, SMEM_REQ>>>(
        QGh, Xh, attn, nullptr, nullptr, Dn, Ln,
        (long long)Ln * Dn, (long long)Ln * Dn, (long long)Ln * Ln, 0.03125f, 1);

    // Softmax in place + P hi plane (masked rows: zero work)
    softmax_kernel<<<Bn * Ln, 256>>>(attn, Ph);

    // PX = Ph @ XTh per batch; masked tiles skipped; hi plane out
    hmma_gemm<3><<<dim3(Dn / 128, Ln / 128, Bn), 256, SMEM_REQ>>>(
        Ph, XTh, nullptr, PXh, nullptr, Ln, Dn,
        (long long)Ln * Ln, (long long)Dn * Ln, (long long)Ln * Dn, 1.0f, 1);

    // ctx = PXh @ Wvh^T; masked rows/tiles filled with vmean in-kernel
    hmma_gemm<4><<<dim3(Dn / 128, M_ALL / 128, 1), 256, SMEM_REQ>>>(
        PXh, Wvh, ctx, nullptr, vm, Dn, Dn, 0, 0, 0, 1.0f, 2);
}